// round 8
// baseline (speedup 1.0000x reference)
#include <cuda_runtime.h>
#include <cstdint>

#define N_NODES  50000
#define N_EDGES  800000
#define N_GRAPHS 512
#define F_IN     128
#define DD       256
#define EPS      1e-5f
#define NEG_SLOPE 0.01f
#define NSB      196          // ceil(N_NODES/256) scan blocks

typedef unsigned long long ull;

// ---------------- scratch (device globals; no allocation allowed) ----------
__device__ float g_bufA[N_NODES * DD];   // H1 -> H2
__device__ float g_bufB[N_NODES * DD];   // agg1 -> agg2
__device__ float g_C1[4 * DD];
__device__ float g_bc1[DD];
__device__ float g_C2[4 * DD];
__device__ float g_bc2[DD];
__device__ float g_bnsum1[DD];
__device__ float g_bnsq1[DD];
__device__ float g_bnsum2[DD];
__device__ float g_bnsq2[DD];
__device__ float g_sc[DD];
__device__ float g_sh[DD];
__device__ unsigned g_gmax[N_GRAPHS];
__device__ float g_denom[N_GRAPHS];
__device__ float g_gate[N_NODES];
// CSR (dst-sorted, with permuted src and edge_attr)
__device__ int    g_deg[N_NODES];
__device__ int    g_start[N_NODES];
__device__ int    g_cursor[N_NODES];
__device__ int    g_srcs[N_EDGES];
__device__ float4 g_eas[N_EDGES];
__device__ int    g_part[NSB];
__device__ int    g_part2[NSB];

// ---------------- helpers ---------------------------------------------------
__device__ __forceinline__ float leaky(float v) {
    return v >= 0.f ? v : NEG_SLOPE * v;
}
__device__ __forceinline__ unsigned enc_f(float x) {
    unsigned u = __float_as_uint(x);
    return (u & 0x80000000u) ? ~u : (u | 0x80000000u);
}
__device__ __forceinline__ float dec_f(unsigned u) {
    return (u & 0x80000000u) ? __uint_as_float(u ^ 0x80000000u) : __uint_as_float(~u);
}
__device__ __forceinline__ void red_add_v4(float* p, float a, float b, float c, float d) {
    asm volatile("red.global.add.v4.f32 [%0], {%1, %2, %3, %4};"
                 :: "l"(p), "f"(a), "f"(b), "f"(c), "f"(d) : "memory");
}
__device__ __forceinline__ ull dup2(float x) {
    ull r; unsigned u = __float_as_uint(x);
    asm("mov.b64 %0, {%1, %1};" : "=l"(r) : "r"(u));
    return r;
}
__device__ __forceinline__ void fma2(ull& d, ull a, ull b) {
    asm("fma.rn.f32x2 %0, %1, %2, %0;" : "+l"(d) : "l"(a), "l"(b));
}
__device__ __forceinline__ float2 up2(ull v) {
    float2 f; asm("mov.b64 {%0, %1}, %2;" : "=f"(f.x), "=f"(f.y) : "l"(v));
    return f;
}
__device__ __forceinline__ unsigned tf32c(float x) {
    unsigned r;
    asm("cvt.rna.tf32.f32 %0, %1;" : "=r"(r) : "f"(x));
    return r;
}
__device__ __forceinline__ void mma_tf32(float d[4], const unsigned a[4],
                                         unsigned b0, unsigned b1) {
    asm volatile(
        "mma.sync.aligned.m16n8k8.row.col.f32.tf32.tf32.f32 "
        "{%0,%1,%2,%3}, {%4,%5,%6,%7}, {%8,%9}, {%0,%1,%2,%3};"
        : "+f"(d[0]), "+f"(d[1]), "+f"(d[2]), "+f"(d[3])
        : "r"(a[0]), "r"(a[1]), "r"(a[2]), "r"(a[3]), "r"(b0), "r"(b1));
}

// ---------------- zero / init kernels ---------------------------------------
__global__ void zero_init(float* out, int out_n) {
    int i = blockIdx.x * blockDim.x + threadIdx.x;
    if (i < N_NODES) g_deg[i] = 0;
    if (i < DD) {
        g_bnsum1[i] = 0.f; g_bnsq1[i] = 0.f;
        g_bnsum2[i] = 0.f; g_bnsq2[i] = 0.f;
    }
    if (i < N_GRAPHS) { g_gmax[i] = 0u; g_denom[i] = 0.f; }
    for (int k = i; k < out_n; k += gridDim.x * blockDim.x) out[k] = 0.f;
}

// ---------------- CSR build --------------------------------------------------
__global__ void hist_kernel(const int* __restrict__ dst) {
    int e = blockIdx.x * blockDim.x + threadIdx.x;
    if (e < N_EDGES) atomicAdd(&g_deg[__ldg(dst + e)], 1);
}
__global__ void scan1_kernel() {
    __shared__ int sh[256];
    int i = blockIdx.x * 256 + threadIdx.x;
    int v = (i < N_NODES) ? g_deg[i] : 0;
    sh[threadIdx.x] = v; __syncthreads();
#pragma unroll
    for (int off = 1; off < 256; off <<= 1) {
        int tv = (threadIdx.x >= off) ? sh[threadIdx.x - off] : 0;
        __syncthreads();
        sh[threadIdx.x] += tv;
        __syncthreads();
    }
    if (i < N_NODES) g_start[i] = sh[threadIdx.x] - v;
    if (threadIdx.x == 255) g_part[blockIdx.x] = sh[255];
}
__global__ void scan2_kernel() {
    __shared__ int sh[256];
    int t = threadIdx.x;
    int v = (t < NSB) ? g_part[t] : 0;
    sh[t] = v; __syncthreads();
#pragma unroll
    for (int off = 1; off < 256; off <<= 1) {
        int tv = (t >= off) ? sh[t - off] : 0;
        __syncthreads();
        sh[t] += tv;
        __syncthreads();
    }
    if (t < NSB) g_part2[t] = sh[t] - v;
}
__global__ void scan3_kernel() {
    int i = blockIdx.x * 256 + threadIdx.x;
    if (i < N_NODES) {
        int s = g_start[i] + g_part2[blockIdx.x];
        g_start[i] = s;
        g_cursor[i] = s;
    }
}
__global__ void fill_kernel(const int* __restrict__ src,
                            const int* __restrict__ dst,
                            const float* __restrict__ ea) {
    int e = blockIdx.x * blockDim.x + threadIdx.x;
    if (e < N_EDGES) {
        int d = __ldg(dst + e);
        int p = atomicAdd(&g_cursor[d], 1);
        g_srcs[p] = __ldg(src + e);
        g_eas[p] = __ldg((const float4*)ea + e);
    }
}

// ---------------- combined edge matrices ------------------------------------
__global__ void combine_kernel(
    const float* __restrict__ l2w1, const float* __restrict__ l2b1,
    const float* __restrict__ lw1,  const float* __restrict__ lb1,
    const float* __restrict__ l2w2, const float* __restrict__ l2b2,
    const float* __restrict__ lw2,  const float* __restrict__ lb2)
{
    int d = threadIdx.x;   // 256 threads
    {
        float a0 = 0.f, a1 = 0.f, a2 = 0.f, a3 = 0.f, bb = 0.f;
        for (int f = 0; f < F_IN; f++) {
            float w = lw1[d * F_IN + f];
            float4 l2 = *(const float4*)(l2w1 + f * 4);
            a0 += l2.x * w; a1 += l2.y * w; a2 += l2.z * w; a3 += l2.w * w;
            bb += l2b1[f] * w;
        }
        g_C1[0 * DD + d] = a0; g_C1[1 * DD + d] = a1;
        g_C1[2 * DD + d] = a2; g_C1[3 * DD + d] = a3;
        g_bc1[d] = bb + lb1[d];
    }
    {
        float a0 = 0.f, a1 = 0.f, a2 = 0.f, a3 = 0.f, bb = 0.f;
        for (int f = 0; f < DD; f++) {
            float w = lw2[d * DD + f];
            float4 l2 = *(const float4*)(l2w2 + f * 4);
            a0 += l2.x * w; a1 += l2.y * w; a2 += l2.z * w; a3 += l2.w * w;
            bb += l2b2[f] * w;
        }
        g_C2[0 * DD + d] = a0; g_C2[1 * DD + d] = a1;
        g_C2[2 * DD + d] = a2; g_C2[3 * DD + d] = a3;
        g_bc2[d] = bb + lb2[d];
    }
}

// ---------------- GEMM (tf32 tensor cores, k-permuted smem, bias epilogue) ---
// out[m][n] = sum_k A'[m][k] * W[n][k] + bias[n];  A' = leaky(A*sc+sh) if sc.
// Smem rows hold a 32-k tile with columns permuted: col' = (k&3)*8 + (k>>2).
// A thread's mma fragment elements for ALL 4 ks-steps live in one contiguous
// 8-float group -> 2x LDS.128 per row instead of scattered scalar LDS.
__global__ void __launch_bounds__(256)
gemm_tf32(const float* __restrict__ A, const int* __restrict__ idx,
          const float* __restrict__ sc, const float* __restrict__ sh,
          const float* __restrict__ W, const float* __restrict__ bias,
          float* __restrict__ out, int M, int K)
{
    __shared__ unsigned As[128 * 36];
    __shared__ unsigned Bs[128 * 36];
    int t = threadIdx.x;
    int lane = t & 31;
    int wid = t >> 5;
    int wm = wid & 3, wn = wid >> 2;       // warp tile: rows wm*32, cols wn*64
    int bm = blockIdx.x * 128;
    int bn = blockIdx.y * 128;

    int lrow = t >> 1;                     // 0..127
    int lkh = (t & 1) * 16;                // k-half 0 or 16
    int kb = lkh >> 2;                     // position offset within 8-group: 0 or 4

    int c = lane & 3;
    int r4 = lane >> 2;

    int m0 = bm + lrow;
    int mc = m0 < M ? m0 : (M - 1);
    int arow = idx ? __ldg(idx + mc) : mc;
    const float* Arow = A + (size_t)arow * K;
    const float* Wrow = W + (size_t)(bn + lrow) * K;

    float d[2][8][4];
#pragma unroll
    for (int i = 0; i < 2; i++)
#pragma unroll
        for (int j = 0; j < 8; j++)
#pragma unroll
            for (int q = 0; q < 4; q++) d[i][j][q] = 0.f;

    float4 va[4], vb[4];

    auto load_stage = [&](int kc) {
#pragma unroll
        for (int q = 0; q < 4; q++) {
            va[q] = __ldg((const float4*)(Arow + kc + lkh + q * 4));
            vb[q] = __ldg((const float4*)(Wrow + kc + lkh + q * 4));
        }
        if (sc) {
#pragma unroll
            for (int q = 0; q < 4; q++) {
                int ch = kc + lkh + q * 4;
                float4 s = __ldg((const float4*)(sc + ch));
                float4 h = __ldg((const float4*)(sh + ch));
                va[q].x = leaky(va[q].x * s.x + h.x);
                va[q].y = leaky(va[q].y * s.y + h.y);
                va[q].z = leaky(va[q].z * s.z + h.z);
                va[q].w = leaky(va[q].w * s.w + h.w);
            }
        }
    };
    // register 4x4 transpose, then 4 STS.128 per buffer at permuted columns
    auto store_stage = [&]() {
        unsigned* ap = As + lrow * 36 + kb;
        unsigned* bp = Bs + lrow * 36 + kb;
        *(uint4*)(ap)      = make_uint4(tf32c(va[0].x), tf32c(va[1].x), tf32c(va[2].x), tf32c(va[3].x));
        *(uint4*)(ap + 8)  = make_uint4(tf32c(va[0].y), tf32c(va[1].y), tf32c(va[2].y), tf32c(va[3].y));
        *(uint4*)(ap + 16) = make_uint4(tf32c(va[0].z), tf32c(va[1].z), tf32c(va[2].z), tf32c(va[3].z));
        *(uint4*)(ap + 24) = make_uint4(tf32c(va[0].w), tf32c(va[1].w), tf32c(va[2].w), tf32c(va[3].w));
        *(uint4*)(bp)      = make_uint4(tf32c(vb[0].x), tf32c(vb[1].x), tf32c(vb[2].x), tf32c(vb[3].x));
        *(uint4*)(bp + 8)  = make_uint4(tf32c(vb[0].y), tf32c(vb[1].y), tf32c(vb[2].y), tf32c(vb[3].y));
        *(uint4*)(bp + 16) = make_uint4(tf32c(vb[0].z), tf32c(vb[1].z), tf32c(vb[2].z), tf32c(vb[3].z));
        *(uint4*)(bp + 24) = make_uint4(tf32c(vb[0].w), tf32c(vb[1].w), tf32c(vb[2].w), tf32c(vb[3].w));
    };

    load_stage(0);
    store_stage();
    __syncthreads();

    for (int kc = 0; kc < K; kc += 32) {
        bool more = (kc + 32) < K;
        if (more) load_stage(kc + 32);

        // A fragments: 4 rows (r4 + {0,8,16,24} within warp-tile) x 8 positions
        unsigned aE[4][8];
#pragma unroll
        for (int ri = 0; ri < 4; ri++) {
            const uint4* p = (const uint4*)&As[(wm * 32 + r4 + ri * 8) * 36 + c * 8];
            uint4 u0 = p[0], u1 = p[1];
            aE[ri][0] = u0.x; aE[ri][1] = u0.y; aE[ri][2] = u0.z; aE[ri][3] = u0.w;
            aE[ri][4] = u1.x; aE[ri][5] = u1.y; aE[ri][6] = u1.z; aE[ri][7] = u1.w;
        }
#pragma unroll
        for (int j = 0; j < 8; j++) {
            const uint4* pb = (const uint4*)&Bs[(wn * 64 + j * 8 + r4) * 36 + c * 8];
            uint4 v0 = pb[0], v1 = pb[1];
            unsigned bE[8] = {v0.x, v0.y, v0.z, v0.w, v1.x, v1.y, v1.z, v1.w};
#pragma unroll
            for (int ks = 0; ks < 4; ks++) {
                unsigned b0 = bE[2 * ks], b1 = bE[2 * ks + 1];
                unsigned a0v[4] = {aE[0][2 * ks], aE[1][2 * ks],
                                   aE[0][2 * ks + 1], aE[1][2 * ks + 1]};
                mma_tf32(d[0][j], a0v, b0, b1);
                unsigned a1v[4] = {aE[2][2 * ks], aE[3][2 * ks],
                                   aE[2][2 * ks + 1], aE[3][2 * ks + 1]};
                mma_tf32(d[1][j], a1v, b0, b1);
            }
        }
        if (more) {
            __syncthreads();
            store_stage();
            __syncthreads();
        }
    }

    // epilogue (+ bias)
    float2 bsv[8];
#pragma unroll
    for (int j = 0; j < 8; j++) {
        int col = bn + wn * 64 + j * 8 + (lane & 3) * 2;
        bsv[j] = __ldg((const float2*)(bias + col));
    }
#pragma unroll
    for (int i = 0; i < 2; i++) {
        int rg0 = bm + wm * 32 + i * 16 + (lane >> 2);
        int rg1 = rg0 + 8;
#pragma unroll
        for (int j = 0; j < 8; j++) {
            int col = bn + wn * 64 + j * 8 + (lane & 3) * 2;
            if (rg0 < M)
                *(float2*)(out + (size_t)rg0 * DD + col) =
                    make_float2(d[i][j][0] + bsv[j].x, d[i][j][1] + bsv[j].y);
            if (rg1 < M)
                *(float2*)(out + (size_t)rg1 * DD + col) =
                    make_float2(d[i][j][2] + bsv[j].x, d[i][j][3] + bsv[j].y);
        }
    }
}

// ---------------- per-edge packed accumulate (bias pre-folded into H) --------
__device__ __forceinline__ void edge_accum(
    ull acc[4], float4 at, ulonglong2 p, ulonglong2 q,
    const ull c0p[4], const ull c1p[4], const ull c2p[4], const ull c3p[4])
{
    const ull ABS2 = 0x7fffffff7fffffffull;
    const ull D505 = 0x3f0147ae3f0147aeull;  // dup2(0.505f)
    const ull D495 = 0x3efd70a43efd70a4ull;  // dup2(0.495f)
    ull ax = dup2(at.x), ay = dup2(at.y), az = dup2(at.z), aw = dup2(at.w);
    ull hh[4] = {p.x, p.y, q.x, q.y};
#pragma unroll
    for (int i = 0; i < 4; i++) {
        ull m = hh[i];
        fma2(m, ax, c0p[i]); fma2(m, ay, c1p[i]);
        fma2(m, az, c2p[i]); fma2(m, aw, c3p[i]);
        ull ab = m & ABS2;
        fma2(acc[i], D505, m);
        fma2(acc[i], D495, ab);
    }
}

// ---------------- CSR gather (permuted edges, packed f32x2, unroll-4) --------
__global__ void gather_kernel(const float* __restrict__ H,
                              const float* __restrict__ C,
                              float* __restrict__ agg,
                              float* __restrict__ bnsum,
                              float* __restrict__ bnsq)
{
    __shared__ float ssum[DD];
    __shared__ float ssq[DD];
    int t = threadIdx.x;
    ssum[t] = 0.f; ssq[t] = 0.f;
    __syncthreads();

    int lane = t & 31;
    int wid = (blockIdx.x * blockDim.x + t) >> 5;
    int nw = (gridDim.x * blockDim.x) >> 5;
    int d0 = lane * 8;

    ull c0p[4], c1p[4], c2p[4], c3p[4];
    {
        ulonglong2 u;
        u = *(const ulonglong2*)(C + 0 * DD + d0);     c0p[0] = u.x; c0p[1] = u.y;
        u = *(const ulonglong2*)(C + 0 * DD + d0 + 4); c0p[2] = u.x; c0p[3] = u.y;
        u = *(const ulonglong2*)(C + 1 * DD + d0);     c1p[0] = u.x; c1p[1] = u.y;
        u = *(const ulonglong2*)(C + 1 * DD + d0 + 4); c1p[2] = u.x; c1p[3] = u.y;
        u = *(const ulonglong2*)(C + 2 * DD + d0);     c2p[0] = u.x; c2p[1] = u.y;
        u = *(const ulonglong2*)(C + 2 * DD + d0 + 4); c2p[2] = u.x; c2p[3] = u.y;
        u = *(const ulonglong2*)(C + 3 * DD + d0);     c3p[0] = u.x; c3p[1] = u.y;
        u = *(const ulonglong2*)(C + 3 * DD + d0 + 4); c3p[2] = u.x; c3p[3] = u.y;
    }

    float sA[8], qA[8];
#pragma unroll
    for (int i = 0; i < 8; i++) { sA[i] = 0.f; qA[i] = 0.f; }

    for (int n = wid; n < N_NODES; n += nw) {
        int s0 = __ldg(g_start + n);
        int dg = __ldg(g_deg + n);
        ull acc[4] = {0ull, 0ull, 0ull, 0ull};

        int j = 0;
        for (; j + 3 < dg; j += 4) {
            int sa = __ldg(g_srcs + s0 + j);
            int sb = __ldg(g_srcs + s0 + j + 1);
            int sc2 = __ldg(g_srcs + s0 + j + 2);
            int sd = __ldg(g_srcs + s0 + j + 3);
            const ulonglong2* ha = (const ulonglong2*)(H + (size_t)sa * DD + d0);
            const ulonglong2* hb = (const ulonglong2*)(H + (size_t)sb * DD + d0);
            const ulonglong2* hc = (const ulonglong2*)(H + (size_t)sc2 * DD + d0);
            const ulonglong2* hd = (const ulonglong2*)(H + (size_t)sd * DD + d0);
            ulonglong2 pa = ha[0], qa = ha[1];
            ulonglong2 pb = hb[0], qb = hb[1];
            ulonglong2 pc = hc[0], qc = hc[1];
            ulonglong2 pd = hd[0], qd = hd[1];
            float4 at0 = __ldg((const float4*)g_eas + s0 + j);
            float4 at1 = __ldg((const float4*)g_eas + s0 + j + 1);
            float4 at2 = __ldg((const float4*)g_eas + s0 + j + 2);
            float4 at3 = __ldg((const float4*)g_eas + s0 + j + 3);
            edge_accum(acc, at0, pa, qa, c0p, c1p, c2p, c3p);
            edge_accum(acc, at1, pb, qb, c0p, c1p, c2p, c3p);
            edge_accum(acc, at2, pc, qc, c0p, c1p, c2p, c3p);
            edge_accum(acc, at3, pd, qd, c0p, c1p, c2p, c3p);
        }
        for (; j < dg; j++) {
            int sa = __ldg(g_srcs + s0 + j);
            float4 at0 = __ldg((const float4*)g_eas + s0 + j);
            const ulonglong2* ha = (const ulonglong2*)(H + (size_t)sa * DD + d0);
            ulonglong2 pa = ha[0], qa = ha[1];
            edge_accum(acc, at0, pa, qa, c0p, c1p, c2p, c3p);
        }

        ulonglong2* op = (ulonglong2*)(agg + (size_t)n * DD + d0);
        op[0] = make_ulonglong2(acc[0], acc[1]);
        op[1] = make_ulonglong2(acc[2], acc[3]);

#pragma unroll
        for (int i = 0; i < 4; i++) {
            float2 f = up2(acc[i]);
            sA[2 * i]     += f.x;  qA[2 * i]     += f.x * f.x;
            sA[2 * i + 1] += f.y;  qA[2 * i + 1] += f.y * f.y;
        }
    }
#pragma unroll
    for (int i = 0; i < 8; i++) {
        atomicAdd(&ssum[d0 + i], sA[i]);
        atomicAdd(&ssq[d0 + i], qA[i]);
    }
    __syncthreads();
    atomicAdd(&bnsum[t], ssum[t]);
    atomicAdd(&bnsq[t], ssq[t]);
}

// ---------------- BN scale/shift from stats ----------------------------------
__global__ void bnsc_kernel(const float* __restrict__ w, const float* __restrict__ b,
                            const float* __restrict__ bnsum, const float* __restrict__ bnsq)
{
    int c = threadIdx.x;
    const float invN = 1.f / (float)N_NODES;
    float m = bnsum[c] * invN;
    float var = bnsq[c] * invN - m * m;
    float s = w[c] * rsqrtf(var + EPS);
    g_sc[c] = s;
    g_sh[c] = b[c] - m * s;
}

// ---------------- gate (read-only) + segment max ------------------------------
__global__ void gate_kernel(const float* __restrict__ X,
                            const float* __restrict__ gw,
                            const float* __restrict__ gb,
                            const int* __restrict__ batch)
{
    int wid = (blockIdx.x * blockDim.x + threadIdx.x) >> 5;
    int lane = threadIdx.x & 31;
    if (wid >= N_NODES) return;
    int d0 = lane * 8;
    const float4* xp = (const float4*)(X + (size_t)wid * DD + d0);
    float4 h0 = __ldg(xp), h1 = __ldg(xp + 1);
    float v[8] = {h0.x, h0.y, h0.z, h0.w, h1.x, h1.y, h1.z, h1.w};
    float gsum = 0.f;
#pragma unroll
    for (int i = 0; i < 8; i++) {
        int ch = d0 + i;
        gsum += leaky(v[i] * g_sc[ch] + g_sh[ch]) * __ldg(gw + ch);
    }
#pragma unroll
    for (int off = 16; off; off >>= 1) gsum += __shfl_xor_sync(0xffffffffu, gsum, off);
    if (lane == 0) {
        gsum += __ldg(gb);
        g_gate[wid] = gsum;
        atomicMax(&g_gmax[__ldg(batch + wid)], enc_f(gsum));
    }
}

// ---------------- fused exp + denom + unnormalized weighted aggregation ------
__global__ void wfinal_kernel(const float* __restrict__ X,
                              const int* __restrict__ batch,
                              float* __restrict__ out)
{
    int wid = (blockIdx.x * blockDim.x + threadIdx.x) >> 5;
    int lane = threadIdx.x & 31;
    if (wid >= N_NODES) return;
    int b = __ldg(batch + wid);
    float e = __expf(g_gate[wid] - dec_f(g_gmax[b]));
    if (lane == 0) atomicAdd(&g_denom[b], e);
    int d0 = lane * 8;
    const float4* xp = (const float4*)(X + (size_t)wid * DD + d0);
    float4 h0 = __ldg(xp), h1 = __ldg(xp + 1);
    float v[8] = {h0.x, h0.y, h0.z, h0.w, h1.x, h1.y, h1.z, h1.w};
#pragma unroll
    for (int i = 0; i < 8; i++) {
        int ch = d0 + i;
        v[i] = e * leaky(v[i] * g_sc[ch] + g_sh[ch]);
    }
    float* op = out + (size_t)b * DD + d0;
    red_add_v4(op,     v[0], v[1], v[2], v[3]);
    red_add_v4(op + 4, v[4], v[5], v[6], v[7]);
}

// ---------------- normalize out by denom --------------------------------------
__global__ void norm_kernel(float* __restrict__ out)
{
    int i = blockIdx.x * blockDim.x + threadIdx.x;
    if (i >= N_GRAPHS * DD) return;
    float dn = g_denom[i >> 8];
    out[i] = dn > 0.f ? out[i] / dn : 0.f;
}

// ---------------- launch -----------------------------------------------------
extern "C" void kernel_launch(void* const* d_in, const int* in_sizes, int n_in,
                              void* d_out, int out_size)
{
    const int*   node_ids  = (const int*)d_in[0];
    const int*   edge_index= (const int*)d_in[1];
    const float* edge_attr = (const float*)d_in[2];
    const int*   batch     = (const int*)d_in[3];
    const float* emb       = (const float*)d_in[4];
    const float* c1_lin2_w = (const float*)d_in[5];
    const float* c1_lin2_b = (const float*)d_in[6];
    const float* c1_lin_w  = (const float*)d_in[7];
    const float* c1_lin_b  = (const float*)d_in[8];
    const float* bn1_w     = (const float*)d_in[9];
    const float* bn1_b     = (const float*)d_in[10];
    const float* c2_lin2_w = (const float*)d_in[11];
    const float* c2_lin2_b = (const float*)d_in[12];
    const float* c2_lin_w  = (const float*)d_in[13];
    const float* c2_lin_b  = (const float*)d_in[14];
    const float* bn2_w     = (const float*)d_in[15];
    const float* bn2_b     = (const float*)d_in[16];
    const float* gate_w    = (const float*)d_in[17];
    const float* gate_b    = (const float*)d_in[18];
    float* out = (float*)d_out;

    const int* src = edge_index;
    const int* dst = edge_index + N_EDGES;

    float *pA, *pB, *pC1, *pbc1, *pC2, *pbc2, *psc, *psh;
    float *pbs1, *pbq1, *pbs2, *pbq2;
    cudaGetSymbolAddress((void**)&pA,   g_bufA);
    cudaGetSymbolAddress((void**)&pB,   g_bufB);
    cudaGetSymbolAddress((void**)&pC1,  g_C1);
    cudaGetSymbolAddress((void**)&pbc1, g_bc1);
    cudaGetSymbolAddress((void**)&pC2,  g_C2);
    cudaGetSymbolAddress((void**)&pbc2, g_bc2);
    cudaGetSymbolAddress((void**)&psc,  g_sc);
    cudaGetSymbolAddress((void**)&psh,  g_sh);
    cudaGetSymbolAddress((void**)&pbs1, g_bnsum1);
    cudaGetSymbolAddress((void**)&pbq1, g_bnsq1);
    cudaGetSymbolAddress((void**)&pbs2, g_bnsum2);
    cudaGetSymbolAddress((void**)&pbq2, g_bnsq2);

    // ---- init (deg, bn stats, graph accum, out) ----
    zero_init<<<NSB, 256>>>(out, out_size);

    // ---- CSR build (dst-sorted, permuted src + edge_attr) ----
    hist_kernel<<<(N_EDGES + 255) / 256, 256>>>(dst);
    scan1_kernel<<<NSB, 256>>>();
    scan2_kernel<<<1, 256>>>();
    scan3_kernel<<<NSB, 256>>>();
    fill_kernel<<<(N_EDGES + 255) / 256, 256>>>(src, dst, edge_attr);

    // ---- combined edge matrices ----
    combine_kernel<<<1, 256>>>(c1_lin2_w, c1_lin2_b, c1_lin_w, c1_lin_b,
                               c2_lin2_w, c2_lin2_b, c2_lin_w, c2_lin_b);

    dim3 gg((N_NODES + 127) / 128, DD / 128);

    // ---- layer 1: H1 = emb[node_ids] @ W1^T + bc1 (tf32 tensor cores) ----
    gemm_tf32<<<gg, 256>>>(emb, node_ids, nullptr, nullptr, c1_lin_w, pbc1, pA, N_NODES, F_IN);

    // ---- conv1 gather -> agg1 (bufB) + bn1 stats ----
    gather_kernel<<<1024, 256>>>(pA, pC1, pB, pbs1, pbq1);
    bnsc_kernel<<<1, 256>>>(bn1_w, bn1_b, pbs1, pbq1);

    // ---- layer 2: H2 = leaky(bn1(agg1)) @ W2^T + bc2 (BN fused into A-load) ----
    gemm_tf32<<<gg, 256>>>(pB, nullptr, psc, psh, c2_lin_w, pbc2, pA, N_NODES, DD);

    // ---- conv2 gather -> agg2 (bufB) + bn2 stats ----
    gather_kernel<<<1024, 256>>>(pA, pC2, pB, pbs2, pbq2);
    bnsc_kernel<<<1, 256>>>(bn2_w, bn2_b, pbs2, pbq2);

    // ---- gate (read-only) + segment max ----
    int nb = (N_NODES * 32 + 255) / 256;
    gate_kernel<<<nb, 256>>>(pB, gate_w, gate_b, batch);

    // ---- fused softmax + weighted aggregation (unnormalized), then normalize ----
    wfinal_kernel<<<nb, 256>>>(pB, batch, out);
    norm_kernel<<<(N_GRAPHS * DD + 255) / 256, 256>>>(out);
}

// round 9
// speedup vs baseline: 1.1516x; 1.1516x over previous
#include <cuda_runtime.h>
#include <cstdint>

#define N_NODES  50000
#define N_EDGES  800000
#define N_GRAPHS 512
#define N_IDS    51
#define F_IN     128
#define DD       256
#define EPS      1e-5f
#define NEG_SLOPE 0.01f
#define NSB      196          // ceil(N_NODES/256) scan blocks

typedef unsigned long long ull;

// ---------------- scratch (device globals; no allocation allowed) ----------
__device__ float g_bufA[N_NODES * DD];   // H2
__device__ float g_bufB[N_NODES * DD];   // agg1 -> agg2
__device__ float g_HT[N_IDS * DD];       // emb_table @ W1^T + bc1
__device__ float g_C1[4 * DD];
__device__ float g_bc1[DD];
__device__ float g_C2[4 * DD];
__device__ float g_bc2[DD];
__device__ float g_bnsum1[DD];
__device__ float g_bnsq1[DD];
__device__ float g_bnsum2[DD];
__device__ float g_bnsq2[DD];
__device__ float g_sc[DD];
__device__ float g_sh[DD];
__device__ unsigned g_gmax[N_GRAPHS];
__device__ float g_denom[N_GRAPHS];
__device__ float g_gate[N_NODES];
// CSR (dst-sorted, with permuted src, src-node-id and edge_attr)
__device__ int    g_deg[N_NODES];
__device__ int    g_start[N_NODES];
__device__ int    g_cursor[N_NODES];
__device__ int    g_srcs[N_EDGES];
__device__ int    g_srcnid[N_EDGES];
__device__ float4 g_eas[N_EDGES];
__device__ int    g_part[NSB];
__device__ int    g_part2[NSB];

// ---------------- helpers ---------------------------------------------------
__device__ __forceinline__ float leaky(float v) {
    return v >= 0.f ? v : NEG_SLOPE * v;
}
__device__ __forceinline__ unsigned enc_f(float x) {
    unsigned u = __float_as_uint(x);
    return (u & 0x80000000u) ? ~u : (u | 0x80000000u);
}
__device__ __forceinline__ float dec_f(unsigned u) {
    return (u & 0x80000000u) ? __uint_as_float(u ^ 0x80000000u) : __uint_as_float(~u);
}
__device__ __forceinline__ void red_add_v4(float* p, float a, float b, float c, float d) {
    asm volatile("red.global.add.v4.f32 [%0], {%1, %2, %3, %4};"
                 :: "l"(p), "f"(a), "f"(b), "f"(c), "f"(d) : "memory");
}
__device__ __forceinline__ ull dup2(float x) {
    ull r; unsigned u = __float_as_uint(x);
    asm("mov.b64 %0, {%1, %1};" : "=l"(r) : "r"(u));
    return r;
}
__device__ __forceinline__ void fma2(ull& d, ull a, ull b) {
    asm("fma.rn.f32x2 %0, %1, %2, %0;" : "+l"(d) : "l"(a), "l"(b));
}
__device__ __forceinline__ float2 up2(ull v) {
    float2 f; asm("mov.b64 {%0, %1}, %2;" : "=f"(f.x), "=f"(f.y) : "l"(v));
    return f;
}
__device__ __forceinline__ unsigned tf32c(float x) {
    unsigned r;
    asm("cvt.rna.tf32.f32 %0, %1;" : "=r"(r) : "f"(x));
    return r;
}
__device__ __forceinline__ void mma_tf32(float d[4], const unsigned a[4],
                                         unsigned b0, unsigned b1) {
    asm volatile(
        "mma.sync.aligned.m16n8k8.row.col.f32.tf32.tf32.f32 "
        "{%0,%1,%2,%3}, {%4,%5,%6,%7}, {%8,%9}, {%0,%1,%2,%3};"
        : "+f"(d[0]), "+f"(d[1]), "+f"(d[2]), "+f"(d[3])
        : "r"(a[0]), "r"(a[1]), "r"(a[2]), "r"(a[3]), "r"(b0), "r"(b1));
}

// ---------------- zero / init kernels ---------------------------------------
__global__ void zero_init(float* out, int out_n) {
    int i = blockIdx.x * blockDim.x + threadIdx.x;
    if (i < N_NODES) g_deg[i] = 0;
    if (i < DD) {
        g_bnsum1[i] = 0.f; g_bnsq1[i] = 0.f;
        g_bnsum2[i] = 0.f; g_bnsq2[i] = 0.f;
    }
    if (i < N_GRAPHS) { g_gmax[i] = 0u; g_denom[i] = 0.f; }
    for (int k = i; k < out_n; k += gridDim.x * blockDim.x) out[k] = 0.f;
}

// ---------------- CSR build --------------------------------------------------
__global__ void hist_kernel(const int* __restrict__ dst) {
    int e = blockIdx.x * blockDim.x + threadIdx.x;
    if (e < N_EDGES) atomicAdd(&g_deg[__ldg(dst + e)], 1);
}
__global__ void scan1_kernel() {
    __shared__ int sh[256];
    int i = blockIdx.x * 256 + threadIdx.x;
    int v = (i < N_NODES) ? g_deg[i] : 0;
    sh[threadIdx.x] = v; __syncthreads();
#pragma unroll
    for (int off = 1; off < 256; off <<= 1) {
        int tv = (threadIdx.x >= off) ? sh[threadIdx.x - off] : 0;
        __syncthreads();
        sh[threadIdx.x] += tv;
        __syncthreads();
    }
    if (i < N_NODES) g_start[i] = sh[threadIdx.x] - v;
    if (threadIdx.x == 255) g_part[blockIdx.x] = sh[255];
}
__global__ void scan2_kernel() {
    __shared__ int sh[256];
    int t = threadIdx.x;
    int v = (t < NSB) ? g_part[t] : 0;
    sh[t] = v; __syncthreads();
#pragma unroll
    for (int off = 1; off < 256; off <<= 1) {
        int tv = (t >= off) ? sh[t - off] : 0;
        __syncthreads();
        sh[t] += tv;
        __syncthreads();
    }
    if (t < NSB) g_part2[t] = sh[t] - v;
}
__global__ void scan3_kernel() {
    int i = blockIdx.x * 256 + threadIdx.x;
    if (i < N_NODES) {
        int s = g_start[i] + g_part2[blockIdx.x];
        g_start[i] = s;
        g_cursor[i] = s;
    }
}
__global__ void fill_kernel(const int* __restrict__ src,
                            const int* __restrict__ dst,
                            const float* __restrict__ ea,
                            const int* __restrict__ node_ids) {
    int e = blockIdx.x * blockDim.x + threadIdx.x;
    if (e < N_EDGES) {
        int d = __ldg(dst + e);
        int s = __ldg(src + e);
        int p = atomicAdd(&g_cursor[d], 1);
        g_srcs[p] = s;
        g_srcnid[p] = __ldg(node_ids + s);
        g_eas[p] = __ldg((const float4*)ea + e);
    }
}

// ---------------- combined edge matrices ------------------------------------
__global__ void combine_kernel(
    const float* __restrict__ l2w1, const float* __restrict__ l2b1,
    const float* __restrict__ lw1,  const float* __restrict__ lb1,
    const float* __restrict__ l2w2, const float* __restrict__ l2b2,
    const float* __restrict__ lw2,  const float* __restrict__ lb2)
{
    int d = threadIdx.x;   // 256 threads
    {
        float a0 = 0.f, a1 = 0.f, a2 = 0.f, a3 = 0.f, bb = 0.f;
        for (int f = 0; f < F_IN; f++) {
            float w = lw1[d * F_IN + f];
            float4 l2 = *(const float4*)(l2w1 + f * 4);
            a0 += l2.x * w; a1 += l2.y * w; a2 += l2.z * w; a3 += l2.w * w;
            bb += l2b1[f] * w;
        }
        g_C1[0 * DD + d] = a0; g_C1[1 * DD + d] = a1;
        g_C1[2 * DD + d] = a2; g_C1[3 * DD + d] = a3;
        g_bc1[d] = bb + lb1[d];
    }
    {
        float a0 = 0.f, a1 = 0.f, a2 = 0.f, a3 = 0.f, bb = 0.f;
        for (int f = 0; f < DD; f++) {
            float w = lw2[d * DD + f];
            float4 l2 = *(const float4*)(l2w2 + f * 4);
            a0 += l2.x * w; a1 += l2.y * w; a2 += l2.z * w; a3 += l2.w * w;
            bb += l2b2[f] * w;
        }
        g_C2[0 * DD + d] = a0; g_C2[1 * DD + d] = a1;
        g_C2[2 * DD + d] = a2; g_C2[3 * DD + d] = a3;
        g_bc2[d] = bb + lb2[d];
    }
}

// ---------------- HT = emb_table @ W1^T + bc1  (51 x 256, exact fp32) --------
__global__ void ht_kernel(const float* __restrict__ emb,
                          const float* __restrict__ lw1)
{
    __shared__ float ev[F_IN];
    int v = blockIdx.x;     // 0..50
    int d = threadIdx.x;    // 0..255
    if (d < F_IN) ev[d] = emb[v * F_IN + d];
    __syncthreads();
    const float* wr = lw1 + (size_t)d * F_IN;
    float s = 0.f;
#pragma unroll 8
    for (int f = 0; f < F_IN; f++) s += ev[f] * __ldg(wr + f);
    g_HT[v * DD + d] = s + g_bc1[d];
}

// ---------------- GEMM (tf32 tensor cores, bias epilogue) — R6 version -------
// out[m][n] = sum_k A'[m][k] * W[n][k] + bias[n];  A' = leaky(A*sc+sh) if sc.
__global__ void __launch_bounds__(256)
gemm_tf32(const float* __restrict__ A,
          const float* __restrict__ sc, const float* __restrict__ sh,
          const float* __restrict__ W, const float* __restrict__ bias,
          float* __restrict__ out, int M, int K)
{
    __shared__ unsigned As[128 * 36];
    __shared__ unsigned Bs[128 * 36];
    int t = threadIdx.x;
    int lane = t & 31;
    int wid = t >> 5;
    int wm = wid & 3, wn = wid >> 2;       // warp tile: rows wm*32, cols wn*64
    int bm = blockIdx.x * 128;
    int bn = blockIdx.y * 128;

    int lrow = t >> 1;
    int lkh = (t & 1) * 16;

    int m0 = bm + lrow;
    int mc = m0 < M ? m0 : (M - 1);
    const float* Arow = A + (size_t)mc * K;
    const float* Wrow = W + (size_t)(bn + lrow) * K;

    float d[2][8][4];
#pragma unroll
    for (int i = 0; i < 2; i++)
#pragma unroll
        for (int j = 0; j < 8; j++)
#pragma unroll
            for (int c = 0; c < 4; c++) d[i][j][c] = 0.f;

    float4 va[4], vb[4];

    auto load_stage = [&](int kc) {
#pragma unroll
        for (int q = 0; q < 4; q++) {
            va[q] = __ldg((const float4*)(Arow + kc + lkh + q * 4));
            vb[q] = __ldg((const float4*)(Wrow + kc + lkh + q * 4));
        }
        if (sc) {
#pragma unroll
            for (int q = 0; q < 4; q++) {
                int ch = kc + lkh + q * 4;
                float4 s = __ldg((const float4*)(sc + ch));
                float4 h = __ldg((const float4*)(sh + ch));
                va[q].x = leaky(va[q].x * s.x + h.x);
                va[q].y = leaky(va[q].y * s.y + h.y);
                va[q].z = leaky(va[q].z * s.z + h.z);
                va[q].w = leaky(va[q].w * s.w + h.w);
            }
        }
    };
    auto store_stage = [&]() {
        unsigned* ap = As + lrow * 36 + lkh;
        unsigned* bp = Bs + lrow * 36 + lkh;
#pragma unroll
        for (int q = 0; q < 4; q++) {
            *(uint4*)(ap + q * 4) = make_uint4(tf32c(va[q].x), tf32c(va[q].y),
                                               tf32c(va[q].z), tf32c(va[q].w));
            *(uint4*)(bp + q * 4) = make_uint4(tf32c(vb[q].x), tf32c(vb[q].y),
                                               tf32c(vb[q].z), tf32c(vb[q].w));
        }
    };

    load_stage(0);
    store_stage();
    __syncthreads();

    for (int kc = 0; kc < K; kc += 32) {
        bool more = (kc + 32) < K;
        if (more) load_stage(kc + 32);
#pragma unroll
        for (int ks = 0; ks < 4; ks++) {
            int k0 = ks * 8;
            unsigned a[2][4];
            int ra = (wm * 32 + (lane >> 2)) * 36 + k0 + (lane & 3);
#pragma unroll
            for (int i = 0; i < 2; i++) {
                int base = ra + i * 16 * 36;
                a[i][0] = As[base];
                a[i][1] = As[base + 8 * 36];
                a[i][2] = As[base + 4];
                a[i][3] = As[base + 8 * 36 + 4];
            }
            int rb = (wn * 64 + (lane >> 2)) * 36 + k0 + (lane & 3);
#pragma unroll
            for (int j = 0; j < 8; j++) {
                unsigned b0 = Bs[rb + j * 8 * 36];
                unsigned b1 = Bs[rb + j * 8 * 36 + 4];
                mma_tf32(d[0][j], a[0], b0, b1);
                mma_tf32(d[1][j], a[1], b0, b1);
            }
        }
        if (more) {
            __syncthreads();
            store_stage();
            __syncthreads();
        }
    }

    // epilogue (+ bias)
    float2 bsv[8];
#pragma unroll
    for (int j = 0; j < 8; j++) {
        int col = bn + wn * 64 + j * 8 + (lane & 3) * 2;
        bsv[j] = __ldg((const float2*)(bias + col));
    }
#pragma unroll
    for (int i = 0; i < 2; i++) {
        int rg0 = bm + wm * 32 + i * 16 + (lane >> 2);
        int rg1 = rg0 + 8;
#pragma unroll
        for (int j = 0; j < 8; j++) {
            int col = bn + wn * 64 + j * 8 + (lane & 3) * 2;
            if (rg0 < M)
                *(float2*)(out + (size_t)rg0 * DD + col) =
                    make_float2(d[i][j][0] + bsv[j].x, d[i][j][1] + bsv[j].y);
            if (rg1 < M)
                *(float2*)(out + (size_t)rg1 * DD + col) =
                    make_float2(d[i][j][2] + bsv[j].x, d[i][j][3] + bsv[j].y);
        }
    }
}

// ---------------- per-edge packed accumulate (bias pre-folded into H) --------
__device__ __forceinline__ void edge_accum(
    ull acc[4], float4 at, ulonglong2 p, ulonglong2 q,
    const ull c0p[4], const ull c1p[4], const ull c2p[4], const ull c3p[4])
{
    const ull ABS2 = 0x7fffffff7fffffffull;
    const ull D505 = 0x3f0147ae3f0147aeull;  // dup2(0.505f)
    const ull D495 = 0x3efd70a43efd70a4ull;  // dup2(0.495f)
    ull ax = dup2(at.x), ay = dup2(at.y), az = dup2(at.z), aw = dup2(at.w);
    ull hh[4] = {p.x, p.y, q.x, q.y};
#pragma unroll
    for (int i = 0; i < 4; i++) {
        ull m = hh[i];
        fma2(m, ax, c0p[i]); fma2(m, ay, c1p[i]);
        fma2(m, az, c2p[i]); fma2(m, aw, c3p[i]);
        ull ab = m & ABS2;
        fma2(acc[i], D505, m);
        fma2(acc[i], D495, ab);
    }
}

// ---------------- CSR gather (permuted edges, packed f32x2, unroll-4) --------
// srcs gives the row index into H (node index for layer 2, node-id for layer 1)
__global__ void gather_kernel(const float* __restrict__ H,
                              const int* __restrict__ srcs,
                              const float* __restrict__ C,
                              float* __restrict__ agg,
                              float* __restrict__ bnsum,
                              float* __restrict__ bnsq)
{
    __shared__ float ssum[DD];
    __shared__ float ssq[DD];
    int t = threadIdx.x;
    ssum[t] = 0.f; ssq[t] = 0.f;
    __syncthreads();

    int lane = t & 31;
    int wid = (blockIdx.x * blockDim.x + t) >> 5;
    int nw = (gridDim.x * blockDim.x) >> 5;
    int d0 = lane * 8;

    ull c0p[4], c1p[4], c2p[4], c3p[4];
    {
        ulonglong2 u;
        u = *(const ulonglong2*)(C + 0 * DD + d0);     c0p[0] = u.x; c0p[1] = u.y;
        u = *(const ulonglong2*)(C + 0 * DD + d0 + 4); c0p[2] = u.x; c0p[3] = u.y;
        u = *(const ulonglong2*)(C + 1 * DD + d0);     c1p[0] = u.x; c1p[1] = u.y;
        u = *(const ulonglong2*)(C + 1 * DD + d0 + 4); c1p[2] = u.x; c1p[3] = u.y;
        u = *(const ulonglong2*)(C + 2 * DD + d0);     c2p[0] = u.x; c2p[1] = u.y;
        u = *(const ulonglong2*)(C + 2 * DD + d0 + 4); c2p[2] = u.x; c2p[3] = u.y;
        u = *(const ulonglong2*)(C + 3 * DD + d0);     c3p[0] = u.x; c3p[1] = u.y;
        u = *(const ulonglong2*)(C + 3 * DD + d0 + 4); c3p[2] = u.x; c3p[3] = u.y;
    }

    float sA[8], qA[8];
#pragma unroll
    for (int i = 0; i < 8; i++) { sA[i] = 0.f; qA[i] = 0.f; }

    for (int n = wid; n < N_NODES; n += nw) {
        int s0 = __ldg(g_start + n);
        int dg = __ldg(g_deg + n);
        ull acc[4] = {0ull, 0ull, 0ull, 0ull};

        int j = 0;
        for (; j + 3 < dg; j += 4) {
            int sa = __ldg(srcs + s0 + j);
            int sb = __ldg(srcs + s0 + j + 1);
            int sc2 = __ldg(srcs + s0 + j + 2);
            int sd = __ldg(srcs + s0 + j + 3);
            const ulonglong2* ha = (const ulonglong2*)(H + (size_t)sa * DD + d0);
            const ulonglong2* hb = (const ulonglong2*)(H + (size_t)sb * DD + d0);
            const ulonglong2* hc = (const ulonglong2*)(H + (size_t)sc2 * DD + d0);
            const ulonglong2* hd = (const ulonglong2*)(H + (size_t)sd * DD + d0);
            ulonglong2 pa = ha[0], qa = ha[1];
            ulonglong2 pb = hb[0], qb = hb[1];
            ulonglong2 pc = hc[0], qc = hc[1];
            ulonglong2 pd = hd[0], qd = hd[1];
            float4 at0 = __ldg((const float4*)g_eas + s0 + j);
            float4 at1 = __ldg((const float4*)g_eas + s0 + j + 1);
            float4 at2 = __ldg((const float4*)g_eas + s0 + j + 2);
            float4 at3 = __ldg((const float4*)g_eas + s0 + j + 3);
            edge_accum(acc, at0, pa, qa, c0p, c1p, c2p, c3p);
            edge_accum(acc, at1, pb, qb, c0p, c1p, c2p, c3p);
            edge_accum(acc, at2, pc, qc, c0p, c1p, c2p, c3p);
            edge_accum(acc, at3, pd, qd, c0p, c1p, c2p, c3p);
        }
        for (; j < dg; j++) {
            int sa = __ldg(srcs + s0 + j);
            float4 at0 = __ldg((const float4*)g_eas + s0 + j);
            const ulonglong2* ha = (const ulonglong2*)(H + (size_t)sa * DD + d0);
            ulonglong2 pa = ha[0], qa = ha[1];
            edge_accum(acc, at0, pa, qa, c0p, c1p, c2p, c3p);
        }

        ulonglong2* op = (ulonglong2*)(agg + (size_t)n * DD + d0);
        op[0] = make_ulonglong2(acc[0], acc[1]);
        op[1] = make_ulonglong2(acc[2], acc[3]);

#pragma unroll
        for (int i = 0; i < 4; i++) {
            float2 f = up2(acc[i]);
            sA[2 * i]     += f.x;  qA[2 * i]     += f.x * f.x;
            sA[2 * i + 1] += f.y;  qA[2 * i + 1] += f.y * f.y;
        }
    }
#pragma unroll
    for (int i = 0; i < 8; i++) {
        atomicAdd(&ssum[d0 + i], sA[i]);
        atomicAdd(&ssq[d0 + i], qA[i]);
    }
    __syncthreads();
    atomicAdd(&bnsum[t], ssum[t]);
    atomicAdd(&bnsq[t], ssq[t]);
}

// ---------------- BN scale/shift from stats ----------------------------------
__global__ void bnsc_kernel(const float* __restrict__ w, const float* __restrict__ b,
                            const float* __restrict__ bnsum, const float* __restrict__ bnsq)
{
    int c = threadIdx.x;
    const float invN = 1.f / (float)N_NODES;
    float m = bnsum[c] * invN;
    float var = bnsq[c] * invN - m * m;
    float s = w[c] * rsqrtf(var + EPS);
    g_sc[c] = s;
    g_sh[c] = b[c] - m * s;
}

// ---------------- gate (read-only) + segment max ------------------------------
__global__ void gate_kernel(const float* __restrict__ X,
                            const float* __restrict__ gw,
                            const float* __restrict__ gb,
                            const int* __restrict__ batch)
{
    int wid = (blockIdx.x * blockDim.x + threadIdx.x) >> 5;
    int lane = threadIdx.x & 31;
    if (wid >= N_NODES) return;
    int d0 = lane * 8;
    const float4* xp = (const float4*)(X + (size_t)wid * DD + d0);
    float4 h0 = __ldg(xp), h1 = __ldg(xp + 1);
    float v[8] = {h0.x, h0.y, h0.z, h0.w, h1.x, h1.y, h1.z, h1.w};
    float gsum = 0.f;
#pragma unroll
    for (int i = 0; i < 8; i++) {
        int ch = d0 + i;
        gsum += leaky(v[i] * g_sc[ch] + g_sh[ch]) * __ldg(gw + ch);
    }
#pragma unroll
    for (int off = 16; off; off >>= 1) gsum += __shfl_xor_sync(0xffffffffu, gsum, off);
    if (lane == 0) {
        gsum += __ldg(gb);
        g_gate[wid] = gsum;
        atomicMax(&g_gmax[__ldg(batch + wid)], enc_f(gsum));
    }
}

// ---------------- fused exp + denom + unnormalized weighted aggregation ------
__global__ void wfinal_kernel(const float* __restrict__ X,
                              const int* __restrict__ batch,
                              float* __restrict__ out)
{
    int wid = (blockIdx.x * blockDim.x + threadIdx.x) >> 5;
    int lane = threadIdx.x & 31;
    if (wid >= N_NODES) return;
    int b = __ldg(batch + wid);
    float e = __expf(g_gate[wid] - dec_f(g_gmax[b]));
    if (lane == 0) atomicAdd(&g_denom[b], e);
    int d0 = lane * 8;
    const float4* xp = (const float4*)(X + (size_t)wid * DD + d0);
    float4 h0 = __ldg(xp), h1 = __ldg(xp + 1);
    float v[8] = {h0.x, h0.y, h0.z, h0.w, h1.x, h1.y, h1.z, h1.w};
#pragma unroll
    for (int i = 0; i < 8; i++) {
        int ch = d0 + i;
        v[i] = e * leaky(v[i] * g_sc[ch] + g_sh[ch]);
    }
    float* op = out + (size_t)b * DD + d0;
    red_add_v4(op,     v[0], v[1], v[2], v[3]);
    red_add_v4(op + 4, v[4], v[5], v[6], v[7]);
}

// ---------------- normalize out by denom --------------------------------------
__global__ void norm_kernel(float* __restrict__ out)
{
    int i = blockIdx.x * blockDim.x + threadIdx.x;
    if (i >= N_GRAPHS * DD) return;
    float dn = g_denom[i >> 8];
    out[i] = dn > 0.f ? out[i] / dn : 0.f;
}

// ---------------- launch -----------------------------------------------------
extern "C" void kernel_launch(void* const* d_in, const int* in_sizes, int n_in,
                              void* d_out, int out_size)
{
    const int*   node_ids  = (const int*)d_in[0];
    const int*   edge_index= (const int*)d_in[1];
    const float* edge_attr = (const float*)d_in[2];
    const int*   batch     = (const int*)d_in[3];
    const float* emb       = (const float*)d_in[4];
    const float* c1_lin2_w = (const float*)d_in[5];
    const float* c1_lin2_b = (const float*)d_in[6];
    const float* c1_lin_w  = (const float*)d_in[7];
    const float* c1_lin_b  = (const float*)d_in[8];
    const float* bn1_w     = (const float*)d_in[9];
    const float* bn1_b     = (const float*)d_in[10];
    const float* c2_lin2_w = (const float*)d_in[11];
    const float* c2_lin2_b = (const float*)d_in[12];
    const float* c2_lin_w  = (const float*)d_in[13];
    const float* c2_lin_b  = (const float*)d_in[14];
    const float* bn2_w     = (const float*)d_in[15];
    const float* bn2_b     = (const float*)d_in[16];
    const float* gate_w    = (const float*)d_in[17];
    const float* gate_b    = (const float*)d_in[18];
    float* out = (float*)d_out;

    const int* src = edge_index;
    const int* dst = edge_index + N_EDGES;

    float *pA, *pB, *pHT, *pC1, *pC2, *pbc2, *psc, *psh;
    float *pbs1, *pbq1, *pbs2, *pbq2;
    int *pSrcs, *pSrcnid;
    cudaGetSymbolAddress((void**)&pA,   g_bufA);
    cudaGetSymbolAddress((void**)&pB,   g_bufB);
    cudaGetSymbolAddress((void**)&pHT,  g_HT);
    cudaGetSymbolAddress((void**)&pC1,  g_C1);
    cudaGetSymbolAddress((void**)&pC2,  g_C2);
    cudaGetSymbolAddress((void**)&pbc2, g_bc2);
    cudaGetSymbolAddress((void**)&psc,  g_sc);
    cudaGetSymbolAddress((void**)&psh,  g_sh);
    cudaGetSymbolAddress((void**)&pbs1, g_bnsum1);
    cudaGetSymbolAddress((void**)&pbq1, g_bnsq1);
    cudaGetSymbolAddress((void**)&pbs2, g_bnsum2);
    cudaGetSymbolAddress((void**)&pbq2, g_bnsq2);
    cudaGetSymbolAddress((void**)&pSrcs,   g_srcs);
    cudaGetSymbolAddress((void**)&pSrcnid, g_srcnid);

    // ---- init (deg, bn stats, graph accum, out) ----
    zero_init<<<NSB, 256>>>(out, out_size);

    // ---- CSR build (dst-sorted, permuted src + src-node-id + edge_attr) ----
    hist_kernel<<<(N_EDGES + 255) / 256, 256>>>(dst);
    scan1_kernel<<<NSB, 256>>>();
    scan2_kernel<<<1, 256>>>();
    scan3_kernel<<<NSB, 256>>>();
    fill_kernel<<<(N_EDGES + 255) / 256, 256>>>(src, dst, edge_attr, node_ids);

    // ---- combined edge matrices, then HT (replaces GEMM1 entirely) ----
    combine_kernel<<<1, 256>>>(c1_lin2_w, c1_lin2_b, c1_lin_w, c1_lin_b,
                               c2_lin2_w, c2_lin2_b, c2_lin_w, c2_lin_b);
    ht_kernel<<<N_IDS, 256>>>(emb, c1_lin_w);

    // ---- conv1 gather from L1-resident HT -> agg1 (bufB) + bn1 stats ----
    gather_kernel<<<1024, 256>>>(pHT, pSrcnid, pC1, pB, pbs1, pbq1);
    bnsc_kernel<<<1, 256>>>(bn1_w, bn1_b, pbs1, pbq1);

    // ---- layer 2: H2 = leaky(bn1(agg1)) @ W2^T + bc2 (BN fused into A-load) ----
    dim3 gg((N_NODES + 127) / 128, DD / 128);
    gemm_tf32<<<gg, 256>>>(pB, psc, psh, c2_lin_w, pbc2, pA, N_NODES, DD);

    // ---- conv2 gather -> agg2 (bufB) + bn2 stats ----
    gather_kernel<<<1024, 256>>>(pA, pSrcs, pC2, pB, pbs2, pbq2);
    bnsc_kernel<<<1, 256>>>(bn2_w, bn2_b, pbs2, pbq2);

    // ---- gate (read-only) + segment max ----
    int nb = (N_NODES * 32 + 255) / 256;
    gate_kernel<<<nb, 256>>>(pB, gate_w, gate_b, batch);

    // ---- fused softmax + weighted aggregation (unnormalized), then normalize ----
    wfinal_kernel<<<nb, 256>>>(pB, batch, out);
    norm_kernel<<<(N_GRAPHS * DD + 255) / 256, 256>>>(out);
}

// round 10
// speedup vs baseline: 1.2543x; 1.0891x over previous
#include <cuda_runtime.h>
#include <cuda_fp16.h>
#include <cstdint>

#define N_NODES  50000
#define N_EDGES  800000
#define N_GRAPHS 512
#define N_IDS    51
#define F_IN     128
#define DD       256
#define EPS      1e-5f
#define NEG_SLOPE 0.01f
#define NSB      196          // ceil(N_NODES/256) scan blocks

typedef unsigned long long ull;

// ---------------- scratch (device globals; no allocation allowed) ----------
__device__ float g_bufA[N_NODES * DD];   // H2 (stored as __half, reinterpreted)
__device__ float g_bufB[N_NODES * DD];   // agg1 -> agg2
__device__ float g_HT[N_IDS * DD];       // emb_table @ W1^T + bc1
__device__ float g_C1[4 * DD];
__device__ float g_bc1[DD];
__device__ float g_C2[4 * DD];
__device__ float g_bc2[DD];
__device__ float g_bnsum1[DD];
__device__ float g_bnsq1[DD];
__device__ float g_bnsum2[DD];
__device__ float g_bnsq2[DD];
__device__ float g_sc[DD];
__device__ float g_sh[DD];
__device__ float g_gate[N_NODES];
// CSR (dst-sorted, with permuted src, src-node-id and edge_attr)
__device__ int    g_deg[N_NODES];
__device__ int    g_start[N_NODES];
__device__ int    g_cursor[N_NODES];
__device__ int    g_srcs[N_EDGES];
__device__ int    g_srcnid[N_EDGES];
__device__ float4 g_eas[N_EDGES];
__device__ int    g_part[NSB];
__device__ int    g_part2[NSB];

// ---------------- helpers ---------------------------------------------------
__device__ __forceinline__ float leaky(float v) {
    return v >= 0.f ? v : NEG_SLOPE * v;
}
__device__ __forceinline__ ull dup2(float x) {
    ull r; unsigned u = __float_as_uint(x);
    asm("mov.b64 %0, {%1, %1};" : "=l"(r) : "r"(u));
    return r;
}
__device__ __forceinline__ void fma2(ull& d, ull a, ull b) {
    asm("fma.rn.f32x2 %0, %1, %2, %0;" : "+l"(d) : "l"(a), "l"(b));
}
__device__ __forceinline__ float2 up2(ull v) {
    float2 f; asm("mov.b64 {%0, %1}, %2;" : "=f"(f.x), "=f"(f.y) : "l"(v));
    return f;
}
__device__ __forceinline__ ull pack2(float lo, float hi) {
    ull r;
    asm("mov.b64 %0, {%1, %2};" : "=l"(r) : "f"(lo), "f"(hi));
    return r;
}
__device__ __forceinline__ unsigned tf32c(float x) {
    unsigned r;
    asm("cvt.rna.tf32.f32 %0, %1;" : "=r"(r) : "f"(x));
    return r;
}
__device__ __forceinline__ void mma_tf32(float d[4], const unsigned a[4],
                                         unsigned b0, unsigned b1) {
    asm volatile(
        "mma.sync.aligned.m16n8k8.row.col.f32.tf32.tf32.f32 "
        "{%0,%1,%2,%3}, {%4,%5,%6,%7}, {%8,%9}, {%0,%1,%2,%3};"
        : "+f"(d[0]), "+f"(d[1]), "+f"(d[2]), "+f"(d[3])
        : "r"(a[0]), "r"(a[1]), "r"(a[2]), "r"(a[3]), "r"(b0), "r"(b1));
}

// ---------------- zero / init kernels ---------------------------------------
__global__ void zero_init() {
    int i = blockIdx.x * blockDim.x + threadIdx.x;
    if (i < N_NODES) g_deg[i] = 0;
    if (i < DD) {
        g_bnsum1[i] = 0.f; g_bnsq1[i] = 0.f;
        g_bnsum2[i] = 0.f; g_bnsq2[i] = 0.f;
    }
}

// ---------------- CSR build --------------------------------------------------
__global__ void hist_kernel(const int* __restrict__ dst) {
    int e = blockIdx.x * blockDim.x + threadIdx.x;
    if (e < N_EDGES) atomicAdd(&g_deg[__ldg(dst + e)], 1);
}
__global__ void scan1_kernel() {
    __shared__ int sh[256];
    int i = blockIdx.x * 256 + threadIdx.x;
    int v = (i < N_NODES) ? g_deg[i] : 0;
    sh[threadIdx.x] = v; __syncthreads();
#pragma unroll
    for (int off = 1; off < 256; off <<= 1) {
        int tv = (threadIdx.x >= off) ? sh[threadIdx.x - off] : 0;
        __syncthreads();
        sh[threadIdx.x] += tv;
        __syncthreads();
    }
    if (i < N_NODES) g_start[i] = sh[threadIdx.x] - v;
    if (threadIdx.x == 255) g_part[blockIdx.x] = sh[255];
}
__global__ void scan2_kernel() {
    __shared__ int sh[256];
    int t = threadIdx.x;
    int v = (t < NSB) ? g_part[t] : 0;
    sh[t] = v; __syncthreads();
#pragma unroll
    for (int off = 1; off < 256; off <<= 1) {
        int tv = (t >= off) ? sh[t - off] : 0;
        __syncthreads();
        sh[t] += tv;
        __syncthreads();
    }
    if (t < NSB) g_part2[t] = sh[t] - v;
}
__global__ void scan3_kernel() {
    int i = blockIdx.x * 256 + threadIdx.x;
    if (i < N_NODES) {
        int s = g_start[i] + g_part2[blockIdx.x];
        g_start[i] = s;
        g_cursor[i] = s;
    }
}
__global__ void fill_kernel(const int* __restrict__ src,
                            const int* __restrict__ dst,
                            const float* __restrict__ ea,
                            const int* __restrict__ node_ids) {
    int e = blockIdx.x * blockDim.x + threadIdx.x;
    if (e < N_EDGES) {
        int d = __ldg(dst + e);
        int s = __ldg(src + e);
        int p = atomicAdd(&g_cursor[d], 1);
        g_srcs[p] = s;
        g_srcnid[p] = __ldg(node_ids + s);
        g_eas[p] = __ldg((const float4*)ea + e);
    }
}

// ---------------- combined edge matrices ------------------------------------
__global__ void combine_kernel(
    const float* __restrict__ l2w1, const float* __restrict__ l2b1,
    const float* __restrict__ lw1,  const float* __restrict__ lb1,
    const float* __restrict__ l2w2, const float* __restrict__ l2b2,
    const float* __restrict__ lw2,  const float* __restrict__ lb2)
{
    int d = threadIdx.x;   // 256 threads
    {
        float a0 = 0.f, a1 = 0.f, a2 = 0.f, a3 = 0.f, bb = 0.f;
        for (int f = 0; f < F_IN; f++) {
            float w = lw1[d * F_IN + f];
            float4 l2 = *(const float4*)(l2w1 + f * 4);
            a0 += l2.x * w; a1 += l2.y * w; a2 += l2.z * w; a3 += l2.w * w;
            bb += l2b1[f] * w;
        }
        g_C1[0 * DD + d] = a0; g_C1[1 * DD + d] = a1;
        g_C1[2 * DD + d] = a2; g_C1[3 * DD + d] = a3;
        g_bc1[d] = bb + lb1[d];
    }
    {
        float a0 = 0.f, a1 = 0.f, a2 = 0.f, a3 = 0.f, bb = 0.f;
        for (int f = 0; f < DD; f++) {
            float w = lw2[d * DD + f];
            float4 l2 = *(const float4*)(l2w2 + f * 4);
            a0 += l2.x * w; a1 += l2.y * w; a2 += l2.z * w; a3 += l2.w * w;
            bb += l2b2[f] * w;
        }
        g_C2[0 * DD + d] = a0; g_C2[1 * DD + d] = a1;
        g_C2[2 * DD + d] = a2; g_C2[3 * DD + d] = a3;
        g_bc2[d] = bb + lb2[d];
    }
}

// ---------------- HT = emb_table @ W1^T + bc1  (51 x 256, exact fp32) --------
__global__ void ht_kernel(const float* __restrict__ emb,
                          const float* __restrict__ lw1)
{
    __shared__ float ev[F_IN];
    int v = blockIdx.x;     // 0..50
    int d = threadIdx.x;    // 0..255
    if (d < F_IN) ev[d] = emb[v * F_IN + d];
    __syncthreads();
    const float* wr = lw1 + (size_t)d * F_IN;
    float s = 0.f;
#pragma unroll 8
    for (int f = 0; f < F_IN; f++) s += ev[f] * __ldg(wr + f);
    g_HT[v * DD + d] = s + g_bc1[d];
}

// ---------------- GEMM (tf32 tensor cores, bias epilogue, half output) -------
// out_h[m][n] = (half) (sum_k A'[m][k] * W[n][k] + bias[n]);  A'=leaky(A*sc+sh)
__global__ void __launch_bounds__(256)
gemm_tf32(const float* __restrict__ A,
          const float* __restrict__ sc, const float* __restrict__ sh,
          const float* __restrict__ W, const float* __restrict__ bias,
          __half* __restrict__ out, int M, int K)
{
    __shared__ unsigned As[128 * 36];
    __shared__ unsigned Bs[128 * 36];
    int t = threadIdx.x;
    int lane = t & 31;
    int wid = t >> 5;
    int wm = wid & 3, wn = wid >> 2;       // warp tile: rows wm*32, cols wn*64
    int bm = blockIdx.x * 128;
    int bn = blockIdx.y * 128;

    int lrow = t >> 1;
    int lkh = (t & 1) * 16;

    int m0 = bm + lrow;
    int mc = m0 < M ? m0 : (M - 1);
    const float* Arow = A + (size_t)mc * K;
    const float* Wrow = W + (size_t)(bn + lrow) * K;

    float d[2][8][4];
#pragma unroll
    for (int i = 0; i < 2; i++)
#pragma unroll
        for (int j = 0; j < 8; j++)
#pragma unroll
            for (int c = 0; c < 4; c++) d[i][j][c] = 0.f;

    float4 va[4], vb[4];

    auto load_stage = [&](int kc) {
#pragma unroll
        for (int q = 0; q < 4; q++) {
            va[q] = __ldg((const float4*)(Arow + kc + lkh + q * 4));
            vb[q] = __ldg((const float4*)(Wrow + kc + lkh + q * 4));
        }
#pragma unroll
        for (int q = 0; q < 4; q++) {
            int ch = kc + lkh + q * 4;
            float4 s = __ldg((const float4*)(sc + ch));
            float4 h = __ldg((const float4*)(sh + ch));
            va[q].x = leaky(va[q].x * s.x + h.x);
            va[q].y = leaky(va[q].y * s.y + h.y);
            va[q].z = leaky(va[q].z * s.z + h.z);
            va[q].w = leaky(va[q].w * s.w + h.w);
        }
    };
    auto store_stage = [&]() {
        unsigned* ap = As + lrow * 36 + lkh;
        unsigned* bp = Bs + lrow * 36 + lkh;
#pragma unroll
        for (int q = 0; q < 4; q++) {
            *(uint4*)(ap + q * 4) = make_uint4(tf32c(va[q].x), tf32c(va[q].y),
                                               tf32c(va[q].z), tf32c(va[q].w));
            *(uint4*)(bp + q * 4) = make_uint4(tf32c(vb[q].x), tf32c(vb[q].y),
                                               tf32c(vb[q].z), tf32c(vb[q].w));
        }
    };

    load_stage(0);
    store_stage();
    __syncthreads();

    for (int kc = 0; kc < K; kc += 32) {
        bool more = (kc + 32) < K;
        if (more) load_stage(kc + 32);
#pragma unroll
        for (int ks = 0; ks < 4; ks++) {
            int k0 = ks * 8;
            unsigned a[2][4];
            int ra = (wm * 32 + (lane >> 2)) * 36 + k0 + (lane & 3);
#pragma unroll
            for (int i = 0; i < 2; i++) {
                int base = ra + i * 16 * 36;
                a[i][0] = As[base];
                a[i][1] = As[base + 8 * 36];
                a[i][2] = As[base + 4];
                a[i][3] = As[base + 8 * 36 + 4];
            }
            int rb = (wn * 64 + (lane >> 2)) * 36 + k0 + (lane & 3);
#pragma unroll
            for (int j = 0; j < 8; j++) {
                unsigned b0 = Bs[rb + j * 8 * 36];
                unsigned b1 = Bs[rb + j * 8 * 36 + 4];
                mma_tf32(d[0][j], a[0], b0, b1);
                mma_tf32(d[1][j], a[1], b0, b1);
            }
        }
        if (more) {
            __syncthreads();
            store_stage();
            __syncthreads();
        }
    }

    // epilogue: +bias, convert to half
    float2 bsv[8];
#pragma unroll
    for (int j = 0; j < 8; j++) {
        int col = bn + wn * 64 + j * 8 + (lane & 3) * 2;
        bsv[j] = __ldg((const float2*)(bias + col));
    }
#pragma unroll
    for (int i = 0; i < 2; i++) {
        int rg0 = bm + wm * 32 + i * 16 + (lane >> 2);
        int rg1 = rg0 + 8;
#pragma unroll
        for (int j = 0; j < 8; j++) {
            int col = bn + wn * 64 + j * 8 + (lane & 3) * 2;
            if (rg0 < M)
                *(__half2*)(out + (size_t)rg0 * DD + col) =
                    __floats2half2_rn(d[i][j][0] + bsv[j].x, d[i][j][1] + bsv[j].y);
            if (rg1 < M)
                *(__half2*)(out + (size_t)rg1 * DD + col) =
                    __floats2half2_rn(d[i][j][2] + bsv[j].x, d[i][j][3] + bsv[j].y);
        }
    }
}

// ---------------- per-edge packed accumulate (bias pre-folded into H) --------
__device__ __forceinline__ void edge_accum(
    ull acc[4], float4 at, const ull hh[4],
    const ull c0p[4], const ull c1p[4], const ull c2p[4], const ull c3p[4])
{
    const ull ABS2 = 0x7fffffff7fffffffull;
    const ull D505 = 0x3f0147ae3f0147aeull;  // dup2(0.505f)
    const ull D495 = 0x3efd70a43efd70a4ull;  // dup2(0.495f)
    ull ax = dup2(at.x), ay = dup2(at.y), az = dup2(at.z), aw = dup2(at.w);
#pragma unroll
    for (int i = 0; i < 4; i++) {
        ull m = hh[i];
        fma2(m, ax, c0p[i]); fma2(m, ay, c1p[i]);
        fma2(m, az, c2p[i]); fma2(m, aw, c3p[i]);
        ull ab = m & ABS2;
        fma2(acc[i], D505, m);
        fma2(acc[i], D495, ab);
    }
}

// ---------------- CSR gather (fp32 or fp16 H rows) ----------------------------
template <bool HALF>
__global__ void gather_kernel(const void* __restrict__ Hv,
                              const int* __restrict__ srcs,
                              const float* __restrict__ C,
                              float* __restrict__ agg,
                              float* __restrict__ bnsum,
                              float* __restrict__ bnsq)
{
    __shared__ float ssum[DD];
    __shared__ float ssq[DD];
    int t = threadIdx.x;
    ssum[t] = 0.f; ssq[t] = 0.f;
    __syncthreads();

    int lane = t & 31;
    int wid = (blockIdx.x * blockDim.x + t) >> 5;
    int nw = (gridDim.x * blockDim.x) >> 5;
    int d0 = lane * 8;

    ull c0p[4], c1p[4], c2p[4], c3p[4];
    {
        ulonglong2 u;
        u = *(const ulonglong2*)(C + 0 * DD + d0);     c0p[0] = u.x; c0p[1] = u.y;
        u = *(const ulonglong2*)(C + 0 * DD + d0 + 4); c0p[2] = u.x; c0p[3] = u.y;
        u = *(const ulonglong2*)(C + 1 * DD + d0);     c1p[0] = u.x; c1p[1] = u.y;
        u = *(const ulonglong2*)(C + 1 * DD + d0 + 4); c1p[2] = u.x; c1p[3] = u.y;
        u = *(const ulonglong2*)(C + 2 * DD + d0);     c2p[0] = u.x; c2p[1] = u.y;
        u = *(const ulonglong2*)(C + 2 * DD + d0 + 4); c2p[2] = u.x; c2p[3] = u.y;
        u = *(const ulonglong2*)(C + 3 * DD + d0);     c3p[0] = u.x; c3p[1] = u.y;
        u = *(const ulonglong2*)(C + 3 * DD + d0 + 4); c3p[2] = u.x; c3p[3] = u.y;
    }

    const float* Hf = (const float*)Hv;
    const __half* Hh = (const __half*)Hv;

    auto load_h = [&](int row, ull hh[4]) {
        if (HALF) {
            uint4 u = __ldg((const uint4*)(Hh + (size_t)row * DD + d0));
            float2 f0 = __half22float2(*(__half2*)&u.x);
            float2 f1 = __half22float2(*(__half2*)&u.y);
            float2 f2 = __half22float2(*(__half2*)&u.z);
            float2 f3 = __half22float2(*(__half2*)&u.w);
            hh[0] = pack2(f0.x, f0.y); hh[1] = pack2(f1.x, f1.y);
            hh[2] = pack2(f2.x, f2.y); hh[3] = pack2(f3.x, f3.y);
        } else {
            const ulonglong2* hp = (const ulonglong2*)(Hf + (size_t)row * DD + d0);
            ulonglong2 p = hp[0], q = hp[1];
            hh[0] = p.x; hh[1] = p.y; hh[2] = q.x; hh[3] = q.y;
        }
    };

    float sA[8], qA[8];
#pragma unroll
    for (int i = 0; i < 8; i++) { sA[i] = 0.f; qA[i] = 0.f; }

    for (int n = wid; n < N_NODES; n += nw) {
        int s0 = __ldg(g_start + n);
        int dg = __ldg(g_deg + n);
        ull acc[4] = {0ull, 0ull, 0ull, 0ull};

        int j = 0;
        for (; j + 3 < dg; j += 4) {
            int sa = __ldg(srcs + s0 + j);
            int sb = __ldg(srcs + s0 + j + 1);
            int sc2 = __ldg(srcs + s0 + j + 2);
            int sd = __ldg(srcs + s0 + j + 3);
            ull ha[4], hb[4], hc[4], hd[4];
            load_h(sa, ha); load_h(sb, hb); load_h(sc2, hc); load_h(sd, hd);
            float4 at0 = __ldg((const float4*)g_eas + s0 + j);
            float4 at1 = __ldg((const float4*)g_eas + s0 + j + 1);
            float4 at2 = __ldg((const float4*)g_eas + s0 + j + 2);
            float4 at3 = __ldg((const float4*)g_eas + s0 + j + 3);
            edge_accum(acc, at0, ha, c0p, c1p, c2p, c3p);
            edge_accum(acc, at1, hb, c0p, c1p, c2p, c3p);
            edge_accum(acc, at2, hc, c0p, c1p, c2p, c3p);
            edge_accum(acc, at3, hd, c0p, c1p, c2p, c3p);
        }
        for (; j < dg; j++) {
            int sa = __ldg(srcs + s0 + j);
            float4 at0 = __ldg((const float4*)g_eas + s0 + j);
            ull ha[4];
            load_h(sa, ha);
            edge_accum(acc, at0, ha, c0p, c1p, c2p, c3p);
        }

        ulonglong2* op = (ulonglong2*)(agg + (size_t)n * DD + d0);
        op[0] = make_ulonglong2(acc[0], acc[1]);
        op[1] = make_ulonglong2(acc[2], acc[3]);

#pragma unroll
        for (int i = 0; i < 4; i++) {
            float2 f = up2(acc[i]);
            sA[2 * i]     += f.x;  qA[2 * i]     += f.x * f.x;
            sA[2 * i + 1] += f.y;  qA[2 * i + 1] += f.y * f.y;
        }
    }
#pragma unroll
    for (int i = 0; i < 8; i++) {
        atomicAdd(&ssum[d0 + i], sA[i]);
        atomicAdd(&ssq[d0 + i], qA[i]);
    }
    __syncthreads();
    atomicAdd(&bnsum[t], ssum[t]);
    atomicAdd(&bnsq[t], ssq[t]);
}

// ---------------- BN scale/shift from stats ----------------------------------
__global__ void bnsc_kernel(const float* __restrict__ w, const float* __restrict__ b,
                            const float* __restrict__ bnsum, const float* __restrict__ bnsq)
{
    int c = threadIdx.x;
    const float invN = 1.f / (float)N_NODES;
    float m = bnsum[c] * invN;
    float var = bnsq[c] * invN - m * m;
    float s = w[c] * rsqrtf(var + EPS);
    g_sc[c] = s;
    g_sh[c] = b[c] - m * s;
}

// ---------------- fused attention: gate + softmax + weighted mean -------------
// One block per graph (batch is sorted -> contiguous node ranges).
__device__ __forceinline__ int lbound(const int* a, int v) {
    int lo = 0, hi = N_NODES;
    while (lo < hi) {
        int m = (lo + hi) >> 1;
        if (__ldg(a + m) < v) lo = m + 1; else hi = m;
    }
    return lo;
}

__global__ void attn_kernel(const float* __restrict__ X,
                            const int* __restrict__ batch,
                            const float* __restrict__ gw,
                            const float* __restrict__ gb,
                            float* __restrict__ out)
{
    __shared__ int sr0, sr1;
    __shared__ float smax[8];
    __shared__ float sgmax;
    int g = blockIdx.x;
    int t = threadIdx.x;
    int lane = t & 31, w = t >> 5;

    if (t == 0) { sr0 = lbound(batch, g); sr1 = lbound(batch, g + 1); }
    __syncthreads();
    int r0 = sr0, r1 = sr1;

    // pass 1: gates + block max (warp per node)
    float wmax = -3.4e38f;
    {
        int d0 = lane * 8;
        float gwv[8], scv[8], shv[8];
#pragma unroll
        for (int i = 0; i < 8; i++) {
            gwv[i] = __ldg(gw + d0 + i);
            scv[i] = g_sc[d0 + i];
            shv[i] = g_sh[d0 + i];
        }
        for (int n = r0 + w; n < r1; n += 8) {
            const float4* xp = (const float4*)(X + (size_t)n * DD + d0);
            float4 h0 = __ldg(xp), h1 = __ldg(xp + 1);
            float v[8] = {h0.x, h0.y, h0.z, h0.w, h1.x, h1.y, h1.z, h1.w};
            float gsum = 0.f;
#pragma unroll
            for (int i = 0; i < 8; i++)
                gsum += leaky(v[i] * scv[i] + shv[i]) * gwv[i];
#pragma unroll
            for (int off = 16; off; off >>= 1)
                gsum += __shfl_xor_sync(0xffffffffu, gsum, off);
            if (lane == 0) {
                gsum += __ldg(gb);
                g_gate[n] = gsum;
                wmax = fmaxf(wmax, gsum);
            }
        }
    }
    if (lane == 0) smax[w] = wmax;
    __syncthreads();
    if (t == 0) {
        float m = smax[0];
#pragma unroll
        for (int i = 1; i < 8; i++) m = fmaxf(m, smax[i]);
        sgmax = m;
    }
    __syncthreads();
    float gmax = sgmax;

    // pass 2: per-channel weighted accumulation (thread = channel)
    float sc_c = g_sc[t], sh_c = g_sh[t];
    float acc = 0.f, denom = 0.f;
    for (int n = r0; n < r1; n++) {
        float e = __expf(g_gate[n] - gmax);
        denom += e;
        float x = __ldg(X + (size_t)n * DD + t);
        acc += e * leaky(x * sc_c + sh_c);
    }
    out[(size_t)g * DD + t] = denom > 0.f ? acc / denom : 0.f;
}

// ---------------- launch -----------------------------------------------------
extern "C" void kernel_launch(void* const* d_in, const int* in_sizes, int n_in,
                              void* d_out, int out_size)
{
    const int*   node_ids  = (const int*)d_in[0];
    const int*   edge_index= (const int*)d_in[1];
    const float* edge_attr = (const float*)d_in[2];
    const int*   batch     = (const int*)d_in[3];
    const float* emb       = (const float*)d_in[4];
    const float* c1_lin2_w = (const float*)d_in[5];
    const float* c1_lin2_b = (const float*)d_in[6];
    const float* c1_lin_w  = (const float*)d_in[7];
    const float* c1_lin_b  = (const float*)d_in[8];
    const float* bn1_w     = (const float*)d_in[9];
    const float* bn1_b     = (const float*)d_in[10];
    const float* c2_lin2_w = (const float*)d_in[11];
    const float* c2_lin2_b = (const float*)d_in[12];
    const float* c2_lin_w  = (const float*)d_in[13];
    const float* c2_lin_b  = (const float*)d_in[14];
    const float* bn2_w     = (const float*)d_in[15];
    const float* bn2_b     = (const float*)d_in[16];
    const float* gate_w    = (const float*)d_in[17];
    const float* gate_b    = (const float*)d_in[18];
    float* out = (float*)d_out;

    const int* src = edge_index;
    const int* dst = edge_index + N_EDGES;

    float *pA, *pB, *pHT, *pC1, *pC2, *pbc2, *psc, *psh;
    float *pbs1, *pbq1, *pbs2, *pbq2;
    int *pSrcs, *pSrcnid;
    cudaGetSymbolAddress((void**)&pA,   g_bufA);
    cudaGetSymbolAddress((void**)&pB,   g_bufB);
    cudaGetSymbolAddress((void**)&pHT,  g_HT);
    cudaGetSymbolAddress((void**)&pC1,  g_C1);
    cudaGetSymbolAddress((void**)&pC2,  g_C2);
    cudaGetSymbolAddress((void**)&pbc2, g_bc2);
    cudaGetSymbolAddress((void**)&psc,  g_sc);
    cudaGetSymbolAddress((void**)&psh,  g_sh);
    cudaGetSymbolAddress((void**)&pbs1, g_bnsum1);
    cudaGetSymbolAddress((void**)&pbq1, g_bnsq1);
    cudaGetSymbolAddress((void**)&pbs2, g_bnsum2);
    cudaGetSymbolAddress((void**)&pbq2, g_bnsq2);
    cudaGetSymbolAddress((void**)&pSrcs,   g_srcs);
    cudaGetSymbolAddress((void**)&pSrcnid, g_srcnid);

    __half* pAh = (__half*)pA;

    // ---- init (deg, bn stats) ----
    zero_init<<<NSB, 256>>>();

    // ---- CSR build (dst-sorted, permuted src + src-node-id + edge_attr) ----
    hist_kernel<<<(N_EDGES + 255) / 256, 256>>>(dst);
    scan1_kernel<<<NSB, 256>>>();
    scan2_kernel<<<1, 256>>>();
    scan3_kernel<<<NSB, 256>>>();
    fill_kernel<<<(N_EDGES + 255) / 256, 256>>>(src, dst, edge_attr, node_ids);

    // ---- combined edge matrices, then HT (replaces GEMM1 entirely) ----
    combine_kernel<<<1, 256>>>(c1_lin2_w, c1_lin2_b, c1_lin_w, c1_lin_b,
                               c2_lin2_w, c2_lin2_b, c2_lin_w, c2_lin_b);
    ht_kernel<<<N_IDS, 256>>>(emb, c1_lin_w);

    // ---- conv1 gather from L1-resident HT -> agg1 (bufB) + bn1 stats ----
    gather_kernel<false><<<1024, 256>>>(pHT, pSrcnid, pC1, pB, pbs1, pbq1);
    bnsc_kernel<<<1, 256>>>(bn1_w, bn1_b, pbs1, pbq1);

    // ---- layer 2: H2 = (half) leaky(bn1(agg1)) @ W2^T + bc2 ----
    dim3 gg((N_NODES + 127) / 128, DD / 128);
    gemm_tf32<<<gg, 256>>>(pB, psc, psh, c2_lin_w, pbc2, pAh, N_NODES, DD);

    // ---- conv2 gather (fp16 H2) -> agg2 (bufB) + bn2 stats ----
    gather_kernel<true><<<1024, 256>>>(pAh, pSrcs, pC2, pB, pbs2, pbq2);
    bnsc_kernel<<<1, 256>>>(bn2_w, bn2_b, pbs2, pbq2);

    // ---- fused attention: gate + softmax + weighted mean (block per graph) ----
    attn_kernel<<<N_GRAPHS, 256>>>(pB, batch, gate_w, gate_b, out);
}

// round 11
// speedup vs baseline: 1.3033x; 1.0391x over previous
#include <cuda_runtime.h>
#include <cuda_fp16.h>
#include <cstdint>

#define N_NODES  50000
#define N_EDGES  800000
#define N_GRAPHS 512
#define N_IDS    51
#define F_IN     128
#define DD       256
#define EPS      1e-5f
#define NEG_SLOPE 0.01f
#define NSB      196          // ceil(N_NODES/256) scan blocks

typedef unsigned long long ull;

// ---------------- scratch (device globals; no allocation allowed) ----------
__device__ float g_bufA[N_NODES * DD];   // H2 (as __half)
__device__ float g_bufB[N_NODES * DD];   // agg1 (as __half) -> agg2 (fp32)
__device__ float g_HT[N_IDS * DD];       // emb_table @ W1^T + bc1
__device__ float g_C1[4 * DD];
__device__ float g_bc1[DD];
__device__ float g_C2[4 * DD];
__device__ float g_bc2[DD];
__device__ float g_bnsum1[DD];
__device__ float g_bnsq1[DD];
__device__ float g_bnsum2[DD];
__device__ float g_bnsq2[DD];
__device__ float g_sc[DD];
__device__ float g_sh[DD];
__device__ float g_gate[N_NODES];
// CSR (dst-sorted, with permuted src, src-node-id and edge_attr)
__device__ int    g_deg[N_NODES];
__device__ int    g_start[N_NODES];
__device__ int    g_cursor[N_NODES];
__device__ int    g_srcs[N_EDGES];
__device__ int    g_srcnid[N_EDGES];
__device__ float4 g_eas[N_EDGES];
__device__ int    g_part[NSB];

// ---------------- helpers ---------------------------------------------------
__device__ __forceinline__ float leaky(float v) {
    return v >= 0.f ? v : NEG_SLOPE * v;
}
__device__ __forceinline__ ull dup2(float x) {
    ull r; unsigned u = __float_as_uint(x);
    asm("mov.b64 %0, {%1, %1};" : "=l"(r) : "r"(u));
    return r;
}
__device__ __forceinline__ void fma2(ull& d, ull a, ull b) {
    asm("fma.rn.f32x2 %0, %1, %2, %0;" : "+l"(d) : "l"(a), "l"(b));
}
__device__ __forceinline__ float2 up2(ull v) {
    float2 f; asm("mov.b64 {%0, %1}, %2;" : "=f"(f.x), "=f"(f.y) : "l"(v));
    return f;
}
__device__ __forceinline__ ull pack2(float lo, float hi) {
    ull r;
    asm("mov.b64 %0, {%1, %2};" : "=l"(r) : "f"(lo), "f"(hi));
    return r;
}
__device__ __forceinline__ unsigned tf32c(float x) {
    unsigned r;
    asm("cvt.rna.tf32.f32 %0, %1;" : "=r"(r) : "f"(x));
    return r;
}
__device__ __forceinline__ void mma_tf32(float d[4], const unsigned a[4],
                                         unsigned b0, unsigned b1) {
    asm volatile(
        "mma.sync.aligned.m16n8k8.row.col.f32.tf32.tf32.f32 "
        "{%0,%1,%2,%3}, {%4,%5,%6,%7}, {%8,%9}, {%0,%1,%2,%3};"
        : "+f"(d[0]), "+f"(d[1]), "+f"(d[2]), "+f"(d[3])
        : "r"(a[0]), "r"(a[1]), "r"(a[2]), "r"(a[3]), "r"(b0), "r"(b1));
}

// ---------------- zero / init kernels ---------------------------------------
__global__ void zero_init() {
    int i = blockIdx.x * blockDim.x + threadIdx.x;
    if (i < N_NODES) g_deg[i] = 0;
    if (i < DD) {
        g_bnsum1[i] = 0.f; g_bnsq1[i] = 0.f;
        g_bnsum2[i] = 0.f; g_bnsq2[i] = 0.f;
    }
}

// ---------------- CSR build --------------------------------------------------
__global__ void hist_kernel(const int* __restrict__ dst) {
    int e = blockIdx.x * blockDim.x + threadIdx.x;
    if (e < N_EDGES) atomicAdd(&g_deg[__ldg(dst + e)], 1);
}
__global__ void scan1_kernel() {
    __shared__ int sh[256];
    int i = blockIdx.x * 256 + threadIdx.x;
    int v = (i < N_NODES) ? g_deg[i] : 0;
    sh[threadIdx.x] = v; __syncthreads();
#pragma unroll
    for (int off = 1; off < 256; off <<= 1) {
        int tv = (threadIdx.x >= off) ? sh[threadIdx.x - off] : 0;
        __syncthreads();
        sh[threadIdx.x] += tv;
        __syncthreads();
    }
    if (i < N_NODES) g_start[i] = sh[threadIdx.x] - v;
    if (threadIdx.x == 255) g_part[blockIdx.x] = sh[255];
}
// merged scan2+scan3: every block rescans the 196 partials itself
__global__ void scan23_kernel() {
    __shared__ int sh[256];
    __shared__ int sexcl;
    int t = threadIdx.x;
    int v = (t < NSB) ? g_part[t] : 0;
    sh[t] = v; __syncthreads();
#pragma unroll
    for (int off = 1; off < 256; off <<= 1) {
        int tv = (t >= off) ? sh[t - off] : 0;
        __syncthreads();
        sh[t] += tv;
        __syncthreads();
    }
    if (t == 0) sexcl = (blockIdx.x == 0) ? 0 : sh[blockIdx.x - 1];
    __syncthreads();
    int i = blockIdx.x * 256 + t;
    if (i < N_NODES) {
        int s = g_start[i] + sexcl;
        g_start[i] = s;
        g_cursor[i] = s;
    }
}
__global__ void fill_kernel(const int* __restrict__ src,
                            const int* __restrict__ dst,
                            const float* __restrict__ ea,
                            const int* __restrict__ node_ids) {
    int e = blockIdx.x * blockDim.x + threadIdx.x;
    if (e < N_EDGES) {
        int d = __ldg(dst + e);
        int s = __ldg(src + e);
        int p = atomicAdd(&g_cursor[d], 1);
        g_srcs[p] = s;
        g_srcnid[p] = __ldg(node_ids + s);
        g_eas[p] = __ldg((const float4*)ea + e);
    }
}

// ---------------- combined edge matrices ------------------------------------
__global__ void combine_kernel(
    const float* __restrict__ l2w1, const float* __restrict__ l2b1,
    const float* __restrict__ lw1,  const float* __restrict__ lb1,
    const float* __restrict__ l2w2, const float* __restrict__ l2b2,
    const float* __restrict__ lw2,  const float* __restrict__ lb2)
{
    int d = threadIdx.x;   // 256 threads
    {
        float a0 = 0.f, a1 = 0.f, a2 = 0.f, a3 = 0.f, bb = 0.f;
        for (int f = 0; f < F_IN; f++) {
            float w = lw1[d * F_IN + f];
            float4 l2 = *(const float4*)(l2w1 + f * 4);
            a0 += l2.x * w; a1 += l2.y * w; a2 += l2.z * w; a3 += l2.w * w;
            bb += l2b1[f] * w;
        }
        g_C1[0 * DD + d] = a0; g_C1[1 * DD + d] = a1;
        g_C1[2 * DD + d] = a2; g_C1[3 * DD + d] = a3;
        g_bc1[d] = bb + lb1[d];
    }
    {
        float a0 = 0.f, a1 = 0.f, a2 = 0.f, a3 = 0.f, bb = 0.f;
        for (int f = 0; f < DD; f++) {
            float w = lw2[d * DD + f];
            float4 l2 = *(const float4*)(l2w2 + f * 4);
            a0 += l2.x * w; a1 += l2.y * w; a2 += l2.z * w; a3 += l2.w * w;
            bb += l2b2[f] * w;
        }
        g_C2[0 * DD + d] = a0; g_C2[1 * DD + d] = a1;
        g_C2[2 * DD + d] = a2; g_C2[3 * DD + d] = a3;
        g_bc2[d] = bb + lb2[d];
    }
}

// ---------------- HT = emb_table @ W1^T + bc1  (51 x 256, exact fp32) --------
__global__ void ht_kernel(const float* __restrict__ emb,
                          const float* __restrict__ lw1)
{
    __shared__ float ev[F_IN];
    int v = blockIdx.x;     // 0..50
    int d = threadIdx.x;    // 0..255
    if (d < F_IN) ev[d] = emb[v * F_IN + d];
    __syncthreads();
    const float* wr = lw1 + (size_t)d * F_IN;
    float s = 0.f;
#pragma unroll 8
    for (int f = 0; f < F_IN; f++) s += ev[f] * __ldg(wr + f);
    g_HT[v * DD + d] = s + g_bc1[d];
}

// ---------------- GEMM (tf32 tensor cores, fp16 A input, half output) --------
// out_h[m][n] = (half)(sum_k leaky(A_h[m][k]*sc+sh) * W[n][k] + bias[n])
__global__ void __launch_bounds__(256)
gemm_tf32(const __half* __restrict__ A,
          const float* __restrict__ sc, const float* __restrict__ sh,
          const float* __restrict__ W, const float* __restrict__ bias,
          __half* __restrict__ out, int M, int K)
{
    __shared__ unsigned As[128 * 36];
    __shared__ unsigned Bs[128 * 36];
    int t = threadIdx.x;
    int lane = t & 31;
    int wid = t >> 5;
    int wm = wid & 3, wn = wid >> 2;       // warp tile: rows wm*32, cols wn*64
    int bm = blockIdx.x * 128;
    int bn = blockIdx.y * 128;

    int lrow = t >> 1;
    int lkh = (t & 1) * 16;

    int m0 = bm + lrow;
    int mc = m0 < M ? m0 : (M - 1);
    const __half* Arow = A + (size_t)mc * K;
    const float* Wrow = W + (size_t)(bn + lrow) * K;

    float d[2][8][4];
#pragma unroll
    for (int i = 0; i < 2; i++)
#pragma unroll
        for (int j = 0; j < 8; j++)
#pragma unroll
            for (int c = 0; c < 4; c++) d[i][j][c] = 0.f;

    float4 va[4], vb[4];

    auto load_stage = [&](int kc) {
        uint4 u0 = __ldg((const uint4*)(Arow + kc + lkh));
        uint4 u1 = __ldg((const uint4*)(Arow + kc + lkh + 8));
        float2 f;
        f = __half22float2(*(__half2*)&u0.x); va[0].x = f.x; va[0].y = f.y;
        f = __half22float2(*(__half2*)&u0.y); va[0].z = f.x; va[0].w = f.y;
        f = __half22float2(*(__half2*)&u0.z); va[1].x = f.x; va[1].y = f.y;
        f = __half22float2(*(__half2*)&u0.w); va[1].z = f.x; va[1].w = f.y;
        f = __half22float2(*(__half2*)&u1.x); va[2].x = f.x; va[2].y = f.y;
        f = __half22float2(*(__half2*)&u1.y); va[2].z = f.x; va[2].w = f.y;
        f = __half22float2(*(__half2*)&u1.z); va[3].x = f.x; va[3].y = f.y;
        f = __half22float2(*(__half2*)&u1.w); va[3].z = f.x; va[3].w = f.y;
#pragma unroll
        for (int q = 0; q < 4; q++) {
            vb[q] = __ldg((const float4*)(Wrow + kc + lkh + q * 4));
            int ch = kc + lkh + q * 4;
            float4 s = __ldg((const float4*)(sc + ch));
            float4 h = __ldg((const float4*)(sh + ch));
            va[q].x = leaky(va[q].x * s.x + h.x);
            va[q].y = leaky(va[q].y * s.y + h.y);
            va[q].z = leaky(va[q].z * s.z + h.z);
            va[q].w = leaky(va[q].w * s.w + h.w);
        }
    };
    auto store_stage = [&]() {
        unsigned* ap = As + lrow * 36 + lkh;
        unsigned* bp = Bs + lrow * 36 + lkh;
#pragma unroll
        for (int q = 0; q < 4; q++) {
            *(uint4*)(ap + q * 4) = make_uint4(tf32c(va[q].x), tf32c(va[q].y),
                                               tf32c(va[q].z), tf32c(va[q].w));
            *(uint4*)(bp + q * 4) = make_uint4(tf32c(vb[q].x), tf32c(vb[q].y),
                                               tf32c(vb[q].z), tf32c(vb[q].w));
        }
    };

    load_stage(0);
    store_stage();
    __syncthreads();

    for (int kc = 0; kc < K; kc += 32) {
        bool more = (kc + 32) < K;
        if (more) load_stage(kc + 32);
#pragma unroll
        for (int ks = 0; ks < 4; ks++) {
            int k0 = ks * 8;
            unsigned a[2][4];
            int ra = (wm * 32 + (lane >> 2)) * 36 + k0 + (lane & 3);
#pragma unroll
            for (int i = 0; i < 2; i++) {
                int base = ra + i * 16 * 36;
                a[i][0] = As[base];
                a[i][1] = As[base + 8 * 36];
                a[i][2] = As[base + 4];
                a[i][3] = As[base + 8 * 36 + 4];
            }
            int rb = (wn * 64 + (lane >> 2)) * 36 + k0 + (lane & 3);
#pragma unroll
            for (int j = 0; j < 8; j++) {
                unsigned b0 = Bs[rb + j * 8 * 36];
                unsigned b1 = Bs[rb + j * 8 * 36 + 4];
                mma_tf32(d[0][j], a[0], b0, b1);
                mma_tf32(d[1][j], a[1], b0, b1);
            }
        }
        if (more) {
            __syncthreads();
            store_stage();
            __syncthreads();
        }
    }

    // epilogue: +bias, convert to half
    float2 bsv[8];
#pragma unroll
    for (int j = 0; j < 8; j++) {
        int col = bn + wn * 64 + j * 8 + (lane & 3) * 2;
        bsv[j] = __ldg((const float2*)(bias + col));
    }
#pragma unroll
    for (int i = 0; i < 2; i++) {
        int rg0 = bm + wm * 32 + i * 16 + (lane >> 2);
        int rg1 = rg0 + 8;
#pragma unroll
        for (int j = 0; j < 8; j++) {
            int col = bn + wn * 64 + j * 8 + (lane & 3) * 2;
            if (rg0 < M)
                *(__half2*)(out + (size_t)rg0 * DD + col) =
                    __floats2half2_rn(d[i][j][0] + bsv[j].x, d[i][j][1] + bsv[j].y);
            if (rg1 < M)
                *(__half2*)(out + (size_t)rg1 * DD + col) =
                    __floats2half2_rn(d[i][j][2] + bsv[j].x, d[i][j][3] + bsv[j].y);
        }
    }
}

// ---------------- per-edge packed accumulate (bias pre-folded into H) --------
__device__ __forceinline__ void edge_accum(
    ull acc[4], float4 at, const ull hh[4],
    const ull c0p[4], const ull c1p[4], const ull c2p[4], const ull c3p[4])
{
    const ull ABS2 = 0x7fffffff7fffffffull;
    const ull D505 = 0x3f0147ae3f0147aeull;  // dup2(0.505f)
    const ull D495 = 0x3efd70a43efd70a4ull;  // dup2(0.495f)
    ull ax = dup2(at.x), ay = dup2(at.y), az = dup2(at.z), aw = dup2(at.w);
#pragma unroll
    for (int i = 0; i < 4; i++) {
        ull m = hh[i];
        fma2(m, ax, c0p[i]); fma2(m, ay, c1p[i]);
        fma2(m, az, c2p[i]); fma2(m, aw, c3p[i]);
        ull ab = m & ABS2;
        fma2(acc[i], D505, m);
        fma2(acc[i], D495, ab);
    }
}

// ---------------- CSR gather (templated fp16/fp32 in & out) ------------------
template <bool HALF_IN, bool HALF_OUT>
__global__ void gather_kernel(const void* __restrict__ Hv,
                              const int* __restrict__ srcs,
                              const float* __restrict__ C,
                              void* __restrict__ aggv,
                              float* __restrict__ bnsum,
                              float* __restrict__ bnsq)
{
    __shared__ float ssum[DD];
    __shared__ float ssq[DD];
    int t = threadIdx.x;
    ssum[t] = 0.f; ssq[t] = 0.f;
    __syncthreads();

    int lane = t & 31;
    int wid = (blockIdx.x * blockDim.x + t) >> 5;
    int nw = (gridDim.x * blockDim.x) >> 5;
    int d0 = lane * 8;

    ull c0p[4], c1p[4], c2p[4], c3p[4];
    {
        ulonglong2 u;
        u = *(const ulonglong2*)(C + 0 * DD + d0);     c0p[0] = u.x; c0p[1] = u.y;
        u = *(const ulonglong2*)(C + 0 * DD + d0 + 4); c0p[2] = u.x; c0p[3] = u.y;
        u = *(const ulonglong2*)(C + 1 * DD + d0);     c1p[0] = u.x; c1p[1] = u.y;
        u = *(const ulonglong2*)(C + 1 * DD + d0 + 4); c1p[2] = u.x; c1p[3] = u.y;
        u = *(const ulonglong2*)(C + 2 * DD + d0);     c2p[0] = u.x; c2p[1] = u.y;
        u = *(const ulonglong2*)(C + 2 * DD + d0 + 4); c2p[2] = u.x; c2p[3] = u.y;
        u = *(const ulonglong2*)(C + 3 * DD + d0);     c3p[0] = u.x; c3p[1] = u.y;
        u = *(const ulonglong2*)(C + 3 * DD + d0 + 4); c3p[2] = u.x; c3p[3] = u.y;
    }

    const float* Hf = (const float*)Hv;
    const __half* Hh = (const __half*)Hv;

    auto load_h = [&](int row, ull hh[4]) {
        if (HALF_IN) {
            uint4 u = __ldg((const uint4*)(Hh + (size_t)row * DD + d0));
            float2 f0 = __half22float2(*(__half2*)&u.x);
            float2 f1 = __half22float2(*(__half2*)&u.y);
            float2 f2 = __half22float2(*(__half2*)&u.z);
            float2 f3 = __half22float2(*(__half2*)&u.w);
            hh[0] = pack2(f0.x, f0.y); hh[1] = pack2(f1.x, f1.y);
            hh[2] = pack2(f2.x, f2.y); hh[3] = pack2(f3.x, f3.y);
        } else {
            const ulonglong2* hp = (const ulonglong2*)(Hf + (size_t)row * DD + d0);
            ulonglong2 p = hp[0], q = hp[1];
            hh[0] = p.x; hh[1] = p.y; hh[2] = q.x; hh[3] = q.y;
        }
    };

    float sA[8], qA[8];
#pragma unroll
    for (int i = 0; i < 8; i++) { sA[i] = 0.f; qA[i] = 0.f; }

    for (int n = wid; n < N_NODES; n += nw) {
        int s0 = __ldg(g_start + n);
        int dg = __ldg(g_deg + n);
        ull acc[4] = {0ull, 0ull, 0ull, 0ull};

        int j = 0;
        for (; j + 3 < dg; j += 4) {
            int sa = __ldg(srcs + s0 + j);
            int sb = __ldg(srcs + s0 + j + 1);
            int sc2 = __ldg(srcs + s0 + j + 2);
            int sd = __ldg(srcs + s0 + j + 3);
            ull ha[4], hb[4], hc[4], hd[4];
            load_h(sa, ha); load_h(sb, hb); load_h(sc2, hc); load_h(sd, hd);
            float4 at0 = __ldg((const float4*)g_eas + s0 + j);
            float4 at1 = __ldg((const float4*)g_eas + s0 + j + 1);
            float4 at2 = __ldg((const float4*)g_eas + s0 + j + 2);
            float4 at3 = __ldg((const float4*)g_eas + s0 + j + 3);
            edge_accum(acc, at0, ha, c0p, c1p, c2p, c3p);
            edge_accum(acc, at1, hb, c0p, c1p, c2p, c3p);
            edge_accum(acc, at2, hc, c0p, c1p, c2p, c3p);
            edge_accum(acc, at3, hd, c0p, c1p, c2p, c3p);
        }
        for (; j < dg; j++) {
            int sa = __ldg(srcs + s0 + j);
            float4 at0 = __ldg((const float4*)g_eas + s0 + j);
            ull ha[4];
            load_h(sa, ha);
            edge_accum(acc, at0, ha, c0p, c1p, c2p, c3p);
        }

        float2 f0 = up2(acc[0]), f1 = up2(acc[1]);
        float2 f2 = up2(acc[2]), f3 = up2(acc[3]);
        if (HALF_OUT) {
            __half2 h0 = __floats2half2_rn(f0.x, f0.y);
            __half2 h1 = __floats2half2_rn(f1.x, f1.y);
            __half2 h2 = __floats2half2_rn(f2.x, f2.y);
            __half2 h3 = __floats2half2_rn(f3.x, f3.y);
            uint4 u;
            u.x = *(unsigned*)&h0; u.y = *(unsigned*)&h1;
            u.z = *(unsigned*)&h2; u.w = *(unsigned*)&h3;
            *(uint4*)((__half*)aggv + (size_t)n * DD + d0) = u;
        } else {
            ulonglong2* op = (ulonglong2*)((float*)aggv + (size_t)n * DD + d0);
            op[0] = make_ulonglong2(acc[0], acc[1]);
            op[1] = make_ulonglong2(acc[2], acc[3]);
        }

        sA[0] += f0.x; qA[0] += f0.x * f0.x;  sA[1] += f0.y; qA[1] += f0.y * f0.y;
        sA[2] += f1.x; qA[2] += f1.x * f1.x;  sA[3] += f1.y; qA[3] += f1.y * f1.y;
        sA[4] += f2.x; qA[4] += f2.x * f2.x;  sA[5] += f2.y; qA[5] += f2.y * f2.y;
        sA[6] += f3.x; qA[6] += f3.x * f3.x;  sA[7] += f3.y; qA[7] += f3.y * f3.y;
    }
#pragma unroll
    for (int i = 0; i < 8; i++) {
        atomicAdd(&ssum[d0 + i], sA[i]);
        atomicAdd(&ssq[d0 + i], qA[i]);
    }
    __syncthreads();
    atomicAdd(&bnsum[t], ssum[t]);
    atomicAdd(&bnsq[t], ssq[t]);
}

// ---------------- BN scale/shift from stats ----------------------------------
__global__ void bnsc_kernel(const float* __restrict__ w, const float* __restrict__ b,
                            const float* __restrict__ bnsum, const float* __restrict__ bnsq)
{
    int c = threadIdx.x;
    const float invN = 1.f / (float)N_NODES;
    float m = bnsum[c] * invN;
    float var = bnsq[c] * invN - m * m;
    float s = w[c] * rsqrtf(var + EPS);
    g_sc[c] = s;
    g_sh[c] = b[c] - m * s;
}

// ---------------- fused attention: gate + softmax + weighted mean -------------
__device__ __forceinline__ int lbound(const int* a, int v) {
    int lo = 0, hi = N_NODES;
    while (lo < hi) {
        int m = (lo + hi) >> 1;
        if (__ldg(a + m) < v) lo = m + 1; else hi = m;
    }
    return lo;
}

__global__ void attn_kernel(const float* __restrict__ X,
                            const int* __restrict__ batch,
                            const float* __restrict__ gw,
                            const float* __restrict__ gb,
                            float* __restrict__ out)
{
    __shared__ int sr0, sr1;
    __shared__ float smax[8];
    __shared__ float sgmax;
    int g = blockIdx.x;
    int t = threadIdx.x;
    int lane = t & 31, w = t >> 5;

    if (t == 0) { sr0 = lbound(batch, g); sr1 = lbound(batch, g + 1); }
    __syncthreads();
    int r0 = sr0, r1 = sr1;

    // pass 1: gates + block max (warp per node)
    float wmax = -3.4e38f;
    {
        int d0 = lane * 8;
        float gwv[8], scv[8], shv[8];
#pragma unroll
        for (int i = 0; i < 8; i++) {
            gwv[i] = __ldg(gw + d0 + i);
            scv[i] = g_sc[d0 + i];
            shv[i] = g_sh[d0 + i];
        }
        for (int n = r0 + w; n < r1; n += 8) {
            const float4* xp = (const float4*)(X + (size_t)n * DD + d0);
            float4 h0 = __ldg(xp), h1 = __ldg(xp + 1);
            float v[8] = {h0.x, h0.y, h0.z, h0.w, h1.x, h1.y, h1.z, h1.w};
            float gsum = 0.f;
#pragma unroll
            for (int i = 0; i < 8; i++)
                gsum += leaky(v[i] * scv[i] + shv[i]) * gwv[i];
#pragma unroll
            for (int off = 16; off; off >>= 1)
                gsum += __shfl_xor_sync(0xffffffffu, gsum, off);
            if (lane == 0) {
                gsum += __ldg(gb);
                g_gate[n] = gsum;
                wmax = fmaxf(wmax, gsum);
            }
        }
    }
    if (lane == 0) smax[w] = wmax;
    __syncthreads();
    if (t == 0) {
        float m = smax[0];
#pragma unroll
        for (int i = 1; i < 8; i++) m = fmaxf(m, smax[i]);
        sgmax = m;
    }
    __syncthreads();
    float gmax = sgmax;

    // pass 2: per-channel weighted accumulation (thread = channel)
    float sc_c = g_sc[t], sh_c = g_sh[t];
    float acc = 0.f, denom = 0.f;
    for (int n = r0; n < r1; n++) {
        float e = __expf(g_gate[n] - gmax);
        denom += e;
        float x = __ldg(X + (size_t)n * DD + t);
        acc += e * leaky(x * sc_c + sh_c);
    }
    out[(size_t)g * DD + t] = denom > 0.f ? acc / denom : 0.f;
}

// ---------------- launch -----------------------------------------------------
extern "C" void kernel_launch(void* const* d_in, const int* in_sizes, int n_in,
                              void* d_out, int out_size)
{
    const int*   node_ids  = (const int*)d_in[0];
    const int*   edge_index= (const int*)d_in[1];
    const float* edge_attr = (const float*)d_in[2];
    const int*   batch     = (const int*)d_in[3];
    const float* emb       = (const float*)d_in[4];
    const float* c1_lin2_w = (const float*)d_in[5];
    const float* c1_lin2_b = (const float*)d_in[6];
    const float* c1_lin_w  = (const float*)d_in[7];
    const float* c1_lin_b  = (const float*)d_in[8];
    const float* bn1_w     = (const float*)d_in[9];
    const float* bn1_b     = (const float*)d_in[10];
    const float* c2_lin2_w = (const float*)d_in[11];
    const float* c2_lin2_b = (const float*)d_in[12];
    const float* c2_lin_w  = (const float*)d_in[13];
    const float* c2_lin_b  = (const float*)d_in[14];
    const float* bn2_w     = (const float*)d_in[15];
    const float* bn2_b     = (const float*)d_in[16];
    const float* gate_w    = (const float*)d_in[17];
    const float* gate_b    = (const float*)d_in[18];
    float* out = (float*)d_out;

    const int* src = edge_index;
    const int* dst = edge_index + N_EDGES;

    float *pA, *pB, *pHT, *pC1, *pC2, *pbc2, *psc, *psh;
    float *pbs1, *pbq1, *pbs2, *pbq2;
    int *pSrcs, *pSrcnid;
    cudaGetSymbolAddress((void**)&pA,   g_bufA);
    cudaGetSymbolAddress((void**)&pB,   g_bufB);
    cudaGetSymbolAddress((void**)&pHT,  g_HT);
    cudaGetSymbolAddress((void**)&pC1,  g_C1);
    cudaGetSymbolAddress((void**)&pC2,  g_C2);
    cudaGetSymbolAddress((void**)&pbc2, g_bc2);
    cudaGetSymbolAddress((void**)&psc,  g_sc);
    cudaGetSymbolAddress((void**)&psh,  g_sh);
    cudaGetSymbolAddress((void**)&pbs1, g_bnsum1);
    cudaGetSymbolAddress((void**)&pbq1, g_bnsq1);
    cudaGetSymbolAddress((void**)&pbs2, g_bnsum2);
    cudaGetSymbolAddress((void**)&pbq2, g_bnsq2);
    cudaGetSymbolAddress((void**)&pSrcs,   g_srcs);
    cudaGetSymbolAddress((void**)&pSrcnid, g_srcnid);

    __half* pAh = (__half*)pA;
    __half* pBh = (__half*)pB;

    // ---- init (deg, bn stats) ----
    zero_init<<<NSB, 256>>>();

    // ---- CSR build (dst-sorted, permuted src + src-node-id + edge_attr) ----
    hist_kernel<<<(N_EDGES + 255) / 256, 256>>>(dst);
    scan1_kernel<<<NSB, 256>>>();
    scan23_kernel<<<NSB, 256>>>();
    fill_kernel<<<(N_EDGES + 255) / 256, 256>>>(src, dst, edge_attr, node_ids);

    // ---- combined edge matrices, then HT (replaces GEMM1 entirely) ----
    combine_kernel<<<1, 256>>>(c1_lin2_w, c1_lin2_b, c1_lin_w, c1_lin_b,
                               c2_lin2_w, c2_lin2_b, c2_lin_w, c2_lin_b);
    ht_kernel<<<N_IDS, 256>>>(emb, c1_lin_w);

    // ---- conv1 gather (fp32 HT in, fp16 agg1 out) + bn1 stats ----
    gather_kernel<false, true><<<1024, 256>>>(pHT, pSrcnid, pC1, pBh, pbs1, pbq1);
    bnsc_kernel<<<1, 256>>>(bn1_w, bn1_b, pbs1, pbq1);

    // ---- layer 2: H2 = (half) leaky(bn1(agg1_h)) @ W2^T + bc2 ----
    dim3 gg((N_NODES + 127) / 128, DD / 128);
    gemm_tf32<<<gg, 256>>>(pBh, psc, psh, c2_lin_w, pbc2, pAh, N_NODES, DD);

    // ---- conv2 gather (fp16 H2 in, fp32 agg2 out) + bn2 stats ----
    gather_kernel<true, false><<<1024, 256>>>(pAh, pSrcs, pC2, pB, pbs2, pbq2);
    bnsc_kernel<<<1, 256>>>(bn2_w, bn2_b, pbs2, pbq2);

    // ---- fused attention: gate + softmax + weighted mean (block per graph) ----
    attn_kernel<<<N_GRAPHS, 256>>>(pB, batch, gate_w, gate_b, out);
}

// round 12
// speedup vs baseline: 1.3623x; 1.0453x over previous
#include <cuda_runtime.h>
#include <cuda_fp16.h>
#include <cstdint>

#define N_NODES  50000
#define N_EDGES  800000
#define N_GRAPHS 512
#define N_IDS    51
#define F_IN     128
#define DD       256
#define EPS      1e-5f
#define NEG_SLOPE 0.01f
#define NSB      196          // ceil(N_NODES/256) scan blocks

typedef unsigned long long ull;

// ---------------- scratch (device globals; no allocation allowed) ----------
__device__ float g_bufA[N_NODES * DD];   // H2 (as __half)
__device__ float g_bufB[N_NODES * DD];   // agg1 (as __half) -> agg2 (fp32)
__device__ float g_HT[N_IDS * DD];       // emb_table @ W1^T + bc1
__device__ float g_C1[4 * DD];
__device__ float g_bc1[DD];
__device__ float g_C2[4 * DD];
__device__ float g_bc2[DD];
__device__ float g_bnsum1[DD];
__device__ float g_bnsq1[DD];
__device__ float g_bnsum2[DD];
__device__ float g_bnsq2[DD];
__device__ float g_sc[DD];
__device__ float g_sh[DD];
__device__ float g_gate[N_NODES];
__device__ int   g_wq1, g_wq2;           // work-stealing counters
// CSR (dst-sorted, with permuted (src, srcnid) pairs and edge_attr)
__device__ int    g_deg[N_NODES];
__device__ int    g_start[N_NODES];
__device__ int    g_cursor[N_NODES];
__device__ int2   g_sp[N_EDGES];         // {src, srcnid}
__device__ float4 g_eas[N_EDGES];
__device__ int    g_part[NSB];

// ---------------- helpers ---------------------------------------------------
__device__ __forceinline__ float leaky(float v) {
    return v >= 0.f ? v : NEG_SLOPE * v;
}
__device__ __forceinline__ ull dup2(float x) {
    ull r; unsigned u = __float_as_uint(x);
    asm("mov.b64 %0, {%1, %1};" : "=l"(r) : "r"(u));
    return r;
}
__device__ __forceinline__ void fma2(ull& d, ull a, ull b) {
    asm("fma.rn.f32x2 %0, %1, %2, %0;" : "+l"(d) : "l"(a), "l"(b));
}
__device__ __forceinline__ float2 up2(ull v) {
    float2 f; asm("mov.b64 {%0, %1}, %2;" : "=f"(f.x), "=f"(f.y) : "l"(v));
    return f;
}
__device__ __forceinline__ ull pack2(float lo, float hi) {
    ull r;
    asm("mov.b64 %0, {%1, %2};" : "=l"(r) : "f"(lo), "f"(hi));
    return r;
}
__device__ __forceinline__ unsigned tf32c(float x) {
    unsigned r;
    asm("cvt.rna.tf32.f32 %0, %1;" : "=r"(r) : "f"(x));
    return r;
}
__device__ __forceinline__ void mma_tf32(float d[4], const unsigned a[4],
                                         unsigned b0, unsigned b1) {
    asm volatile(
        "mma.sync.aligned.m16n8k8.row.col.f32.tf32.tf32.f32 "
        "{%0,%1,%2,%3}, {%4,%5,%6,%7}, {%8,%9}, {%0,%1,%2,%3};"
        : "+f"(d[0]), "+f"(d[1]), "+f"(d[2]), "+f"(d[3])
        : "r"(a[0]), "r"(a[1]), "r"(a[2]), "r"(a[3]), "r"(b0), "r"(b1));
}

// ---------------- zero / init kernels ---------------------------------------
__global__ void zero_init() {
    int i = blockIdx.x * blockDim.x + threadIdx.x;
    if (i < N_NODES) g_deg[i] = 0;
    if (i < DD) {
        g_bnsum1[i] = 0.f; g_bnsq1[i] = 0.f;
        g_bnsum2[i] = 0.f; g_bnsq2[i] = 0.f;
    }
    if (i == 0) { g_wq1 = 0; g_wq2 = 0; }
}

// ---------------- CSR build --------------------------------------------------
__global__ void hist_kernel(const int* __restrict__ dst) {
    int e = blockIdx.x * blockDim.x + threadIdx.x;
    if (e < N_EDGES) atomicAdd(&g_deg[__ldg(dst + e)], 1);
}
__global__ void scan1_kernel() {
    __shared__ int sh[256];
    int i = blockIdx.x * 256 + threadIdx.x;
    int v = (i < N_NODES) ? g_deg[i] : 0;
    sh[threadIdx.x] = v; __syncthreads();
#pragma unroll
    for (int off = 1; off < 256; off <<= 1) {
        int tv = (threadIdx.x >= off) ? sh[threadIdx.x - off] : 0;
        __syncthreads();
        sh[threadIdx.x] += tv;
        __syncthreads();
    }
    if (i < N_NODES) g_start[i] = sh[threadIdx.x] - v;
    if (threadIdx.x == 255) g_part[blockIdx.x] = sh[255];
}
// merged scan2+scan3: every block rescans the 196 partials itself
__global__ void scan23_kernel() {
    __shared__ int sh[256];
    __shared__ int sexcl;
    int t = threadIdx.x;
    int v = (t < NSB) ? g_part[t] : 0;
    sh[t] = v; __syncthreads();
#pragma unroll
    for (int off = 1; off < 256; off <<= 1) {
        int tv = (t >= off) ? sh[t - off] : 0;
        __syncthreads();
        sh[t] += tv;
        __syncthreads();
    }
    if (t == 0) sexcl = (blockIdx.x == 0) ? 0 : sh[blockIdx.x - 1];
    __syncthreads();
    int i = blockIdx.x * 256 + t;
    if (i < N_NODES) {
        int s = g_start[i] + sexcl;
        g_start[i] = s;
        g_cursor[i] = s;
    }
}
__global__ void fill_kernel(const int* __restrict__ src,
                            const int* __restrict__ dst,
                            const float* __restrict__ ea,
                            const int* __restrict__ node_ids) {
    int e = blockIdx.x * blockDim.x + threadIdx.x;
    if (e < N_EDGES) {
        int d = __ldg(dst + e);
        int s = __ldg(src + e);
        int p = atomicAdd(&g_cursor[d], 1);
        g_sp[p] = make_int2(s, __ldg(node_ids + s));
        g_eas[p] = __ldg((const float4*)ea + e);
    }
}

// ---------------- combined edge matrices ------------------------------------
__global__ void combine_kernel(
    const float* __restrict__ l2w1, const float* __restrict__ l2b1,
    const float* __restrict__ lw1,  const float* __restrict__ lb1,
    const float* __restrict__ l2w2, const float* __restrict__ l2b2,
    const float* __restrict__ lw2,  const float* __restrict__ lb2)
{
    int d = threadIdx.x;   // 256 threads
    {
        float a0 = 0.f, a1 = 0.f, a2 = 0.f, a3 = 0.f, bb = 0.f;
        for (int f = 0; f < F_IN; f++) {
            float w = lw1[d * F_IN + f];
            float4 l2 = *(const float4*)(l2w1 + f * 4);
            a0 += l2.x * w; a1 += l2.y * w; a2 += l2.z * w; a3 += l2.w * w;
            bb += l2b1[f] * w;
        }
        g_C1[0 * DD + d] = a0; g_C1[1 * DD + d] = a1;
        g_C1[2 * DD + d] = a2; g_C1[3 * DD + d] = a3;
        g_bc1[d] = bb + lb1[d];
    }
    {
        float a0 = 0.f, a1 = 0.f, a2 = 0.f, a3 = 0.f, bb = 0.f;
        for (int f = 0; f < DD; f++) {
            float w = lw2[d * DD + f];
            float4 l2 = *(const float4*)(l2w2 + f * 4);
            a0 += l2.x * w; a1 += l2.y * w; a2 += l2.z * w; a3 += l2.w * w;
            bb += l2b2[f] * w;
        }
        g_C2[0 * DD + d] = a0; g_C2[1 * DD + d] = a1;
        g_C2[2 * DD + d] = a2; g_C2[3 * DD + d] = a3;
        g_bc2[d] = bb + lb2[d];
    }
}

// ---------------- HT = emb_table @ W1^T + bc1  (51 x 256, exact fp32) --------
__global__ void ht_kernel(const float* __restrict__ emb,
                          const float* __restrict__ lw1)
{
    __shared__ float ev[F_IN];
    int v = blockIdx.x;     // 0..50
    int d = threadIdx.x;    // 0..255
    if (d < F_IN) ev[d] = emb[v * F_IN + d];
    __syncthreads();
    const float* wr = lw1 + (size_t)d * F_IN;
    float s = 0.f;
#pragma unroll 8
    for (int f = 0; f < F_IN; f++) s += ev[f] * __ldg(wr + f);
    g_HT[v * DD + d] = s + g_bc1[d];
}

// ---------------- GEMM (tf32 tensor cores, fp16 A input, half output) --------
__global__ void __launch_bounds__(256)
gemm_tf32(const __half* __restrict__ A,
          const float* __restrict__ sc, const float* __restrict__ sh,
          const float* __restrict__ W, const float* __restrict__ bias,
          __half* __restrict__ out, int M, int K)
{
    __shared__ unsigned As[128 * 36];
    __shared__ unsigned Bs[128 * 36];
    int t = threadIdx.x;
    int lane = t & 31;
    int wid = t >> 5;
    int wm = wid & 3, wn = wid >> 2;       // warp tile: rows wm*32, cols wn*64
    int bm = blockIdx.x * 128;
    int bn = blockIdx.y * 128;

    int lrow = t >> 1;
    int lkh = (t & 1) * 16;

    int m0 = bm + lrow;
    int mc = m0 < M ? m0 : (M - 1);
    const __half* Arow = A + (size_t)mc * K;
    const float* Wrow = W + (size_t)(bn + lrow) * K;

    float d[2][8][4];
#pragma unroll
    for (int i = 0; i < 2; i++)
#pragma unroll
        for (int j = 0; j < 8; j++)
#pragma unroll
            for (int c = 0; c < 4; c++) d[i][j][c] = 0.f;

    float4 va[4], vb[4];

    auto load_stage = [&](int kc) {
        uint4 u0 = __ldg((const uint4*)(Arow + kc + lkh));
        uint4 u1 = __ldg((const uint4*)(Arow + kc + lkh + 8));
        float2 f;
        f = __half22float2(*(__half2*)&u0.x); va[0].x = f.x; va[0].y = f.y;
        f = __half22float2(*(__half2*)&u0.y); va[0].z = f.x; va[0].w = f.y;
        f = __half22float2(*(__half2*)&u0.z); va[1].x = f.x; va[1].y = f.y;
        f = __half22float2(*(__half2*)&u0.w); va[1].z = f.x; va[1].w = f.y;
        f = __half22float2(*(__half2*)&u1.x); va[2].x = f.x; va[2].y = f.y;
        f = __half22float2(*(__half2*)&u1.y); va[2].z = f.x; va[2].w = f.y;
        f = __half22float2(*(__half2*)&u1.z); va[3].x = f.x; va[3].y = f.y;
        f = __half22float2(*(__half2*)&u1.w); va[3].z = f.x; va[3].w = f.y;
#pragma unroll
        for (int q = 0; q < 4; q++) {
            vb[q] = __ldg((const float4*)(Wrow + kc + lkh + q * 4));
            int ch = kc + lkh + q * 4;
            float4 s = __ldg((const float4*)(sc + ch));
            float4 h = __ldg((const float4*)(sh + ch));
            va[q].x = leaky(va[q].x * s.x + h.x);
            va[q].y = leaky(va[q].y * s.y + h.y);
            va[q].z = leaky(va[q].z * s.z + h.z);
            va[q].w = leaky(va[q].w * s.w + h.w);
        }
    };
    auto store_stage = [&]() {
        unsigned* ap = As + lrow * 36 + lkh;
        unsigned* bp = Bs + lrow * 36 + lkh;
#pragma unroll
        for (int q = 0; q < 4; q++) {
            *(uint4*)(ap + q * 4) = make_uint4(tf32c(va[q].x), tf32c(va[q].y),
                                               tf32c(va[q].z), tf32c(va[q].w));
            *(uint4*)(bp + q * 4) = make_uint4(tf32c(vb[q].x), tf32c(vb[q].y),
                                               tf32c(vb[q].z), tf32c(vb[q].w));
        }
    };

    load_stage(0);
    store_stage();
    __syncthreads();

    for (int kc = 0; kc < K; kc += 32) {
        bool more = (kc + 32) < K;
        if (more) load_stage(kc + 32);
#pragma unroll
        for (int ks = 0; ks < 4; ks++) {
            int k0 = ks * 8;
            unsigned a[2][4];
            int ra = (wm * 32 + (lane >> 2)) * 36 + k0 + (lane & 3);
#pragma unroll
            for (int i = 0; i < 2; i++) {
                int base = ra + i * 16 * 36;
                a[i][0] = As[base];
                a[i][1] = As[base + 8 * 36];
                a[i][2] = As[base + 4];
                a[i][3] = As[base + 8 * 36 + 4];
            }
            int rb = (wn * 64 + (lane >> 2)) * 36 + k0 + (lane & 3);
#pragma unroll
            for (int j = 0; j < 8; j++) {
                unsigned b0 = Bs[rb + j * 8 * 36];
                unsigned b1 = Bs[rb + j * 8 * 36 + 4];
                mma_tf32(d[0][j], a[0], b0, b1);
                mma_tf32(d[1][j], a[1], b0, b1);
            }
        }
        if (more) {
            __syncthreads();
            store_stage();
            __syncthreads();
        }
    }

    // epilogue: +bias, convert to half
    float2 bsv[8];
#pragma unroll
    for (int j = 0; j < 8; j++) {
        int col = bn + wn * 64 + j * 8 + (lane & 3) * 2;
        bsv[j] = __ldg((const float2*)(bias + col));
    }
#pragma unroll
    for (int i = 0; i < 2; i++) {
        int rg0 = bm + wm * 32 + i * 16 + (lane >> 2);
        int rg1 = rg0 + 8;
#pragma unroll
        for (int j = 0; j < 8; j++) {
            int col = bn + wn * 64 + j * 8 + (lane & 3) * 2;
            if (rg0 < M)
                *(__half2*)(out + (size_t)rg0 * DD + col) =
                    __floats2half2_rn(d[i][j][0] + bsv[j].x, d[i][j][1] + bsv[j].y);
            if (rg1 < M)
                *(__half2*)(out + (size_t)rg1 * DD + col) =
                    __floats2half2_rn(d[i][j][2] + bsv[j].x, d[i][j][3] + bsv[j].y);
        }
    }
}

// ---------------- per-edge packed accumulate (bias pre-folded into H) --------
__device__ __forceinline__ void edge_accum(
    ull acc[4], float4 at, const ull hh[4],
    const ull c0p[4], const ull c1p[4], const ull c2p[4], const ull c3p[4])
{
    const ull ABS2 = 0x7fffffff7fffffffull;
    const ull D505 = 0x3f0147ae3f0147aeull;  // dup2(0.505f)
    const ull D495 = 0x3efd70a43efd70a4ull;  // dup2(0.495f)
    ull ax = dup2(at.x), ay = dup2(at.y), az = dup2(at.z), aw = dup2(at.w);
#pragma unroll
    for (int i = 0; i < 4; i++) {
        ull m = hh[i];
        fma2(m, ax, c0p[i]); fma2(m, ay, c1p[i]);
        fma2(m, az, c2p[i]); fma2(m, aw, c3p[i]);
        ull ab = m & ABS2;
        fma2(acc[i], D505, m);
        fma2(acc[i], D495, ab);
    }
}

// ---------------- CSR gather (work stealing; fp16/fp32 in & out) -------------
template <bool HALF_IN, bool HALF_OUT, bool USE_NID>
__global__ void gather_kernel(const void* __restrict__ Hv,
                              const float* __restrict__ C,
                              void* __restrict__ aggv,
                              float* __restrict__ bnsum,
                              float* __restrict__ bnsq,
                              int* __restrict__ wq)
{
    __shared__ float ssum[DD];
    __shared__ float ssq[DD];
    int t = threadIdx.x;
    ssum[t] = 0.f; ssq[t] = 0.f;
    __syncthreads();

    int lane = t & 31;
    int d0 = lane * 8;

    ull c0p[4], c1p[4], c2p[4], c3p[4];
    {
        ulonglong2 u;
        u = *(const ulonglong2*)(C + 0 * DD + d0);     c0p[0] = u.x; c0p[1] = u.y;
        u = *(const ulonglong2*)(C + 0 * DD + d0 + 4); c0p[2] = u.x; c0p[3] = u.y;
        u = *(const ulonglong2*)(C + 1 * DD + d0);     c1p[0] = u.x; c1p[1] = u.y;
        u = *(const ulonglong2*)(C + 1 * DD + d0 + 4); c1p[2] = u.x; c1p[3] = u.y;
        u = *(const ulonglong2*)(C + 2 * DD + d0);     c2p[0] = u.x; c2p[1] = u.y;
        u = *(const ulonglong2*)(C + 2 * DD + d0 + 4); c2p[2] = u.x; c2p[3] = u.y;
        u = *(const ulonglong2*)(C + 3 * DD + d0);     c3p[0] = u.x; c3p[1] = u.y;
        u = *(const ulonglong2*)(C + 3 * DD + d0 + 4); c3p[2] = u.x; c3p[3] = u.y;
    }

    const float* Hf = (const float*)Hv;
    const __half* Hh = (const __half*)Hv;

    auto load_h = [&](int row, ull hh[4]) {
        if (HALF_IN) {
            uint4 u = __ldg((const uint4*)(Hh + (size_t)row * DD + d0));
            float2 f0 = __half22float2(*(__half2*)&u.x);
            float2 f1 = __half22float2(*(__half2*)&u.y);
            float2 f2 = __half22float2(*(__half2*)&u.z);
            float2 f3 = __half22float2(*(__half2*)&u.w);
            hh[0] = pack2(f0.x, f0.y); hh[1] = pack2(f1.x, f1.y);
            hh[2] = pack2(f2.x, f2.y); hh[3] = pack2(f3.x, f3.y);
        } else {
            const ulonglong2* hp = (const ulonglong2*)(Hf + (size_t)row * DD + d0);
            ulonglong2 p = hp[0], q = hp[1];
            hh[0] = p.x; hh[1] = p.y; hh[2] = q.x; hh[3] = q.y;
        }
    };

    float sA[8], qA[8];
#pragma unroll
    for (int i = 0; i < 8; i++) { sA[i] = 0.f; qA[i] = 0.f; }

    // work-stealing loop: pop next node while processing current
    int n = 0;
    if (lane == 0) n = atomicAdd(wq, 1);
    n = __shfl_sync(0xffffffffu, n, 0);
    while (n < N_NODES) {
        int nn = 0;
        if (lane == 0) nn = atomicAdd(wq, 1);
        nn = __shfl_sync(0xffffffffu, nn, 0);

        int s0 = __ldg(g_start + n);
        int dg = __ldg(g_deg + n);
        ull acc[4] = {0ull, 0ull, 0ull, 0ull};

        int j = 0;
        for (; j + 3 < dg; j += 4) {
            int2 p0 = __ldg(g_sp + s0 + j);
            int2 p1 = __ldg(g_sp + s0 + j + 1);
            int2 p2 = __ldg(g_sp + s0 + j + 2);
            int2 p3 = __ldg(g_sp + s0 + j + 3);
            int sa = USE_NID ? p0.y : p0.x;
            int sb = USE_NID ? p1.y : p1.x;
            int sc2 = USE_NID ? p2.y : p2.x;
            int sd = USE_NID ? p3.y : p3.x;
            ull ha[4], hb[4], hc[4], hd[4];
            load_h(sa, ha); load_h(sb, hb); load_h(sc2, hc); load_h(sd, hd);
            float4 at0 = __ldg((const float4*)g_eas + s0 + j);
            float4 at1 = __ldg((const float4*)g_eas + s0 + j + 1);
            float4 at2 = __ldg((const float4*)g_eas + s0 + j + 2);
            float4 at3 = __ldg((const float4*)g_eas + s0 + j + 3);
            edge_accum(acc, at0, ha, c0p, c1p, c2p, c3p);
            edge_accum(acc, at1, hb, c0p, c1p, c2p, c3p);
            edge_accum(acc, at2, hc, c0p, c1p, c2p, c3p);
            edge_accum(acc, at3, hd, c0p, c1p, c2p, c3p);
        }
        for (; j < dg; j++) {
            int2 p0 = __ldg(g_sp + s0 + j);
            int sa = USE_NID ? p0.y : p0.x;
            float4 at0 = __ldg((const float4*)g_eas + s0 + j);
            ull ha[4];
            load_h(sa, ha);
            edge_accum(acc, at0, ha, c0p, c1p, c2p, c3p);
        }

        float2 f0 = up2(acc[0]), f1 = up2(acc[1]);
        float2 f2 = up2(acc[2]), f3 = up2(acc[3]);
        if (HALF_OUT) {
            __half2 h0 = __floats2half2_rn(f0.x, f0.y);
            __half2 h1 = __floats2half2_rn(f1.x, f1.y);
            __half2 h2 = __floats2half2_rn(f2.x, f2.y);
            __half2 h3 = __floats2half2_rn(f3.x, f3.y);
            uint4 u;
            u.x = *(unsigned*)&h0; u.y = *(unsigned*)&h1;
            u.z = *(unsigned*)&h2; u.w = *(unsigned*)&h3;
            *(uint4*)((__half*)aggv + (size_t)n * DD + d0) = u;
        } else {
            ulonglong2* op = (ulonglong2*)((float*)aggv + (size_t)n * DD + d0);
            op[0] = make_ulonglong2(acc[0], acc[1]);
            op[1] = make_ulonglong2(acc[2], acc[3]);
        }

        sA[0] += f0.x; qA[0] += f0.x * f0.x;  sA[1] += f0.y; qA[1] += f0.y * f0.y;
        sA[2] += f1.x; qA[2] += f1.x * f1.x;  sA[3] += f1.y; qA[3] += f1.y * f1.y;
        sA[4] += f2.x; qA[4] += f2.x * f2.x;  sA[5] += f2.y; qA[5] += f2.y * f2.y;
        sA[6] += f3.x; qA[6] += f3.x * f3.x;  sA[7] += f3.y; qA[7] += f3.y * f3.y;

        n = nn;
    }
#pragma unroll
    for (int i = 0; i < 8; i++) {
        atomicAdd(&ssum[d0 + i], sA[i]);
        atomicAdd(&ssq[d0 + i], qA[i]);
    }
    __syncthreads();
    atomicAdd(&bnsum[t], ssum[t]);
    atomicAdd(&bnsq[t], ssq[t]);
}

// ---------------- BN scale/shift from stats ----------------------------------
__global__ void bnsc_kernel(const float* __restrict__ w, const float* __restrict__ b,
                            const float* __restrict__ bnsum, const float* __restrict__ bnsq)
{
    int c = threadIdx.x;
    const float invN = 1.f / (float)N_NODES;
    float m = bnsum[c] * invN;
    float var = bnsq[c] * invN - m * m;
    float s = w[c] * rsqrtf(var + EPS);
    g_sc[c] = s;
    g_sh[c] = b[c] - m * s;
}

// ---------------- fused attention: gate + softmax + weighted mean -------------
__device__ __forceinline__ int lbound(const int* a, int v) {
    int lo = 0, hi = N_NODES;
    while (lo < hi) {
        int m = (lo + hi) >> 1;
        if (__ldg(a + m) < v) lo = m + 1; else hi = m;
    }
    return lo;
}

__global__ void attn_kernel(const float* __restrict__ X,
                            const int* __restrict__ batch,
                            const float* __restrict__ gw,
                            const float* __restrict__ gb,
                            float* __restrict__ out)
{
    __shared__ int sr0, sr1;
    __shared__ float smax[8];
    __shared__ float sgmax;
    __shared__ float sE[256];
    int g = blockIdx.x;
    int t = threadIdx.x;
    int lane = t & 31, w = t >> 5;

    if (t == 0) { sr0 = lbound(batch, g); sr1 = lbound(batch, g + 1); }
    __syncthreads();
    int r0 = sr0, r1 = sr1;

    // pass 1: gates + block max (warp per node)
    float wmax = -3.4e38f;
    {
        int d0 = lane * 8;
        float gwv[8], scv[8], shv[8];
#pragma unroll
        for (int i = 0; i < 8; i++) {
            gwv[i] = __ldg(gw + d0 + i);
            scv[i] = g_sc[d0 + i];
            shv[i] = g_sh[d0 + i];
        }
        for (int n = r0 + w; n < r1; n += 8) {
            const float4* xp = (const float4*)(X + (size_t)n * DD + d0);
            float4 h0 = __ldg(xp), h1 = __ldg(xp + 1);
            float v[8] = {h0.x, h0.y, h0.z, h0.w, h1.x, h1.y, h1.z, h1.w};
            float gsum = 0.f;
#pragma unroll
            for (int i = 0; i < 8; i++)
                gsum += leaky(v[i] * scv[i] + shv[i]) * gwv[i];
#pragma unroll
            for (int off = 16; off; off >>= 1)
                gsum += __shfl_xor_sync(0xffffffffu, gsum, off);
            if (lane == 0) {
                gsum += __ldg(gb);
                g_gate[n] = gsum;
                wmax = fmaxf(wmax, gsum);
            }
        }
    }
    if (lane == 0) smax[w] = wmax;
    __syncthreads();
    if (t == 0) {
        float m = smax[0];
#pragma unroll
        for (int i = 1; i < 8; i++) m = fmaxf(m, smax[i]);
        sgmax = m;
    }
    __syncthreads();
    float gmax = sgmax;

    // pass 2: chunked — e computed ONCE per node into smem, reused by all channels
    float sc_c = g_sc[t], sh_c = g_sh[t];
    float acc = 0.f, denom = 0.f;
    for (int c0 = r0; c0 < r1; c0 += 256) {
        int cnt = min(256, r1 - c0);
        __syncthreads();
        if (t < cnt) sE[t] = __expf(g_gate[c0 + t] - gmax);
        __syncthreads();
        for (int i = 0; i < cnt; i++) {
            float e = sE[i];
            denom += e;
            float x = __ldg(X + (size_t)(c0 + i) * DD + t);
            acc += e * leaky(x * sc_c + sh_c);
        }
    }
    out[(size_t)g * DD + t] = denom > 0.f ? acc / denom : 0.f;
}

// ---------------- launch -----------------------------------------------------
extern "C" void kernel_launch(void* const* d_in, const int* in_sizes, int n_in,
                              void* d_out, int out_size)
{
    const int*   node_ids  = (const int*)d_in[0];
    const int*   edge_index= (const int*)d_in[1];
    const float* edge_attr = (const float*)d_in[2];
    const int*   batch     = (const int*)d_in[3];
    const float* emb       = (const float*)d_in[4];
    const float* c1_lin2_w = (const float*)d_in[5];
    const float* c1_lin2_b = (const float*)d_in[6];
    const float* c1_lin_w  = (const float*)d_in[7];
    const float* c1_lin_b  = (const float*)d_in[8];
    const float* bn1_w     = (const float*)d_in[9];
    const float* bn1_b     = (const float*)d_in[10];
    const float* c2_lin2_w = (const float*)d_in[11];
    const float* c2_lin2_b = (const float*)d_in[12];
    const float* c2_lin_w  = (const float*)d_in[13];
    const float* c2_lin_b  = (const float*)d_in[14];
    const float* bn2_w     = (const float*)d_in[15];
    const float* bn2_b     = (const float*)d_in[16];
    const float* gate_w    = (const float*)d_in[17];
    const float* gate_b    = (const float*)d_in[18];
    float* out = (float*)d_out;

    const int* src = edge_index;
    const int* dst = edge_index + N_EDGES;

    float *pA, *pB, *pHT, *pC1, *pC2, *pbc2, *psc, *psh;
    float *pbs1, *pbq1, *pbs2, *pbq2;
    int *pWq1, *pWq2;
    cudaGetSymbolAddress((void**)&pA,   g_bufA);
    cudaGetSymbolAddress((void**)&pB,   g_bufB);
    cudaGetSymbolAddress((void**)&pHT,  g_HT);
    cudaGetSymbolAddress((void**)&pC1,  g_C1);
    cudaGetSymbolAddress((void**)&pC2,  g_C2);
    cudaGetSymbolAddress((void**)&pbc2, g_bc2);
    cudaGetSymbolAddress((void**)&psc,  g_sc);
    cudaGetSymbolAddress((void**)&psh,  g_sh);
    cudaGetSymbolAddress((void**)&pbs1, g_bnsum1);
    cudaGetSymbolAddress((void**)&pbq1, g_bnsq1);
    cudaGetSymbolAddress((void**)&pbs2, g_bnsum2);
    cudaGetSymbolAddress((void**)&pbq2, g_bnsq2);
    cudaGetSymbolAddress((void**)&pWq1, g_wq1);
    cudaGetSymbolAddress((void**)&pWq2, g_wq2);

    __half* pAh = (__half*)pA;
    __half* pBh = (__half*)pB;

    // ---- init (deg, bn stats, work queues) ----
    zero_init<<<NSB, 256>>>();

    // ---- CSR build (dst-sorted, permuted (src,srcnid) + edge_attr) ----
    hist_kernel<<<(N_EDGES + 255) / 256, 256>>>(dst);
    scan1_kernel<<<NSB, 256>>>();
    scan23_kernel<<<NSB, 256>>>();
    fill_kernel<<<(N_EDGES + 255) / 256, 256>>>(src, dst, edge_attr, node_ids);

    // ---- combined edge matrices, then HT (replaces GEMM1 entirely) ----
    combine_kernel<<<1, 256>>>(c1_lin2_w, c1_lin2_b, c1_lin_w, c1_lin_b,
                               c2_lin2_w, c2_lin2_b, c2_lin_w, c2_lin_b);
    ht_kernel<<<N_IDS, 256>>>(emb, c1_lin_w);

    // ---- conv1 gather (fp32 HT in, fp16 agg1 out) + bn1 stats ----
    gather_kernel<false, true, true><<<1024, 256>>>(pHT, pC1, pBh, pbs1, pbq1, pWq1);
    bnsc_kernel<<<1, 256>>>(bn1_w, bn1_b, pbs1, pbq1);

    // ---- layer 2: H2 = (half) leaky(bn1(agg1_h)) @ W2^T + bc2 ----
    dim3 gg((N_NODES + 127) / 128, DD / 128);
    gemm_tf32<<<gg, 256>>>(pBh, psc, psh, c2_lin_w, pbc2, pAh, N_NODES, DD);

    // ---- conv2 gather (fp16 H2 in, fp32 agg2 out) + bn2 stats ----
    gather_kernel<true, false, false><<<1024, 256>>>(pAh, pC2, pB, pbs2, pbq2, pWq2);
    bnsc_kernel<<<1, 256>>>(bn2_w, bn2_b, pbs2, pbq2);

    // ---- fused attention: gate + softmax + weighted mean (block per graph) ----
    attn_kernel<<<N_GRAPHS, 256>>>(pB, batch, gate_w, gate_b, out);
}

// round 13
// speedup vs baseline: 1.4480x; 1.0629x over previous
#include <cuda_runtime.h>
#include <cuda_fp16.h>
#include <cstdint>

#define N_NODES  50000
#define N_EDGES  800000
#define N_GRAPHS 512
#define N_IDS    51
#define F_IN     128
#define DD       256
#define EPS      1e-5f
#define NEG_SLOPE 0.01f
#define NSB      196          // ceil(N_NODES/256) scan blocks

typedef unsigned long long ull;

// ---------------- scratch (device globals; no allocation allowed) ----------
__device__ float g_bufA[N_NODES * DD];   // H2 (as __half)
__device__ float g_bufB[N_NODES * DD];   // agg1 (as __half) -> agg2 (fp32)
__device__ float g_HT[N_IDS * DD];       // emb_table @ W1^T + bc1
__device__ __half g_W2h[DD * DD];        // c2_lin_w as fp16
__device__ float g_C1[4 * DD];
__device__ float g_bc1[DD];
__device__ float g_C2[4 * DD];
__device__ float g_bc2[DD];
__device__ float g_bnsum1[DD];
__device__ float g_bnsq1[DD];
__device__ float g_bnsum2[DD];
__device__ float g_bnsq2[DD];
__device__ float g_sc[DD];
__device__ float g_sh[DD];
__device__ float g_gate[N_NODES];
__device__ int   g_wq1, g_wq2;           // work-stealing counters
// CSR (dst-sorted, with permuted (src, srcnid) pairs and edge_attr)
__device__ int    g_deg[N_NODES];
__device__ int    g_start[N_NODES];
__device__ int    g_cursor[N_NODES];
__device__ int2   g_sp[N_EDGES];         // {src, srcnid}
__device__ float4 g_eas[N_EDGES];
__device__ int    g_part[NSB];

// ---------------- helpers ---------------------------------------------------
__device__ __forceinline__ float leaky(float v) {
    return v >= 0.f ? v : NEG_SLOPE * v;
}
__device__ __forceinline__ ull dup2(float x) {
    ull r; unsigned u = __float_as_uint(x);
    asm("mov.b64 %0, {%1, %1};" : "=l"(r) : "r"(u));
    return r;
}
__device__ __forceinline__ void fma2(ull& d, ull a, ull b) {
    asm("fma.rn.f32x2 %0, %1, %2, %0;" : "+l"(d) : "l"(a), "l"(b));
}
__device__ __forceinline__ float2 up2(ull v) {
    float2 f; asm("mov.b64 {%0, %1}, %2;" : "=f"(f.x), "=f"(f.y) : "l"(v));
    return f;
}
__device__ __forceinline__ ull pack2(float lo, float hi) {
    ull r;
    asm("mov.b64 %0, {%1, %2};" : "=l"(r) : "f"(lo), "f"(hi));
    return r;
}
// m16n8k16 fp16 mma, fp32 accumulate
__device__ __forceinline__ void mma_f16(float d[4], const unsigned a[4],
                                        unsigned b0, unsigned b1) {
    asm volatile(
        "mma.sync.aligned.m16n8k16.row.col.f32.f16.f16.f32 "
        "{%0,%1,%2,%3}, {%4,%5,%6,%7}, {%8,%9}, {%0,%1,%2,%3};"
        : "+f"(d[0]), "+f"(d[1]), "+f"(d[2]), "+f"(d[3])
        : "r"(a[0]), "r"(a[1]), "r"(a[2]), "r"(a[3]), "r"(b0), "r"(b1));
}

// ---------------- zero / init kernels ---------------------------------------
__global__ void zero_init() {
    int i = blockIdx.x * blockDim.x + threadIdx.x;
    if (i < N_NODES) g_deg[i] = 0;
    if (i < DD) {
        g_bnsum1[i] = 0.f; g_bnsq1[i] = 0.f;
        g_bnsum2[i] = 0.f; g_bnsq2[i] = 0.f;
    }
    if (i == 0) { g_wq1 = 0; g_wq2 = 0; }
}

// ---------------- CSR build --------------------------------------------------
__global__ void hist_kernel(const int* __restrict__ dst) {
    int e = blockIdx.x * blockDim.x + threadIdx.x;
    if (e < N_EDGES) atomicAdd(&g_deg[__ldg(dst + e)], 1);
}
__global__ void scan1_kernel() {
    __shared__ int sh[256];
    int i = blockIdx.x * 256 + threadIdx.x;
    int v = (i < N_NODES) ? g_deg[i] : 0;
    sh[threadIdx.x] = v; __syncthreads();
#pragma unroll
    for (int off = 1; off < 256; off <<= 1) {
        int tv = (threadIdx.x >= off) ? sh[threadIdx.x - off] : 0;
        __syncthreads();
        sh[threadIdx.x] += tv;
        __syncthreads();
    }
    if (i < N_NODES) g_start[i] = sh[threadIdx.x] - v;
    if (threadIdx.x == 255) g_part[blockIdx.x] = sh[255];
}
__global__ void scan23_kernel() {
    __shared__ int sh[256];
    __shared__ int sexcl;
    int t = threadIdx.x;
    int v = (t < NSB) ? g_part[t] : 0;
    sh[t] = v; __syncthreads();
#pragma unroll
    for (int off = 1; off < 256; off <<= 1) {
        int tv = (t >= off) ? sh[t - off] : 0;
        __syncthreads();
        sh[t] += tv;
        __syncthreads();
    }
    if (t == 0) sexcl = (blockIdx.x == 0) ? 0 : sh[blockIdx.x - 1];
    __syncthreads();
    int i = blockIdx.x * 256 + t;
    if (i < N_NODES) {
        int s = g_start[i] + sexcl;
        g_start[i] = s;
        g_cursor[i] = s;
    }
}
__global__ void fill_kernel(const int* __restrict__ src,
                            const int* __restrict__ dst,
                            const float* __restrict__ ea,
                            const int* __restrict__ node_ids) {
    int e = blockIdx.x * blockDim.x + threadIdx.x;
    if (e < N_EDGES) {
        int d = __ldg(dst + e);
        int s = __ldg(src + e);
        int p = atomicAdd(&g_cursor[d], 1);
        g_sp[p] = make_int2(s, __ldg(node_ids + s));
        g_eas[p] = __ldg((const float4*)ea + e);
    }
}

// ---------------- combined edge matrices + W2 -> fp16 ------------------------
__global__ void combine_kernel(
    const float* __restrict__ l2w1, const float* __restrict__ l2b1,
    const float* __restrict__ lw1,  const float* __restrict__ lb1,
    const float* __restrict__ l2w2, const float* __restrict__ l2b2,
    const float* __restrict__ lw2,  const float* __restrict__ lb2)
{
    int d = threadIdx.x;   // 256 threads
    {
        float a0 = 0.f, a1 = 0.f, a2 = 0.f, a3 = 0.f, bb = 0.f;
        for (int f = 0; f < F_IN; f++) {
            float w = lw1[d * F_IN + f];
            float4 l2 = *(const float4*)(l2w1 + f * 4);
            a0 += l2.x * w; a1 += l2.y * w; a2 += l2.z * w; a3 += l2.w * w;
            bb += l2b1[f] * w;
        }
        g_C1[0 * DD + d] = a0; g_C1[1 * DD + d] = a1;
        g_C1[2 * DD + d] = a2; g_C1[3 * DD + d] = a3;
        g_bc1[d] = bb + lb1[d];
    }
    {
        float a0 = 0.f, a1 = 0.f, a2 = 0.f, a3 = 0.f, bb = 0.f;
        for (int f = 0; f < DD; f++) {
            float w = lw2[d * DD + f];
            float4 l2 = *(const float4*)(l2w2 + f * 4);
            a0 += l2.x * w; a1 += l2.y * w; a2 += l2.z * w; a3 += l2.w * w;
            bb += l2b2[f] * w;
        }
        g_C2[0 * DD + d] = a0; g_C2[1 * DD + d] = a1;
        g_C2[2 * DD + d] = a2; g_C2[3 * DD + d] = a3;
        g_bc2[d] = bb + lb2[d];
    }
}
__global__ void w2h_kernel(const float* __restrict__ lw2) {
    int i = blockIdx.x * blockDim.x + threadIdx.x;   // over 65536/2 pairs
    float2 v = __ldg((const float2*)lw2 + i);
    *((__half2*)g_W2h + i) = __floats2half2_rn(v.x, v.y);
}

// ---------------- HT = emb_table @ W1^T + bc1  (51 x 256, exact fp32) --------
__global__ void ht_kernel(const float* __restrict__ emb,
                          const float* __restrict__ lw1)
{
    __shared__ float ev[F_IN];
    int v = blockIdx.x;     // 0..50
    int d = threadIdx.x;    // 0..255
    if (d < F_IN) ev[d] = emb[v * F_IN + d];
    __syncthreads();
    const float* wr = lw1 + (size_t)d * F_IN;
    float s = 0.f;
#pragma unroll 8
    for (int f = 0; f < F_IN; f++) s += ev[f] * __ldg(wr + f);
    g_HT[v * DD + d] = s + g_bc1[d];
}

// ---------------- GEMM (fp16 HMMA m16n8k16, fp32 accum, half in/out) ---------
// out_h[m][n] = (half)(sum_k leaky(A_h[m][k]*sc+sh) * W_h[n][k] + bias[n])
// Smem layout: rows of 16 k-pairs (__half2 as unsigned) + 4 pad -> stride 20.
__global__ void __launch_bounds__(256)
gemm_f16(const __half* __restrict__ A,
         const float* __restrict__ sc, const float* __restrict__ sh,
         const __half* __restrict__ Wh, const float* __restrict__ bias,
         __half* __restrict__ out, int M, int K)
{
    __shared__ unsigned As[128 * 20];   // 10 KB
    __shared__ unsigned Bs[128 * 20];   // 10 KB
    int t = threadIdx.x;
    int lane = t & 31;
    int wid = t >> 5;
    int wm = wid & 3, wn = wid >> 2;     // warp tile: rows wm*32, cols wn*64
    int bm = blockIdx.x * 128;
    int bn = blockIdx.y * 128;

    int lrow = t >> 1;                   // 0..127
    int lh = t & 1;                      // k-half: pairs [8h, 8h+8)

    int gid = lane >> 2;                 // 0..7
    int c = lane & 3;                    // 0..3

    int m0 = bm + lrow;
    int mc = m0 < M ? m0 : (M - 1);
    const __half* Arow = A + (size_t)mc * K;
    const __half* Wrow = Wh + (size_t)(bn + lrow) * K;

    float d[2][8][4];
#pragma unroll
    for (int i = 0; i < 2; i++)
#pragma unroll
        for (int j = 0; j < 8; j++)
#pragma unroll
            for (int q = 0; q < 4; q++) d[i][j][q] = 0.f;

    uint4 ra0, ra1, rb0, rb1;            // staged 16 halves each (A, B)

    auto load_stage = [&](int kc) {
        int kb = kc + lh * 16;
        ra0 = __ldg((const uint4*)(Arow + kb));
        ra1 = __ldg((const uint4*)(Arow + kb + 8));
        rb0 = __ldg((const uint4*)(Wrow + kb));
        rb1 = __ldg((const uint4*)(Wrow + kb + 8));
        // transform A: halves -> float -> bn+leaky -> halves (pairs preserved)
        unsigned* au = &ra0.x;
#pragma unroll
        for (int q = 0; q < 8; q++) {
            unsigned* p = (q < 4) ? (&ra0.x + q) : (&ra1.x + (q - 4));
            float2 f = __half22float2(*(__half2*)p);
            int ch = kb + q * 2;
            float2 s = __ldg((const float2*)(sc + ch));
            float2 hh = __ldg((const float2*)(sh + ch));
            f.x = leaky(f.x * s.x + hh.x);
            f.y = leaky(f.y * s.y + hh.y);
            __half2 r = __floats2half2_rn(f.x, f.y);
            *p = *(unsigned*)&r;
        }
        (void)au;
    };
    auto store_stage = [&]() {
        unsigned* ap = As + lrow * 20 + lh * 8;
        unsigned* bp = Bs + lrow * 20 + lh * 8;
        *(uint4*)(ap)     = ra0;
        *(uint4*)(ap + 4) = ra1;
        *(uint4*)(bp)     = rb0;
        *(uint4*)(bp + 4) = rb1;
    };

    load_stage(0);
    store_stage();
    __syncthreads();

    for (int kc = 0; kc < K; kc += 32) {
        bool more = (kc + 32) < K;
        if (more) load_stage(kc + 32);
#pragma unroll
        for (int ks = 0; ks < 2; ks++) {
            int kp = ks * 8 + c;
            unsigned a[2][4];
#pragma unroll
            for (int i = 0; i < 2; i++) {
                int r = (wm * 32 + i * 16 + gid) * 20;
                a[i][0] = As[r + kp];
                a[i][1] = As[r + 8 * 20 + kp];
                a[i][2] = As[r + kp + 4];
                a[i][3] = As[r + 8 * 20 + kp + 4];
            }
#pragma unroll
            for (int j = 0; j < 8; j++) {
                int rn = (wn * 64 + j * 8 + gid) * 20;
                unsigned b0 = Bs[rn + kp];
                unsigned b1 = Bs[rn + kp + 4];
                mma_f16(d[0][j], a[0], b0, b1);
                mma_f16(d[1][j], a[1], b0, b1);
            }
        }
        if (more) {
            __syncthreads();
            store_stage();
            __syncthreads();
        }
    }

    // epilogue: +bias, convert to half
    float2 bsv[8];
#pragma unroll
    for (int j = 0; j < 8; j++) {
        int col = bn + wn * 64 + j * 8 + c * 2;
        bsv[j] = __ldg((const float2*)(bias + col));
    }
#pragma unroll
    for (int i = 0; i < 2; i++) {
        int rg0 = bm + wm * 32 + i * 16 + gid;
        int rg1 = rg0 + 8;
#pragma unroll
        for (int j = 0; j < 8; j++) {
            int col = bn + wn * 64 + j * 8 + c * 2;
            if (rg0 < M)
                *(__half2*)(out + (size_t)rg0 * DD + col) =
                    __floats2half2_rn(d[i][j][0] + bsv[j].x, d[i][j][1] + bsv[j].y);
            if (rg1 < M)
                *(__half2*)(out + (size_t)rg1 * DD + col) =
                    __floats2half2_rn(d[i][j][2] + bsv[j].x, d[i][j][3] + bsv[j].y);
        }
    }
}

// ---------------- per-edge packed accumulate (bias pre-folded into H) --------
__device__ __forceinline__ void edge_accum(
    ull acc[4], float4 at, const ull hh[4],
    const ull c0p[4], const ull c1p[4], const ull c2p[4], const ull c3p[4])
{
    const ull ABS2 = 0x7fffffff7fffffffull;
    const ull D505 = 0x3f0147ae3f0147aeull;  // dup2(0.505f)
    const ull D495 = 0x3efd70a43efd70a4ull;  // dup2(0.495f)
    ull ax = dup2(at.x), ay = dup2(at.y), az = dup2(at.z), aw = dup2(at.w);
#pragma unroll
    for (int i = 0; i < 4; i++) {
        ull m = hh[i];
        fma2(m, ax, c0p[i]); fma2(m, ay, c1p[i]);
        fma2(m, az, c2p[i]); fma2(m, aw, c3p[i]);
        ull ab = m & ABS2;
        fma2(acc[i], D505, m);
        fma2(acc[i], D495, ab);
    }
}

// ---------------- CSR gather (work stealing; fp16/fp32 in & out) -------------
template <bool HALF_IN, bool HALF_OUT, bool USE_NID>
__global__ void gather_kernel(const void* __restrict__ Hv,
                              const float* __restrict__ C,
                              void* __restrict__ aggv,
                              float* __restrict__ bnsum,
                              float* __restrict__ bnsq,
                              int* __restrict__ wq)
{
    __shared__ float ssum[DD];
    __shared__ float ssq[DD];
    int t = threadIdx.x;
    ssum[t] = 0.f; ssq[t] = 0.f;
    __syncthreads();

    int lane = t & 31;
    int d0 = lane * 8;

    ull c0p[4], c1p[4], c2p[4], c3p[4];
    {
        ulonglong2 u;
        u = *(const ulonglong2*)(C + 0 * DD + d0);     c0p[0] = u.x; c0p[1] = u.y;
        u = *(const ulonglong2*)(C + 0 * DD + d0 + 4); c0p[2] = u.x; c0p[3] = u.y;
        u = *(const ulonglong2*)(C + 1 * DD + d0);     c1p[0] = u.x; c1p[1] = u.y;
        u = *(const ulonglong2*)(C + 1 * DD + d0 + 4); c1p[2] = u.x; c1p[3] = u.y;
        u = *(const ulonglong2*)(C + 2 * DD + d0);     c2p[0] = u.x; c2p[1] = u.y;
        u = *(const ulonglong2*)(C + 2 * DD + d0 + 4); c2p[2] = u.x; c2p[3] = u.y;
        u = *(const ulonglong2*)(C + 3 * DD + d0);     c3p[0] = u.x; c3p[1] = u.y;
        u = *(const ulonglong2*)(C + 3 * DD + d0 + 4); c3p[2] = u.x; c3p[3] = u.y;
    }

    const float* Hf = (const float*)Hv;
    const __half* Hh = (const __half*)Hv;

    auto load_h = [&](int row, ull hh[4]) {
        if (HALF_IN) {
            uint4 u = __ldg((const uint4*)(Hh + (size_t)row * DD + d0));
            float2 f0 = __half22float2(*(__half2*)&u.x);
            float2 f1 = __half22float2(*(__half2*)&u.y);
            float2 f2 = __half22float2(*(__half2*)&u.z);
            float2 f3 = __half22float2(*(__half2*)&u.w);
            hh[0] = pack2(f0.x, f0.y); hh[1] = pack2(f1.x, f1.y);
            hh[2] = pack2(f2.x, f2.y); hh[3] = pack2(f3.x, f3.y);
        } else {
            const ulonglong2* hp = (const ulonglong2*)(Hf + (size_t)row * DD + d0);
            ulonglong2 p = hp[0], q = hp[1];
            hh[0] = p.x; hh[1] = p.y; hh[2] = q.x; hh[3] = q.y;
        }
    };

    float sA[8], qA[8];
#pragma unroll
    for (int i = 0; i < 8; i++) { sA[i] = 0.f; qA[i] = 0.f; }

    int n = 0;
    if (lane == 0) n = atomicAdd(wq, 1);
    n = __shfl_sync(0xffffffffu, n, 0);
    while (n < N_NODES) {
        int nn = 0;
        if (lane == 0) nn = atomicAdd(wq, 1);
        nn = __shfl_sync(0xffffffffu, nn, 0);

        int s0 = __ldg(g_start + n);
        int dg = __ldg(g_deg + n);
        ull acc[4] = {0ull, 0ull, 0ull, 0ull};

        int j = 0;
        for (; j + 3 < dg; j += 4) {
            int2 p0 = __ldg(g_sp + s0 + j);
            int2 p1 = __ldg(g_sp + s0 + j + 1);
            int2 p2 = __ldg(g_sp + s0 + j + 2);
            int2 p3 = __ldg(g_sp + s0 + j + 3);
            int sa = USE_NID ? p0.y : p0.x;
            int sb = USE_NID ? p1.y : p1.x;
            int sc2 = USE_NID ? p2.y : p2.x;
            int sd = USE_NID ? p3.y : p3.x;
            ull ha[4], hb[4], hc[4], hd[4];
            load_h(sa, ha); load_h(sb, hb); load_h(sc2, hc); load_h(sd, hd);
            float4 at0 = __ldg((const float4*)g_eas + s0 + j);
            float4 at1 = __ldg((const float4*)g_eas + s0 + j + 1);
            float4 at2 = __ldg((const float4*)g_eas + s0 + j + 2);
            float4 at3 = __ldg((const float4*)g_eas + s0 + j + 3);
            edge_accum(acc, at0, ha, c0p, c1p, c2p, c3p);
            edge_accum(acc, at1, hb, c0p, c1p, c2p, c3p);
            edge_accum(acc, at2, hc, c0p, c1p, c2p, c3p);
            edge_accum(acc, at3, hd, c0p, c1p, c2p, c3p);
        }
        for (; j < dg; j++) {
            int2 p0 = __ldg(g_sp + s0 + j);
            int sa = USE_NID ? p0.y : p0.x;
            float4 at0 = __ldg((const float4*)g_eas + s0 + j);
            ull ha[4];
            load_h(sa, ha);
            edge_accum(acc, at0, ha, c0p, c1p, c2p, c3p);
        }

        float2 f0 = up2(acc[0]), f1 = up2(acc[1]);
        float2 f2 = up2(acc[2]), f3 = up2(acc[3]);
        if (HALF_OUT) {
            __half2 h0 = __floats2half2_rn(f0.x, f0.y);
            __half2 h1 = __floats2half2_rn(f1.x, f1.y);
            __half2 h2 = __floats2half2_rn(f2.x, f2.y);
            __half2 h3 = __floats2half2_rn(f3.x, f3.y);
            uint4 u;
            u.x = *(unsigned*)&h0; u.y = *(unsigned*)&h1;
            u.z = *(unsigned*)&h2; u.w = *(unsigned*)&h3;
            *(uint4*)((__half*)aggv + (size_t)n * DD + d0) = u;
        } else {
            ulonglong2* op = (ulonglong2*)((float*)aggv + (size_t)n * DD + d0);
            op[0] = make_ulonglong2(acc[0], acc[1]);
            op[1] = make_ulonglong2(acc[2], acc[3]);
        }

        sA[0] += f0.x; qA[0] += f0.x * f0.x;  sA[1] += f0.y; qA[1] += f0.y * f0.y;
        sA[2] += f1.x; qA[2] += f1.x * f1.x;  sA[3] += f1.y; qA[3] += f1.y * f1.y;
        sA[4] += f2.x; qA[4] += f2.x * f2.x;  sA[5] += f2.y; qA[5] += f2.y * f2.y;
        sA[6] += f3.x; qA[6] += f3.x * f3.x;  sA[7] += f3.y; qA[7] += f3.y * f3.y;

        n = nn;
    }
#pragma unroll
    for (int i = 0; i < 8; i++) {
        atomicAdd(&ssum[d0 + i], sA[i]);
        atomicAdd(&ssq[d0 + i], qA[i]);
    }
    __syncthreads();
    atomicAdd(&bnsum[t], ssum[t]);
    atomicAdd(&bnsq[t], ssq[t]);
}

// ---------------- BN scale/shift from stats ----------------------------------
__global__ void bnsc_kernel(const float* __restrict__ w, const float* __restrict__ b,
                            const float* __restrict__ bnsum, const float* __restrict__ bnsq)
{
    int c = threadIdx.x;
    const float invN = 1.f / (float)N_NODES;
    float m = bnsum[c] * invN;
    float var = bnsq[c] * invN - m * m;
    float s = w[c] * rsqrtf(var + EPS);
    g_sc[c] = s;
    g_sh[c] = b[c] - m * s;
}

// ---------------- fused attention: gate + softmax + weighted mean -------------
__device__ __forceinline__ int lbound(const int* a, int v) {
    int lo = 0, hi = N_NODES;
    while (lo < hi) {
        int m = (lo + hi) >> 1;
        if (__ldg(a + m) < v) lo = m + 1; else hi = m;
    }
    return lo;
}

__global__ void attn_kernel(const float* __restrict__ X,
                            const int* __restrict__ batch,
                            const float* __restrict__ gw,
                            const float* __restrict__ gb,
                            float* __restrict__ out)
{
    __shared__ int sr0, sr1;
    __shared__ float smax[8];
    __shared__ float sgmax;
    __shared__ float sE[256];
    int g = blockIdx.x;
    int t = threadIdx.x;
    int lane = t & 31, w = t >> 5;

    if (t == 0) { sr0 = lbound(batch, g); sr1 = lbound(batch, g + 1); }
    __syncthreads();
    int r0 = sr0, r1 = sr1;

    // pass 1: gates + block max (warp per node)
    float wmax = -3.4e38f;
    {
        int d0 = lane * 8;
        float gwv[8], scv[8], shv[8];
#pragma unroll
        for (int i = 0; i < 8; i++) {
            gwv[i] = __ldg(gw + d0 + i);
            scv[i] = g_sc[d0 + i];
            shv[i] = g_sh[d0 + i];
        }
        for (int n = r0 + w; n < r1; n += 8) {
            const float4* xp = (const float4*)(X + (size_t)n * DD + d0);
            float4 h0 = __ldg(xp), h1 = __ldg(xp + 1);
            float v[8] = {h0.x, h0.y, h0.z, h0.w, h1.x, h1.y, h1.z, h1.w};
            float gsum = 0.f;
#pragma unroll
            for (int i = 0; i < 8; i++)
                gsum += leaky(v[i] * scv[i] + shv[i]) * gwv[i];
#pragma unroll
            for (int off = 16; off; off >>= 1)
                gsum += __shfl_xor_sync(0xffffffffu, gsum, off);
            if (lane == 0) {
                gsum += __ldg(gb);
                g_gate[n] = gsum;
                wmax = fmaxf(wmax, gsum);
            }
        }
    }
    if (lane == 0) smax[w] = wmax;
    __syncthreads();
    if (t == 0) {
        float m = smax[0];
#pragma unroll
        for (int i = 1; i < 8; i++) m = fmaxf(m, smax[i]);
        sgmax = m;
    }
    __syncthreads();
    float gmax = sgmax;

    // pass 2: chunked — e computed once per node into smem, reused by channels
    float sc_c = g_sc[t], sh_c = g_sh[t];
    float acc = 0.f, denom = 0.f;
    for (int c0 = r0; c0 < r1; c0 += 256) {
        int cnt = min(256, r1 - c0);
        __syncthreads();
        if (t < cnt) sE[t] = __expf(g_gate[c0 + t] - gmax);
        __syncthreads();
        for (int i = 0; i < cnt; i++) {
            float e = sE[i];
            denom += e;
            float x = __ldg(X + (size_t)(c0 + i) * DD + t);
            acc += e * leaky(x * sc_c + sh_c);
        }
    }
    out[(size_t)g * DD + t] = denom > 0.f ? acc / denom : 0.f;
}

// ---------------- launch -----------------------------------------------------
extern "C" void kernel_launch(void* const* d_in, const int* in_sizes, int n_in,
                              void* d_out, int out_size)
{
    const int*   node_ids  = (const int*)d_in[0];
    const int*   edge_index= (const int*)d_in[1];
    const float* edge_attr = (const float*)d_in[2];
    const int*   batch     = (const int*)d_in[3];
    const float* emb       = (const float*)d_in[4];
    const float* c1_lin2_w = (const float*)d_in[5];
    const float* c1_lin2_b = (const float*)d_in[6];
    const float* c1_lin_w  = (const float*)d_in[7];
    const float* c1_lin_b  = (const float*)d_in[8];
    const float* bn1_w     = (const float*)d_in[9];
    const float* bn1_b     = (const float*)d_in[10];
    const float* c2_lin2_w = (const float*)d_in[11];
    const float* c2_lin2_b = (const float*)d_in[12];
    const float* c2_lin_w  = (const float*)d_in[13];
    const float* c2_lin_b  = (const float*)d_in[14];
    const float* bn2_w     = (const float*)d_in[15];
    const float* bn2_b     = (const float*)d_in[16];
    const float* gate_w    = (const float*)d_in[17];
    const float* gate_b    = (const float*)d_in[18];
    float* out = (float*)d_out;

    const int* src = edge_index;
    const int* dst = edge_index + N_EDGES;

    float *pA, *pB, *pHT, *pC1, *pC2, *pbc2, *psc, *psh;
    float *pbs1, *pbq1, *pbs2, *pbq2;
    int *pWq1, *pWq2;
    __half* pW2h;
    cudaGetSymbolAddress((void**)&pA,   g_bufA);
    cudaGetSymbolAddress((void**)&pB,   g_bufB);
    cudaGetSymbolAddress((void**)&pHT,  g_HT);
    cudaGetSymbolAddress((void**)&pW2h, g_W2h);
    cudaGetSymbolAddress((void**)&pC1,  g_C1);
    cudaGetSymbolAddress((void**)&pC2,  g_C2);
    cudaGetSymbolAddress((void**)&pbc2, g_bc2);
    cudaGetSymbolAddress((void**)&psc,  g_sc);
    cudaGetSymbolAddress((void**)&psh,  g_sh);
    cudaGetSymbolAddress((void**)&pbs1, g_bnsum1);
    cudaGetSymbolAddress((void**)&pbq1, g_bnsq1);
    cudaGetSymbolAddress((void**)&pbs2, g_bnsum2);
    cudaGetSymbolAddress((void**)&pbq2, g_bnsq2);
    cudaGetSymbolAddress((void**)&pWq1, g_wq1);
    cudaGetSymbolAddress((void**)&pWq2, g_wq2);

    __half* pAh = (__half*)pA;
    __half* pBh = (__half*)pB;

    // ---- init (deg, bn stats, work queues) ----
    zero_init<<<NSB, 256>>>();

    // ---- CSR build (dst-sorted, permuted (src,srcnid) + edge_attr) ----
    hist_kernel<<<(N_EDGES + 255) / 256, 256>>>(dst);
    scan1_kernel<<<NSB, 256>>>();
    scan23_kernel<<<NSB, 256>>>();
    fill_kernel<<<(N_EDGES + 255) / 256, 256>>>(src, dst, edge_attr, node_ids);

    // ---- combined edge matrices, HT, W2 -> fp16 ----
    combine_kernel<<<1, 256>>>(c1_lin2_w, c1_lin2_b, c1_lin_w, c1_lin_b,
                               c2_lin2_w, c2_lin2_b, c2_lin_w, c2_lin_b);
    ht_kernel<<<N_IDS, 256>>>(emb, c1_lin_w);
    w2h_kernel<<<DD * DD / 2 / 256, 256>>>(c2_lin_w);

    // ---- conv1 gather (fp32 HT in, fp16 agg1 out) + bn1 stats ----
    gather_kernel<false, true, true><<<1024, 256>>>(pHT, pC1, pBh, pbs1, pbq1, pWq1);
    bnsc_kernel<<<1, 256>>>(bn1_w, bn1_b, pbs1, pbq1);

    // ---- layer 2: H2 = (half) leaky(bn1(agg1_h)) @ W2h^T + bc2 (fp16 HMMA) ----
    dim3 gg((N_NODES + 127) / 128, DD / 128);
    gemm_f16<<<gg, 256>>>(pBh, psc, psh, pW2h, pbc2, pAh, N_NODES, DD);

    // ---- conv2 gather (fp16 H2 in, fp32 agg2 out) + bn2 stats ----
    gather_kernel<true, false, false><<<1024, 256>>>(pAh, pC2, pB, pbs2, pbq2, pWq2);
    bnsc_kernel<<<1, 256>>>(bn2_w, bn2_b, pbs2, pbq2);

    // ---- fused attention: gate + softmax + weighted mean (block per graph) ----
    attn_kernel<<<N_GRAPHS, 256>>>(pB, batch, gate_w, gate_b, out);
}

// round 14
// speedup vs baseline: 1.5633x; 1.0796x over previous
#include <cuda_runtime.h>
#include <cuda_fp16.h>
#include <cstdint>

#define N_NODES  50000
#define N_EDGES  800000
#define N_GRAPHS 512
#define N_IDS    51
#define F_IN     128
#define DD       256
#define EPS      1e-5f
#define NEG_SLOPE 0.01f
#define NSB      196          // ceil(N_NODES/256) scan blocks
#define GATHER_BLOCKS 1024

typedef unsigned long long ull;

// ---------------- scratch (device globals; no allocation allowed) ----------
__device__ float g_bufA[N_NODES * DD];   // H2 (as __half)
__device__ float g_bufB[N_NODES * DD];   // agg1 (as __half) -> agg2 (fp32)
__device__ float g_HT[N_IDS * DD];       // emb_table @ W1^T + bc1
__device__ __half g_W2h[DD * DD];        // c2_lin_w as fp16
__device__ float g_C1[4 * DD];
__device__ float g_C2[4 * DD];
__device__ float g_bc2[DD];
__device__ float g_bnsum1[DD];
__device__ float g_bnsq1[DD];
__device__ float g_bnsum2[DD];
__device__ float g_bnsq2[DD];
__device__ float g_sc[DD];
__device__ float g_sh[DD];
__device__ float g_gate[N_NODES];
__device__ int   g_wq1, g_wq2;           // work-stealing counters
__device__ int   g_done1, g_done2;       // last-block tickets
// CSR (dst-sorted, with permuted (src, srcnid) pairs and edge_attr)
__device__ int    g_deg[N_NODES];
__device__ int    g_start[N_NODES];
__device__ int    g_cursor[N_NODES];
__device__ int2   g_sp[N_EDGES];         // {src, srcnid}
__device__ float4 g_eas[N_EDGES];
__device__ int    g_part[NSB];

// ---------------- helpers ---------------------------------------------------
__device__ __forceinline__ float leaky(float v) {
    return v >= 0.f ? v : NEG_SLOPE * v;
}
__device__ __forceinline__ ull dup2(float x) {
    ull r; unsigned u = __float_as_uint(x);
    asm("mov.b64 %0, {%1, %1};" : "=l"(r) : "r"(u));
    return r;
}
__device__ __forceinline__ void fma2(ull& d, ull a, ull b) {
    asm("fma.rn.f32x2 %0, %1, %2, %0;" : "+l"(d) : "l"(a), "l"(b));
}
__device__ __forceinline__ float2 up2(ull v) {
    float2 f; asm("mov.b64 {%0, %1}, %2;" : "=f"(f.x), "=f"(f.y) : "l"(v));
    return f;
}
__device__ __forceinline__ ull pack2(float lo, float hi) {
    ull r;
    asm("mov.b64 %0, {%1, %2};" : "=l"(r) : "f"(lo), "f"(hi));
    return r;
}
__device__ __forceinline__ void mma_f16(float d[4], const unsigned a[4],
                                        unsigned b0, unsigned b1) {
    asm volatile(
        "mma.sync.aligned.m16n8k16.row.col.f32.f16.f16.f32 "
        "{%0,%1,%2,%3}, {%4,%5,%6,%7}, {%8,%9}, {%0,%1,%2,%3};"
        : "+f"(d[0]), "+f"(d[1]), "+f"(d[2]), "+f"(d[3])
        : "r"(a[0]), "r"(a[1]), "r"(a[2]), "r"(a[3]), "r"(b0), "r"(b1));
}

// ---------------- zero / init kernels ---------------------------------------
__global__ void zero_init() {
    int i = blockIdx.x * blockDim.x + threadIdx.x;
    if (i < N_NODES) g_deg[i] = 0;
    if (i < DD) {
        g_bnsum1[i] = 0.f; g_bnsq1[i] = 0.f;
        g_bnsum2[i] = 0.f; g_bnsq2[i] = 0.f;
    }
    if (i == 0) { g_wq1 = 0; g_wq2 = 0; g_done1 = 0; g_done2 = 0; }
}

// ---------------- CSR build --------------------------------------------------
__global__ void hist_kernel(const int* __restrict__ dst) {
    int e = blockIdx.x * blockDim.x + threadIdx.x;
    if (e < N_EDGES) atomicAdd(&g_deg[__ldg(dst + e)], 1);
}
__global__ void scan1_kernel() {
    __shared__ int sh[256];
    int i = blockIdx.x * 256 + threadIdx.x;
    int v = (i < N_NODES) ? g_deg[i] : 0;
    sh[threadIdx.x] = v; __syncthreads();
#pragma unroll
    for (int off = 1; off < 256; off <<= 1) {
        int tv = (threadIdx.x >= off) ? sh[threadIdx.x - off] : 0;
        __syncthreads();
        sh[threadIdx.x] += tv;
        __syncthreads();
    }
    if (i < N_NODES) g_start[i] = sh[threadIdx.x] - v;
    if (threadIdx.x == 255) g_part[blockIdx.x] = sh[255];
}
__global__ void scan23_kernel() {
    __shared__ int sh[256];
    __shared__ int sexcl;
    int t = threadIdx.x;
    int v = (t < NSB) ? g_part[t] : 0;
    sh[t] = v; __syncthreads();
#pragma unroll
    for (int off = 1; off < 256; off <<= 1) {
        int tv = (t >= off) ? sh[t - off] : 0;
        __syncthreads();
        sh[t] += tv;
        __syncthreads();
    }
    if (t == 0) sexcl = (blockIdx.x == 0) ? 0 : sh[blockIdx.x - 1];
    __syncthreads();
    int i = blockIdx.x * 256 + t;
    if (i < N_NODES) {
        int s = g_start[i] + sexcl;
        g_start[i] = s;
        g_cursor[i] = s;
    }
}
__global__ void fill_kernel(const int* __restrict__ src,
                            const int* __restrict__ dst,
                            const float* __restrict__ ea,
                            const int* __restrict__ node_ids) {
    int e = blockIdx.x * blockDim.x + threadIdx.x;
    if (e < N_EDGES) {
        int d = __ldg(dst + e);
        int s = __ldg(src + e);
        int p = atomicAdd(&g_cursor[d], 1);
        g_sp[p] = make_int2(s, __ldg(node_ids + s));
        g_eas[p] = __ldg((const float4*)ea + e);
    }
}

// ---------------- merged prep: HT (with inline bc1) + combine + W2->fp16 -----
// blocks [0, N_IDS)            : HT rows
// block  N_IDS                 : C1 / C2 / bc2
// blocks (N_IDS, N_IDS+128]    : W2 -> fp16
__global__ void prep_kernel(
    const float* __restrict__ emb,
    const float* __restrict__ l2w1, const float* __restrict__ l2b1,
    const float* __restrict__ lw1,  const float* __restrict__ lb1,
    const float* __restrict__ l2w2, const float* __restrict__ l2b2,
    const float* __restrict__ lw2,  const float* __restrict__ lb2)
{
    int blk = blockIdx.x;
    int d = threadIdx.x;
    if (blk < N_IDS) {
        // HT[v][d] = sum_f emb[v][f]*W1[d][f] + (sum_f l2b1[f]*W1[d][f] + lb1[d])
        __shared__ float ev[F_IN];
        if (d < F_IN) ev[d] = emb[blk * F_IN + d];
        __syncthreads();
        const float* wr = lw1 + (size_t)d * F_IN;
        float s = 0.f, bb = 0.f;
#pragma unroll 8
        for (int f = 0; f < F_IN; f++) {
            float w = __ldg(wr + f);
            s += ev[f] * w;
            bb += __ldg(l2b1 + f) * w;
        }
        g_HT[blk * DD + d] = s + bb + lb1[d];
    } else if (blk == N_IDS) {
        // C1 = l2w1^T @ W1^T slice; C2 + bc2
        {
            float a0 = 0.f, a1 = 0.f, a2 = 0.f, a3 = 0.f;
            for (int f = 0; f < F_IN; f++) {
                float w = lw1[d * F_IN + f];
                float4 l2 = *(const float4*)(l2w1 + f * 4);
                a0 += l2.x * w; a1 += l2.y * w; a2 += l2.z * w; a3 += l2.w * w;
            }
            g_C1[0 * DD + d] = a0; g_C1[1 * DD + d] = a1;
            g_C1[2 * DD + d] = a2; g_C1[3 * DD + d] = a3;
        }
        {
            float a0 = 0.f, a1 = 0.f, a2 = 0.f, a3 = 0.f, bb = 0.f;
            for (int f = 0; f < DD; f++) {
                float w = lw2[d * DD + f];
                float4 l2 = *(const float4*)(l2w2 + f * 4);
                a0 += l2.x * w; a1 += l2.y * w; a2 += l2.z * w; a3 += l2.w * w;
                bb += l2b2[f] * w;
            }
            g_C2[0 * DD + d] = a0; g_C2[1 * DD + d] = a1;
            g_C2[2 * DD + d] = a2; g_C2[3 * DD + d] = a3;
            g_bc2[d] = bb + lb2[d];
        }
    } else {
        int i = (blk - N_IDS - 1) * 256 + d;   // pair index, 32768 total
        float2 v = __ldg((const float2*)lw2 + i);
        *((__half2*)g_W2h + i) = __floats2half2_rn(v.x, v.y);
    }
}

// ---------------- GEMM (fp16 HMMA m16n8k16, fp32 accum, half in/out) ---------
__global__ void __launch_bounds__(256)
gemm_f16(const __half* __restrict__ A,
         const float* __restrict__ sc, const float* __restrict__ sh,
         const __half* __restrict__ Wh, const float* __restrict__ bias,
         __half* __restrict__ out, int M, int K)
{
    __shared__ unsigned As[128 * 20];   // 10 KB
    __shared__ unsigned Bs[128 * 20];   // 10 KB
    int t = threadIdx.x;
    int lane = t & 31;
    int wid = t >> 5;
    int wm = wid & 3, wn = wid >> 2;
    int bm = blockIdx.x * 128;
    int bn = blockIdx.y * 128;

    int lrow = t >> 1;
    int lh = t & 1;

    int gid = lane >> 2;
    int c = lane & 3;

    int m0 = bm + lrow;
    int mc = m0 < M ? m0 : (M - 1);
    const __half* Arow = A + (size_t)mc * K;
    const __half* Wrow = Wh + (size_t)(bn + lrow) * K;

    float d[2][8][4];
#pragma unroll
    for (int i = 0; i < 2; i++)
#pragma unroll
        for (int j = 0; j < 8; j++)
#pragma unroll
            for (int q = 0; q < 4; q++) d[i][j][q] = 0.f;

    uint4 ra0, ra1, rb0, rb1;

    auto load_stage = [&](int kc) {
        int kb = kc + lh * 16;
        ra0 = __ldg((const uint4*)(Arow + kb));
        ra1 = __ldg((const uint4*)(Arow + kb + 8));
        rb0 = __ldg((const uint4*)(Wrow + kb));
        rb1 = __ldg((const uint4*)(Wrow + kb + 8));
#pragma unroll
        for (int q = 0; q < 8; q++) {
            unsigned* p = (q < 4) ? (&ra0.x + q) : (&ra1.x + (q - 4));
            float2 f = __half22float2(*(__half2*)p);
            int ch = kb + q * 2;
            float2 s = __ldg((const float2*)(sc + ch));
            float2 hh = __ldg((const float2*)(sh + ch));
            f.x = leaky(f.x * s.x + hh.x);
            f.y = leaky(f.y * s.y + hh.y);
            __half2 r = __floats2half2_rn(f.x, f.y);
            *p = *(unsigned*)&r;
        }
    };
    auto store_stage = [&]() {
        unsigned* ap = As + lrow * 20 + lh * 8;
        unsigned* bp = Bs + lrow * 20 + lh * 8;
        *(uint4*)(ap)     = ra0;
        *(uint4*)(ap + 4) = ra1;
        *(uint4*)(bp)     = rb0;
        *(uint4*)(bp + 4) = rb1;
    };

    load_stage(0);
    store_stage();
    __syncthreads();

    for (int kc = 0; kc < K; kc += 32) {
        bool more = (kc + 32) < K;
        if (more) load_stage(kc + 32);
#pragma unroll
        for (int ks = 0; ks < 2; ks++) {
            int kp = ks * 8 + c;
            unsigned a[2][4];
#pragma unroll
            for (int i = 0; i < 2; i++) {
                int r = (wm * 32 + i * 16 + gid) * 20;
                a[i][0] = As[r + kp];
                a[i][1] = As[r + 8 * 20 + kp];
                a[i][2] = As[r + kp + 4];
                a[i][3] = As[r + 8 * 20 + kp + 4];
            }
#pragma unroll
            for (int j = 0; j < 8; j++) {
                int rn = (wn * 64 + j * 8 + gid) * 20;
                unsigned b0 = Bs[rn + kp];
                unsigned b1 = Bs[rn + kp + 4];
                mma_f16(d[0][j], a[0], b0, b1);
                mma_f16(d[1][j], a[1], b0, b1);
            }
        }
        if (more) {
            __syncthreads();
            store_stage();
            __syncthreads();
        }
    }

    float2 bsv[8];
#pragma unroll
    for (int j = 0; j < 8; j++) {
        int col = bn + wn * 64 + j * 8 + c * 2;
        bsv[j] = __ldg((const float2*)(bias + col));
    }
#pragma unroll
    for (int i = 0; i < 2; i++) {
        int rg0 = bm + wm * 32 + i * 16 + gid;
        int rg1 = rg0 + 8;
#pragma unroll
        for (int j = 0; j < 8; j++) {
            int col = bn + wn * 64 + j * 8 + c * 2;
            if (rg0 < M)
                *(__half2*)(out + (size_t)rg0 * DD + col) =
                    __floats2half2_rn(d[i][j][0] + bsv[j].x, d[i][j][1] + bsv[j].y);
            if (rg1 < M)
                *(__half2*)(out + (size_t)rg1 * DD + col) =
                    __floats2half2_rn(d[i][j][2] + bsv[j].x, d[i][j][3] + bsv[j].y);
        }
    }
}

// ---------------- per-edge packed accumulate (bias pre-folded into H) --------
__device__ __forceinline__ void edge_accum(
    ull acc[4], float4 at, const ull hh[4],
    const ull c0p[4], const ull c1p[4], const ull c2p[4], const ull c3p[4])
{
    const ull ABS2 = 0x7fffffff7fffffffull;
    const ull D505 = 0x3f0147ae3f0147aeull;
    const ull D495 = 0x3efd70a43efd70a4ull;
    ull ax = dup2(at.x), ay = dup2(at.y), az = dup2(at.z), aw = dup2(at.w);
#pragma unroll
    for (int i = 0; i < 4; i++) {
        ull m = hh[i];
        fma2(m, ax, c0p[i]); fma2(m, ay, c1p[i]);
        fma2(m, az, c2p[i]); fma2(m, aw, c3p[i]);
        ull ab = m & ABS2;
        fma2(acc[i], D505, m);
        fma2(acc[i], D495, ab);
    }
}

// ---------------- CSR gather (work stealing; BN fused via last-block) --------
template <bool HALF_IN, bool HALF_OUT, bool USE_NID>
__global__ void gather_kernel(const void* __restrict__ Hv,
                              const float* __restrict__ C,
                              void* __restrict__ aggv,
                              float* __restrict__ bnsum,
                              float* __restrict__ bnsq,
                              int* __restrict__ wq,
                              int* __restrict__ done,
                              const float* __restrict__ bnw,
                              const float* __restrict__ bnb)
{
    __shared__ float ssum[DD];
    __shared__ float ssq[DD];
    __shared__ int slast;
    int t = threadIdx.x;
    ssum[t] = 0.f; ssq[t] = 0.f;
    __syncthreads();

    int lane = t & 31;
    int d0 = lane * 8;

    ull c0p[4], c1p[4], c2p[4], c3p[4];
    {
        ulonglong2 u;
        u = *(const ulonglong2*)(C + 0 * DD + d0);     c0p[0] = u.x; c0p[1] = u.y;
        u = *(const ulonglong2*)(C + 0 * DD + d0 + 4); c0p[2] = u.x; c0p[3] = u.y;
        u = *(const ulonglong2*)(C + 1 * DD + d0);     c1p[0] = u.x; c1p[1] = u.y;
        u = *(const ulonglong2*)(C + 1 * DD + d0 + 4); c1p[2] = u.x; c1p[3] = u.y;
        u = *(const ulonglong2*)(C + 2 * DD + d0);     c2p[0] = u.x; c2p[1] = u.y;
        u = *(const ulonglong2*)(C + 2 * DD + d0 + 4); c2p[2] = u.x; c2p[3] = u.y;
        u = *(const ulonglong2*)(C + 3 * DD + d0);     c3p[0] = u.x; c3p[1] = u.y;
        u = *(const ulonglong2*)(C + 3 * DD + d0 + 4); c3p[2] = u.x; c3p[3] = u.y;
    }

    const float* Hf = (const float*)Hv;
    const __half* Hh = (const __half*)Hv;

    auto load_h = [&](int row, ull hh[4]) {
        if (HALF_IN) {
            uint4 u = __ldg((const uint4*)(Hh + (size_t)row * DD + d0));
            float2 f0 = __half22float2(*(__half2*)&u.x);
            float2 f1 = __half22float2(*(__half2*)&u.y);
            float2 f2 = __half22float2(*(__half2*)&u.z);
            float2 f3 = __half22float2(*(__half2*)&u.w);
            hh[0] = pack2(f0.x, f0.y); hh[1] = pack2(f1.x, f1.y);
            hh[2] = pack2(f2.x, f2.y); hh[3] = pack2(f3.x, f3.y);
        } else {
            const ulonglong2* hp = (const ulonglong2*)(Hf + (size_t)row * DD + d0);
            ulonglong2 p = hp[0], q = hp[1];
            hh[0] = p.x; hh[1] = p.y; hh[2] = q.x; hh[3] = q.y;
        }
    };

    float sA[8], qA[8];
#pragma unroll
    for (int i = 0; i < 8; i++) { sA[i] = 0.f; qA[i] = 0.f; }

    int n = 0;
    if (lane == 0) n = atomicAdd(wq, 1);
    n = __shfl_sync(0xffffffffu, n, 0);
    while (n < N_NODES) {
        int nn = 0;
        if (lane == 0) nn = atomicAdd(wq, 1);
        nn = __shfl_sync(0xffffffffu, nn, 0);

        int s0 = __ldg(g_start + n);
        int dg = __ldg(g_deg + n);
        ull acc[4] = {0ull, 0ull, 0ull, 0ull};

        int j = 0;
        for (; j + 3 < dg; j += 4) {
            int2 p0 = __ldg(g_sp + s0 + j);
            int2 p1 = __ldg(g_sp + s0 + j + 1);
            int2 p2 = __ldg(g_sp + s0 + j + 2);
            int2 p3 = __ldg(g_sp + s0 + j + 3);
            int sa = USE_NID ? p0.y : p0.x;
            int sb = USE_NID ? p1.y : p1.x;
            int sc2 = USE_NID ? p2.y : p2.x;
            int sd = USE_NID ? p3.y : p3.x;
            ull ha[4], hb[4], hc[4], hd[4];
            load_h(sa, ha); load_h(sb, hb); load_h(sc2, hc); load_h(sd, hd);
            float4 at0 = __ldg((const float4*)g_eas + s0 + j);
            float4 at1 = __ldg((const float4*)g_eas + s0 + j + 1);
            float4 at2 = __ldg((const float4*)g_eas + s0 + j + 2);
            float4 at3 = __ldg((const float4*)g_eas + s0 + j + 3);
            edge_accum(acc, at0, ha, c0p, c1p, c2p, c3p);
            edge_accum(acc, at1, hb, c0p, c1p, c2p, c3p);
            edge_accum(acc, at2, hc, c0p, c1p, c2p, c3p);
            edge_accum(acc, at3, hd, c0p, c1p, c2p, c3p);
        }
        for (; j < dg; j++) {
            int2 p0 = __ldg(g_sp + s0 + j);
            int sa = USE_NID ? p0.y : p0.x;
            float4 at0 = __ldg((const float4*)g_eas + s0 + j);
            ull ha[4];
            load_h(sa, ha);
            edge_accum(acc, at0, ha, c0p, c1p, c2p, c3p);
        }

        float2 f0 = up2(acc[0]), f1 = up2(acc[1]);
        float2 f2 = up2(acc[2]), f3 = up2(acc[3]);
        if (HALF_OUT) {
            __half2 h0 = __floats2half2_rn(f0.x, f0.y);
            __half2 h1 = __floats2half2_rn(f1.x, f1.y);
            __half2 h2 = __floats2half2_rn(f2.x, f2.y);
            __half2 h3 = __floats2half2_rn(f3.x, f3.y);
            uint4 u;
            u.x = *(unsigned*)&h0; u.y = *(unsigned*)&h1;
            u.z = *(unsigned*)&h2; u.w = *(unsigned*)&h3;
            *(uint4*)((__half*)aggv + (size_t)n * DD + d0) = u;
        } else {
            ulonglong2* op = (ulonglong2*)((float*)aggv + (size_t)n * DD + d0);
            op[0] = make_ulonglong2(acc[0], acc[1]);
            op[1] = make_ulonglong2(acc[2], acc[3]);
        }

        sA[0] += f0.x; qA[0] += f0.x * f0.x;  sA[1] += f0.y; qA[1] += f0.y * f0.y;
        sA[2] += f1.x; qA[2] += f1.x * f1.x;  sA[3] += f1.y; qA[3] += f1.y * f1.y;
        sA[4] += f2.x; qA[4] += f2.x * f2.x;  sA[5] += f2.y; qA[5] += f2.y * f2.y;
        sA[6] += f3.x; qA[6] += f3.x * f3.x;  sA[7] += f3.y; qA[7] += f3.y * f3.y;

        n = nn;
    }
#pragma unroll
    for (int i = 0; i < 8; i++) {
        atomicAdd(&ssum[d0 + i], sA[i]);
        atomicAdd(&ssq[d0 + i], qA[i]);
    }
    __syncthreads();
    atomicAdd(&bnsum[t], ssum[t]);
    atomicAdd(&bnsq[t], ssq[t]);

    // last block computes BN scale/shift in-kernel
    __threadfence();
    if (t == 0) slast = (atomicAdd(done, 1) == (int)gridDim.x - 1) ? 1 : 0;
    __syncthreads();
    if (slast) {
        __threadfence();
        const float invN = 1.f / (float)N_NODES;
        float m = bnsum[t] * invN;
        float var = bnsq[t] * invN - m * m;
        float s = __ldg(bnw + t) * rsqrtf(var + EPS);
        g_sc[t] = s;
        g_sh[t] = __ldg(bnb + t) - m * s;
    }
}

// ---------------- fused attention: gate + softmax + weighted mean -------------
__device__ __forceinline__ int lbound(const int* a, int v) {
    int lo = 0, hi = N_NODES;
    while (lo < hi) {
        int m = (lo + hi) >> 1;
        if (__ldg(a + m) < v) lo = m + 1; else hi = m;
    }
    return lo;
}

__global__ void attn_kernel(const float* __restrict__ X,
                            const int* __restrict__ batch,
                            const float* __restrict__ gw,
                            const float* __restrict__ gb,
                            float* __restrict__ out)
{
    __shared__ int sr0, sr1;
    __shared__ float smax[8];
    __shared__ float sgmax;
    __shared__ float sE[256];
    int g = blockIdx.x;
    int t = threadIdx.x;
    int lane = t & 31, w = t >> 5;

    if (t == 0) { sr0 = lbound(batch, g); sr1 = lbound(batch, g + 1); }
    __syncthreads();
    int r0 = sr0, r1 = sr1;

    float wmax = -3.4e38f;
    {
        int d0 = lane * 8;
        float gwv[8], scv[8], shv[8];
#pragma unroll
        for (int i = 0; i < 8; i++) {
            gwv[i] = __ldg(gw + d0 + i);
            scv[i] = g_sc[d0 + i];
            shv[i] = g_sh[d0 + i];
        }
        for (int n = r0 + w; n < r1; n += 8) {
            const float4* xp = (const float4*)(X + (size_t)n * DD + d0);
            float4 h0 = __ldg(xp), h1 = __ldg(xp + 1);
            float v[8] = {h0.x, h0.y, h0.z, h0.w, h1.x, h1.y, h1.z, h1.w};
            float gsum = 0.f;
#pragma unroll
            for (int i = 0; i < 8; i++)
                gsum += leaky(v[i] * scv[i] + shv[i]) * gwv[i];
#pragma unroll
            for (int off = 16; off; off >>= 1)
                gsum += __shfl_xor_sync(0xffffffffu, gsum, off);
            if (lane == 0) {
                gsum += __ldg(gb);
                g_gate[n] = gsum;
                wmax = fmaxf(wmax, gsum);
            }
        }
    }
    if (lane == 0) smax[w] = wmax;
    __syncthreads();
    if (t == 0) {
        float m = smax[0];
#pragma unroll
        for (int i = 1; i < 8; i++) m = fmaxf(m, smax[i]);
        sgmax = m;
    }
    __syncthreads();
    float gmax = sgmax;

    float sc_c = g_sc[t], sh_c = g_sh[t];
    float acc = 0.f, denom = 0.f;
    for (int c0 = r0; c0 < r1; c0 += 256) {
        int cnt = min(256, r1 - c0);
        __syncthreads();
        if (t < cnt) sE[t] = __expf(g_gate[c0 + t] - gmax);
        __syncthreads();
        for (int i = 0; i < cnt; i++) {
            float e = sE[i];
            denom += e;
            float x = __ldg(X + (size_t)(c0 + i) * DD + t);
            acc += e * leaky(x * sc_c + sh_c);
        }
    }
    out[(size_t)g * DD + t] = denom > 0.f ? acc / denom : 0.f;
}

// ---------------- launch -----------------------------------------------------
extern "C" void kernel_launch(void* const* d_in, const int* in_sizes, int n_in,
                              void* d_out, int out_size)
{
    const int*   node_ids  = (const int*)d_in[0];
    const int*   edge_index= (const int*)d_in[1];
    const float* edge_attr = (const float*)d_in[2];
    const int*   batch     = (const int*)d_in[3];
    const float* emb       = (const float*)d_in[4];
    const float* c1_lin2_w = (const float*)d_in[5];
    const float* c1_lin2_b = (const float*)d_in[6];
    const float* c1_lin_w  = (const float*)d_in[7];
    const float* c1_lin_b  = (const float*)d_in[8];
    const float* bn1_w     = (const float*)d_in[9];
    const float* bn1_b     = (const float*)d_in[10];
    const float* c2_lin2_w = (const float*)d_in[11];
    const float* c2_lin2_b = (const float*)d_in[12];
    const float* c2_lin_w  = (const float*)d_in[13];
    const float* c2_lin_b  = (const float*)d_in[14];
    const float* bn2_w     = (const float*)d_in[15];
    const float* bn2_b     = (const float*)d_in[16];
    const float* gate_w    = (const float*)d_in[17];
    const float* gate_b    = (const float*)d_in[18];
    float* out = (float*)d_out;

    const int* src = edge_index;
    const int* dst = edge_index + N_EDGES;

    float *pA, *pB, *pHT, *pC1, *pC2, *pbc2, *psc, *psh;
    float *pbs1, *pbq1, *pbs2, *pbq2;
    int *pWq1, *pWq2, *pDone1, *pDone2;
    __half* pW2h;
    cudaGetSymbolAddress((void**)&pA,    g_bufA);
    cudaGetSymbolAddress((void**)&pB,    g_bufB);
    cudaGetSymbolAddress((void**)&pHT,   g_HT);
    cudaGetSymbolAddress((void**)&pW2h,  g_W2h);
    cudaGetSymbolAddress((void**)&pC1,   g_C1);
    cudaGetSymbolAddress((void**)&pC2,   g_C2);
    cudaGetSymbolAddress((void**)&pbc2,  g_bc2);
    cudaGetSymbolAddress((void**)&psc,   g_sc);
    cudaGetSymbolAddress((void**)&psh,   g_sh);
    cudaGetSymbolAddress((void**)&pbs1,  g_bnsum1);
    cudaGetSymbolAddress((void**)&pbq1,  g_bnsq1);
    cudaGetSymbolAddress((void**)&pbs2,  g_bnsum2);
    cudaGetSymbolAddress((void**)&pbq2,  g_bnsq2);
    cudaGetSymbolAddress((void**)&pWq1,  g_wq1);
    cudaGetSymbolAddress((void**)&pWq2,  g_wq2);
    cudaGetSymbolAddress((void**)&pDone1, g_done1);
    cudaGetSymbolAddress((void**)&pDone2, g_done2);

    __half* pAh = (__half*)pA;
    __half* pBh = (__half*)pB;

    // ---- init (deg, bn stats, queues, tickets) ----
    zero_init<<<NSB, 256>>>();

    // ---- CSR build ----
    hist_kernel<<<(N_EDGES + 255) / 256, 256>>>(dst);
    scan1_kernel<<<NSB, 256>>>();
    scan23_kernel<<<NSB, 256>>>();
    fill_kernel<<<(N_EDGES + 255) / 256, 256>>>(src, dst, edge_attr, node_ids);

    // ---- merged prep: HT + C1/C2/bc2 + W2h (one launch) ----
    prep_kernel<<<N_IDS + 1 + DD * DD / 2 / 256, 256>>>(
        emb, c1_lin2_w, c1_lin2_b, c1_lin_w, c1_lin_b,
        c2_lin2_w, c2_lin2_b, c2_lin_w, c2_lin_b);

    // ---- conv1 gather (HT -> fp16 agg1) + fused BN1 ----
    gather_kernel<false, true, true><<<GATHER_BLOCKS, 256>>>(
        pHT, pC1, pBh, pbs1, pbq1, pWq1, pDone1, bn1_w, bn1_b);

    // ---- layer 2: H2 = (half) leaky(bn1(agg1_h)) @ W2h^T + bc2 (fp16 HMMA) ----
    dim3 gg((N_NODES + 127) / 128, DD / 128);
    gemm_f16<<<gg, 256>>>(pBh, psc, psh, pW2h, pbc2, pAh, N_NODES, DD);

    // ---- conv2 gather (fp16 H2 -> fp32 agg2) + fused BN2 ----
    gather_kernel<true, false, false><<<GATHER_BLOCKS, 256>>>(
        pAh, pC2, pB, pbs2, pbq2, pWq2, pDone2, bn2_w, bn2_b);

    // ---- fused attention ----
    attn_kernel<<<N_GRAPHS, 256>>>(pB, batch, gate_w, gate_b, out);
}